// round 2
// baseline (speedup 1.0000x reference)
#include <cuda_runtime.h>
#include <math.h>

#define Bz 8
#define Sz 8192
#define Hz 128
#define STEPS 20
#define NBPB 16              // blocks per batch
#define NB (Bz * NBPB)       // 128 blocks total (<= 148 SMs -> co-resident)
#define NT 256               // threads per block
#define SCHUNK (Sz / NBPB)   // 512 positions per block

// -------- persistent scratch (no allocations allowed) --------
__device__ float g_base[(size_t)Bz * Hz * Sz];  // 33.5 MB, fits L2
__device__ float g_coef[4 * Hz];                // A0, A1, D, C
__device__ float g_hh[2][Bz][Hz];               // double-buffered hidden state
__device__ float g_cc[Bz][Hz];
__device__ float g_pm[Bz][NBPB];                // per-block softmax partials
__device__ int   g_pi[Bz][NBPB];
__device__ float g_ps[Bz][NBPB];
__device__ unsigned g_barcnt = 0;
__device__ unsigned g_bargen = 0;

// -------- grid barrier: valid because all NB blocks are co-resident --------
__device__ __forceinline__ void grid_barrier() {
    __syncthreads();
    if (threadIdx.x == 0) {
        volatile unsigned* genp = &g_bargen;
        unsigned gen = *genp;
        __threadfence();
        unsigned arrived = atomicAdd(&g_barcnt, 1u);
        if (arrived == NB - 1) {
            g_barcnt = 0;
            __threadfence();
            atomicAdd(&g_bargen, 1u);
        } else {
            while (*genp == gen) { }
        }
        __threadfence();
    }
    __syncthreads();
}

// -------- accurate tanh without MUFU (Taylor deg-13, err < 2e-7 for |x|<=0.55) --------
__device__ __forceinline__ float tanh_fast(float x) {
    float y = x * x;
    float p = fmaf(y, 3.5921280e-3f, -8.8632355e-3f);
    p = fmaf(p, y, 2.1869489e-2f);
    p = fmaf(p, y, -5.3968254e-2f);
    p = fmaf(p, y, 1.3333333e-1f);
    p = fmaf(p, y, -3.3333333e-1f);
    p = fmaf(p, y, 1.0f);
    float t = x * p;
    if (fabsf(x) > 0.55f) t = tanhf(x);   // rare fallback
    return t;
}

__device__ __forceinline__ float sigmoidf(float x) { return 1.f / (1.f + expf(-x)); }

// -------- K0: fold the per-step projections into rank-2 coefficients --------
__global__ void coef_kernel(const float* __restrict__ W_ref, const float* __restrict__ W_s,
                            const float* __restrict__ b_s,   const float* __restrict__ b_ref,
                            const float* __restrict__ W_pd,  const float* __restrict__ W_d,
                            const float* __restrict__ b_d,   const float* __restrict__ b_pd) {
    int g = threadIdx.x;  // 128 threads
    float a0 = 0.f, a1 = 0.f, dd = 0.f, c = 0.f;
    for (int h = 0; h < Hz; ++h) {
        float wr = W_ref[g * Hz + h];
        a0 = fmaf(wr, W_s[h * 2 + 0], a0);
        a1 = fmaf(wr, W_s[h * 2 + 1], a1);
        c  = fmaf(wr, b_s[h], c);
        float wp = W_pd[g * Hz + h];
        dd = fmaf(wp, W_d[h], dd);
        c  = fmaf(wp, b_d[h], c);
    }
    c += b_ref[g] + b_pd[g];
    g_coef[g] = a0; g_coef[Hz + g] = a1; g_coef[2 * Hz + g] = dd; g_coef[3 * Hz + g] = c;
}

// -------- persistent decode kernel --------
__global__ __launch_bounds__(NT, 1)
void persist_kernel(const float* __restrict__ st,   const float* __restrict__ dyn,
                    const float* __restrict__ W_dec, const float* __restrict__ b_dec,
                    const float* __restrict__ W_ih,  const float* __restrict__ W_hh,
                    const float* __restrict__ b_ih,  const float* __restrict__ b_hh,
                    const float* __restrict__ W_q,   const float* __restrict__ b_q,
                    const float* __restrict__ W_att,
                    float* __restrict__ out, int out_size) {
    const int blk = blockIdx.x;
    const int b = blk / NBPB;
    const int k = blk % NBPB;
    const int t = threadIdx.x;

    __shared__ float s_q[Hz];
    __shared__ float s_watt[Hz];
    __shared__ float s_dh[Hz];
    __shared__ float s_hhold[Hz];
    __shared__ float s_dec[2];
    __shared__ float s_gate[32];
    __shared__ float s_red[NT];
    __shared__ int   s_redi[NT];
    __shared__ float s_red2[NT];
    __shared__ float s_qp[NT];

    // ---- phase 0: materialize base[b,g,s] (one pass, stays in L2) ----
    {
        const int tot = Bz * Hz * Sz;
        for (int idx = blk * NT + t; idx < tot; idx += NB * NT) {
            int s  = idx & (Sz - 1);
            int g  = (idx >> 13) & (Hz - 1);
            int bb = idx >> 20;
            float x = st[(bb * 2 + 0) * Sz + s];
            float y = st[(bb * 2 + 1) * Sz + s];
            float d = dyn[bb * Sz + s];
            g_base[idx] = fmaf(g_coef[g], x,
                          fmaf(g_coef[Hz + g], y,
                          fmaf(g_coef[2 * Hz + g], d, g_coef[3 * Hz + g])));
        }
    }
    if (t < 8) { int g = k * 8 + t; g_hh[0][b][g] = 0.f; g_cc[b][g] = 0.f; }
    if (t < Hz) s_watt[t] = W_att[t];
    if (t == 0) { s_dec[0] = 0.f; s_dec[1] = 0.f; }
    grid_barrier();

    for (int step = 0; step < STEPS; ++step) {
        const int p = step & 1;

        // ---- phase A: LSTM slice (this block owns g in [k*8, k*8+8)) ----
        __syncthreads();
        if (t < Hz) {
            s_hhold[t] = g_hh[p][b][t];
            s_dh[t] = fmaf(W_dec[t * 2 + 0], s_dec[0],
                      fmaf(W_dec[t * 2 + 1], s_dec[1], b_dec[t]));
        }
        __syncthreads();
        {
            int row = t >> 3, l8 = t & 7;
            int q4 = row >> 3, r = row & 7;
            int j = q4 * Hz + k * 8 + r;
            const float* wi = W_ih + j * Hz + l8 * 16;
            const float* wh = W_hh + j * Hz + l8 * 16;
            float acc = 0.f;
            #pragma unroll
            for (int h = 0; h < 16; ++h)
                acc = fmaf(wi[h], s_dh[l8 * 16 + h], fmaf(wh[h], s_hhold[l8 * 16 + h], acc));
            s_red[t] = acc;
        }
        __syncthreads();
        if (t < 32) {
            float gsum = 0.f;
            #pragma unroll
            for (int x = 0; x < 8; ++x) gsum += s_red[t * 8 + x];
            int jj = (t >> 3) * Hz + k * 8 + (t & 7);
            s_gate[t] = gsum + b_ih[jj] + b_hh[jj];
        }
        __syncthreads();
        if (t < 8) {
            int g = k * 8 + t;
            float ig = s_gate[t], fg = s_gate[8 + t], gg = s_gate[16 + t], og = s_gate[24 + t];
            float c  = g_cc[b][g];
            float c2 = fmaf(sigmoidf(fg), c, sigmoidf(ig) * tanhf(gg));
            float h2 = sigmoidf(og) * tanhf(c2);
            g_cc[b][g] = c2;
            g_hh[1 - p][b][g] = h2;
        }
        grid_barrier();

        // ---- phase C: q = W_q @ hh_new + b_q (redundant per block, cheap) ----
        if (t < Hz) s_hhold[t] = g_hh[1 - p][b][t];
        __syncthreads();
        {
            int g = t & (Hz - 1), half = t >> 7;
            const float* wq = W_q + g * Hz + half * 64;
            float qa = 0.f;
            #pragma unroll 8
            for (int h = 0; h < 64; ++h) qa = fmaf(wq[h], s_hhold[half * 64 + h], qa);
            s_qp[t] = qa;
        }
        __syncthreads();
        if (t < Hz) s_q[t] = s_qp[t] + s_qp[Hz + t] + b_q[t];
        __syncthreads();

        // ---- attention scan over this block's 512 s positions ----
        const float* bp = g_base + ((size_t)(b * Hz)) * Sz + k * SCHUNK + t;
        float a0 = 0.f, a1 = 0.f;
        #pragma unroll 4
        for (int g = 0; g < Hz; ++g) {
            float qg = s_q[g], w = s_watt[g];
            float x0 = qg + bp[0];
            float x1 = qg + bp[256];
            a0 = fmaf(w, tanh_fast(x0), a0);
            a1 = fmaf(w, tanh_fast(x1), a1);
            bp += Sz;
        }
        // CRITICAL: replicate the reference's fp32 quantization `attns + 10000.0`.
        // ulp(10000) ~ 9.77e-4 quantizes the scores and creates argmax ties that
        // jnp.argmax breaks by lowest index. All reductions below use aq values.
        a0 = a0 + 10000.0f;
        a1 = a1 + 10000.0f;
        int sA = k * SCHUNK + t, sB = sA + 256;
        float m, sm; int id;
        if (a1 > a0) { m = a1; id = sB; sm = expf(a0 - a1) + 1.f; }
        else         { m = a0; id = sA; sm = 1.f + expf(a1 - a0); }
        s_red[t] = m; s_redi[t] = id; s_red2[t] = sm;
        __syncthreads();
        for (int off = NT / 2; off > 0; off >>= 1) {
            if (t < off) {
                float m1 = s_red[t],        m2 = s_red[t + off];
                int   i1 = s_redi[t],       i2 = s_redi[t + off];
                float sm1 = s_red2[t],      sm2 = s_red2[t + off];
                float nm; int ni;
                if (m2 > m1 || (m2 == m1 && i2 < i1)) { nm = m2; ni = i2; }
                else                                   { nm = m1; ni = i1; }
                s_red[t] = nm; s_redi[t] = ni;
                s_red2[t] = sm1 * expf(m1 - nm) + sm2 * expf(m2 - nm);
            }
            __syncthreads();
        }
        if (t == 0) { g_pm[b][k] = s_red[0]; g_pi[b][k] = s_redi[0]; g_ps[b][k] = s_red2[0]; }
        grid_barrier();

        // ---- phase E: combine partials, emit outputs, gather next dec_in ----
        if (t == 0) {
            float mm = -INFINITY, tot = 0.f; int id2 = 0x7FFFFFFF;
            for (int kk = 0; kk < NBPB; ++kk) {
                float mk = g_pm[b][kk], sk = g_ps[b][kk];
                int   ik = g_pi[b][kk];
                if (mk > mm || (mk == mm && ik < id2)) {
                    tot = tot * expf(mm - mk) + sk;
                    mm = mk; id2 = ik;
                } else {
                    tot += sk * expf(mk - mm);
                }
            }
            float logp = -logf(tot);   // log(max softmax)
            if (k == 0) {
                int oi = b * STEPS + step;
                if (oi < out_size) out[oi] = (float)id2;
                int oj = Bz * STEPS + oi;
                if (oj < out_size) out[oj] = logp;
            }
            s_dec[0] = st[(b * 2 + 0) * Sz + id2];
            s_dec[1] = st[(b * 2 + 1) * Sz + id2];
        }
        // next iteration's leading __syncthreads publishes s_dec
    }
}

extern "C" void kernel_launch(void* const* d_in, const int* in_sizes, int n_in,
                              void* d_out, int out_size) {
    const float* st    = (const float*)d_in[0];
    const float* dyn   = (const float*)d_in[1];
    const float* W_s   = (const float*)d_in[2];
    const float* b_s   = (const float*)d_in[3];
    const float* W_d   = (const float*)d_in[4];
    const float* b_d   = (const float*)d_in[5];
    const float* W_dec = (const float*)d_in[6];
    const float* b_dec = (const float*)d_in[7];
    const float* W_ih  = (const float*)d_in[8];
    const float* W_hh  = (const float*)d_in[9];
    const float* b_ih  = (const float*)d_in[10];
    const float* b_hh  = (const float*)d_in[11];
    const float* W_ref = (const float*)d_in[12];
    const float* b_ref = (const float*)d_in[13];
    const float* W_pd  = (const float*)d_in[14];
    const float* b_pd  = (const float*)d_in[15];
    const float* W_q   = (const float*)d_in[16];
    const float* b_q   = (const float*)d_in[17];
    const float* W_att = (const float*)d_in[18];

    coef_kernel<<<1, Hz>>>(W_ref, W_s, b_s, b_ref, W_pd, W_d, b_d, b_pd);
    persist_kernel<<<NB, NT>>>(st, dyn, W_dec, b_dec, W_ih, W_hh, b_ih, b_hh,
                               W_q, b_q, W_att, (float*)d_out, out_size);
}

// round 3
// speedup vs baseline: 1.2238x; 1.2238x over previous
#include <cuda_runtime.h>
#include <math.h>

#define Bz 8
#define Sz 8192
#define Hz 128
#define STEPS 20
#define NBPB 16              // blocks per batch
#define NB (Bz * NBPB)       // 128 blocks (<=148 SMs -> co-resident)
#define NT 512               // 16 warps/block
#define SCHUNK 512           // positions per block

typedef unsigned long long ull;

// -------- persistent scratch --------
__device__ __align__(16) float g_base[(size_t)Bz * Hz * Sz];  // 33.5 MB, L2-resident
__device__ float g_coef[4 * Hz];
__device__ float g_hh[2][Bz][Hz];
__device__ float g_cc[Bz][Hz];
__device__ float g_pm[Bz][NBPB];
__device__ int   g_pi[Bz][NBPB];
__device__ float g_ps[Bz][NBPB];
__device__ int   g_bmax_i;
__device__ unsigned g_barcnt = 0;
__device__ unsigned g_bargen = 0;

__device__ __forceinline__ void grid_barrier() {
    __syncthreads();
    if (threadIdx.x == 0) {
        volatile unsigned* genp = &g_bargen;
        unsigned gen = *genp;
        __threadfence();
        unsigned arrived = atomicAdd(&g_barcnt, 1u);
        if (arrived == NB - 1) {
            g_barcnt = 0;
            __threadfence();
            atomicAdd(&g_bargen, 1u);
        } else {
            while (*genp == gen) { }
        }
        __threadfence();
    }
    __syncthreads();
}

// -------- packed f32x2 helpers --------
__device__ __forceinline__ ull f2add(ull a, ull b) {
    ull d; asm("add.rn.f32x2 %0, %1, %2;" : "=l"(d) : "l"(a), "l"(b)); return d;
}
__device__ __forceinline__ ull f2mul(ull a, ull b) {
    ull d; asm("mul.rn.f32x2 %0, %1, %2;" : "=l"(d) : "l"(a), "l"(b)); return d;
}
__device__ __forceinline__ ull f2fma(ull a, ull b, ull c) {
    ull d; asm("fma.rn.f32x2 %0, %1, %2, %3;" : "=l"(d) : "l"(a), "l"(b), "l"(c)); return d;
}
__device__ __forceinline__ ull dup2(float f) {
    ull d; asm("mov.b64 %0, {%1, %2};" : "=l"(d) : "f"(f), "f"(f)); return d;
}
__device__ __forceinline__ void unpack2(ull v, float& lo, float& hi) {
    asm("mov.b64 {%0, %1}, %2;" : "=f"(lo), "=f"(hi) : "l"(v));
}

// Taylor tanh over packed pair. NC=4 -> deg-9 (|x|<=0.32, err<9e-8),
// NC=6 -> deg-13 (|x|<=0.55, err<2e-7).
template<int NC>
__device__ __forceinline__ ull scan_loop(const ull* __restrict__ bp,
                                         const ulonglong2* __restrict__ qwp) {
    const ull C1 = dup2(-0.33333334f);
    const ull C2 = dup2( 0.13333334f);
    const ull C3 = dup2(-0.053968254f);
    const ull C4 = dup2( 0.021869489f);
    const ull C5 = dup2(-0.008863236f);
    const ull C6 = dup2( 0.0035921280f);
    const ull ONE = dup2(1.0f);
    ull A = 0ull;
    #pragma unroll 16
    for (int j = 0; j < 64; ++j) {
        ull V = bp[(size_t)j << 12];          // stride Sz floats = 4096 ull
        ulonglong2 qw = qwp[j];               // (q,q),(w,w)
        ull X = f2add(V, qw.x);
        ull Y = f2mul(X, X);
        ull P;
        if (NC == 6) {
            P = f2fma(Y, C6, C5);
            P = f2fma(P, Y, C4);
            P = f2fma(P, Y, C3);
        } else {
            P = f2fma(Y, C4, C3);
        }
        P = f2fma(P, Y, C2);
        P = f2fma(P, Y, C1);
        P = f2fma(P, Y, ONE);
        ull T = f2mul(X, P);
        A = f2fma(qw.y, T, A);
    }
    return A;
}

__device__ __forceinline__ float sigmoidf(float x) { return 1.f / (1.f + expf(-x)); }

// combine (m,id,ss) partial-softmax triples; lower id wins ties
#define SMAX_COMBINE(m, id, ss, mo, io, so)                          \
    if ((mo) > (m) || ((mo) == (m) && (io) < (id))) {                \
        (ss) = (ss) * expf((m) - (mo)) + (so);                       \
        (m) = (mo); (id) = (io);                                     \
    } else {                                                         \
        (ss) = (ss) + (so) * expf((mo) - (m));                       \
    }

// -------- K0: fold per-step projections to rank-3 affine coefficients --------
__global__ void coef_kernel(const float* __restrict__ W_ref, const float* __restrict__ W_s,
                            const float* __restrict__ b_s,   const float* __restrict__ b_ref,
                            const float* __restrict__ W_pd,  const float* __restrict__ W_d,
                            const float* __restrict__ b_d,   const float* __restrict__ b_pd) {
    int g = threadIdx.x;
    if (g == 0) g_bmax_i = 0;
    float a0 = 0.f, a1 = 0.f, dd = 0.f, c = 0.f;
    for (int h = 0; h < Hz; ++h) {
        float wr = W_ref[g * Hz + h];
        a0 = fmaf(wr, W_s[h * 2 + 0], a0);
        a1 = fmaf(wr, W_s[h * 2 + 1], a1);
        c  = fmaf(wr, b_s[h], c);
        float wp = W_pd[g * Hz + h];
        dd = fmaf(wp, W_d[h], dd);
        c  = fmaf(wp, b_d[h], c);
    }
    c += b_ref[g] + b_pd[g];
    g_coef[g] = a0; g_coef[Hz + g] = a1; g_coef[2 * Hz + g] = dd; g_coef[3 * Hz + g] = c;
}

// -------- persistent decode kernel --------
__global__ __launch_bounds__(NT, 1)
void persist_kernel(const float* __restrict__ st,   const float* __restrict__ dyn,
                    const float* __restrict__ W_dec, const float* __restrict__ b_dec,
                    const float* __restrict__ W_ih,  const float* __restrict__ W_hh,
                    const float* __restrict__ b_ih,  const float* __restrict__ b_hh,
                    const float* __restrict__ W_q,   const float* __restrict__ b_q,
                    const float* __restrict__ W_att,
                    float* __restrict__ out, int out_size) {
    const int blk = blockIdx.x;
    const int b = blk / NBPB;
    const int k = blk % NBPB;
    const int t = threadIdx.x;

    __shared__ float s_coef[4 * Hz];
    __shared__ float s_q[Hz];
    __shared__ float s_watt[Hz];
    __shared__ ulonglong2 s_qw[Hz];   // (q,q),(w,w) packed pairs
    __shared__ float s_dh[Hz];
    __shared__ float s_hhold[Hz];
    __shared__ float s_dec[2];
    __shared__ float s_gate[32];
    __shared__ float s_red[256];
    __shared__ float s_qp[NT];
    __shared__ float2 s_Ah[256];
    __shared__ float s_wm[8];
    __shared__ int   s_wi[8];
    __shared__ float s_ws[8];
    __shared__ int   s_path;
    __shared__ int   s_imax;

    // ---- phase 0: materialize base[b,g,s] + track max|base| ----
    s_coef[t < 512 ? t : 0] = g_coef[t < 512 ? t : 0];
    if (t == 0) s_imax = 0;
    __syncthreads();
    {
        float lmax = 0.f;
        const int tot = Bz * Hz * Sz;
        for (int idx = blk * NT + t; idx < tot; idx += NB * NT) {
            int s  = idx & (Sz - 1);
            int g  = (idx >> 13) & (Hz - 1);
            int bb = idx >> 20;
            float x = st[(bb * 2 + 0) * Sz + s];
            float y = st[(bb * 2 + 1) * Sz + s];
            float d = dyn[bb * Sz + s];
            float v = fmaf(s_coef[g], x,
                      fmaf(s_coef[Hz + g], y,
                      fmaf(s_coef[2 * Hz + g], d, s_coef[3 * Hz + g])));
            g_base[idx] = v;
            lmax = fmaxf(lmax, fabsf(v));
        }
        atomicMax(&s_imax, __float_as_int(lmax));
    }
    if (t < 8) { int g = k * 8 + t; g_hh[0][b][g] = 0.f; g_cc[b][g] = 0.f; }
    if (t < Hz) s_watt[t] = W_att[t];
    if (t == 0) { s_dec[0] = 0.f; s_dec[1] = 0.f; }
    __syncthreads();
    if (t == 0) atomicMax(&g_bmax_i, s_imax);
    grid_barrier();
    const float Mb = __int_as_float(g_bmax_i);

    for (int step = 0; step < STEPS; ++step) {
        const int p = step & 1;

        // ---- LSTM: this block computes hidden slice g in [8k, 8k+8) ----
        if (t < Hz) {
            s_hhold[t] = g_hh[p][b][t];
            s_dh[t] = fmaf(W_dec[t * 2 + 0], s_dec[0],
                      fmaf(W_dec[t * 2 + 1], s_dec[1], b_dec[t]));
        }
        __syncthreads();
        if (t < 256) {
            int row = t >> 3, l8 = t & 7;
            int q4 = row >> 3, r = row & 7;
            int j = q4 * Hz + k * 8 + r;
            const float* wi = W_ih + j * Hz + l8 * 16;
            const float* wh = W_hh + j * Hz + l8 * 16;
            float acc = 0.f;
            #pragma unroll
            for (int h = 0; h < 16; ++h)
                acc = fmaf(wi[h], s_dh[l8 * 16 + h], fmaf(wh[h], s_hhold[l8 * 16 + h], acc));
            s_red[t] = acc;
        }
        __syncthreads();
        if (t < 32) {
            float gsum = 0.f;
            #pragma unroll
            for (int x = 0; x < 8; ++x) gsum += s_red[t * 8 + x];
            int jj = (t >> 3) * Hz + k * 8 + (t & 7);
            s_gate[t] = gsum + b_ih[jj] + b_hh[jj];
        }
        __syncthreads();
        if (t < 8) {
            int g = k * 8 + t;
            float ig = s_gate[t], fg = s_gate[8 + t], gg = s_gate[16 + t], og = s_gate[24 + t];
            float c  = g_cc[b][g];
            float c2 = fmaf(sigmoidf(fg), c, sigmoidf(ig) * tanhf(gg));
            float h2 = sigmoidf(og) * tanhf(c2);
            g_cc[b][g] = c2;
            g_hh[1 - p][b][g] = h2;
        }
        grid_barrier();

        // ---- q = W_q @ hh_new + b_q (redundant per block) ----
        if (t < Hz) s_hhold[t] = g_hh[1 - p][b][t];
        __syncthreads();
        {
            int g = t & (Hz - 1), qtr = t >> 7;
            const float* wq = W_q + g * Hz + qtr * 32;
            float qa = 0.f;
            #pragma unroll
            for (int h = 0; h < 32; ++h) qa = fmaf(wq[h], s_hhold[qtr * 32 + h], qa);
            s_qp[t] = qa;
        }
        __syncthreads();
        if (t < Hz) {
            float qv = s_qp[t] + s_qp[Hz + t] + s_qp[2 * Hz + t] + s_qp[3 * Hz + t] + b_q[t];
            s_q[t] = qv;
            ulonglong2 e; e.x = dup2(qv); e.y = dup2(s_watt[t]);
            s_qw[t] = e;
            float myq = fabsf(qv);
            #pragma unroll
            for (int off = 16; off > 0; off >>= 1)
                myq = fmaxf(myq, __shfl_down_sync(0xffffffffu, myq, off));
            if ((t & 31) == 0) s_wm[t >> 5] = myq;
        }
        __syncthreads();
        if (t == 0) {
            float bound = fmaxf(fmaxf(s_wm[0], s_wm[1]), fmaxf(s_wm[2], s_wm[3])) + Mb;
            s_path = (bound <= 0.32f) ? 0 : ((bound <= 0.55f) ? 1 : 2);
        }
        __syncthreads();

        // ---- attention scan: thread = (position pair pp, g-half gh) ----
        const int pp = t & 255, gh = t >> 8;
        const ull* bp = ((const ull*)g_base)
                      + (((size_t)(b * Hz + gh * 64)) << 12) + (k << 8) + pp;
        const int path = s_path;
        float a0, a1;
        if (path <= 1) {
            ull A = (path == 0) ? scan_loop<4>(bp, s_qw + gh * 64)
                                : scan_loop<6>(bp, s_qw + gh * 64);
            unpack2(A, a0, a1);
        } else {
            a0 = 0.f; a1 = 0.f;
            const float2* fp = ((const float2*)g_base)
                             + (((size_t)(b * Hz + gh * 64)) << 12) + (k << 8) + pp;
            for (int j = 0; j < 64; ++j) {
                float2 v = fp[(size_t)j << 12];
                float qv = s_q[gh * 64 + j], w = s_watt[gh * 64 + j];
                a0 = fmaf(w, tanhf(v.x + qv), a0);
                a1 = fmaf(w, tanhf(v.y + qv), a1);
            }
        }
        if (gh == 1) s_Ah[pp] = make_float2(a0, a1);
        __syncthreads();

        // ---- reduce to per-block partial (m, id, ssum) over 512 positions ----
        if (gh == 0) {
            float2 o = s_Ah[pp];
            // replicate reference fp32 quantization `attns + 10000.0`
            float aq0 = (a0 + o.x) + 10000.0f;
            float aq1 = (a1 + o.y) + 10000.0f;
            int s0 = k * SCHUNK + 2 * pp;
            float m, ss; int id;
            if (aq1 > aq0) { m = aq1; id = s0 + 1; ss = 1.f + expf(aq0 - aq1); }
            else           { m = aq0; id = s0;     ss = 1.f + expf(aq1 - aq0); }
            #pragma unroll
            for (int off = 16; off > 0; off >>= 1) {
                float mo = __shfl_down_sync(0xffffffffu, m, off);
                int   io = __shfl_down_sync(0xffffffffu, id, off);
                float so = __shfl_down_sync(0xffffffffu, ss, off);
                SMAX_COMBINE(m, id, ss, mo, io, so);
            }
            if ((t & 31) == 0) { int w = t >> 5; s_wm[w] = m; s_wi[w] = id; s_ws[w] = ss; }
        }
        __syncthreads();
        if (t < 32) {
            float m  = (t < 8) ? s_wm[t] : -1e30f;
            int   id = (t < 8) ? s_wi[t] : 0x7FFFFFFF;
            float ss = (t < 8) ? s_ws[t] : 0.f;
            #pragma unroll
            for (int off = 4; off > 0; off >>= 1) {
                float mo = __shfl_down_sync(0xffffffffu, m, off);
                int   io = __shfl_down_sync(0xffffffffu, id, off);
                float so = __shfl_down_sync(0xffffffffu, ss, off);
                SMAX_COMBINE(m, id, ss, mo, io, so);
            }
            if (t == 0) { g_pm[b][k] = m; g_pi[b][k] = id; g_ps[b][k] = ss; }
        }
        grid_barrier();

        // ---- combine 16 partials (redundant in every block), emit, gather ----
        if (t < 32) {
            float m  = (t < NBPB) ? g_pm[b][t] : -1e30f;
            int   id = (t < NBPB) ? g_pi[b][t] : 0x7FFFFFFF;
            float ss = (t < NBPB) ? g_ps[b][t] : 0.f;
            #pragma unroll
            for (int off = 8; off > 0; off >>= 1) {
                float mo = __shfl_down_sync(0xffffffffu, m, off);
                int   io = __shfl_down_sync(0xffffffffu, id, off);
                float so = __shfl_down_sync(0xffffffffu, ss, off);
                SMAX_COMBINE(m, id, ss, mo, io, so);
            }
            if (t == 0) {
                float logp = -logf(ss);     // log(max softmax)
                if (k == 0) {
                    int oi = b * STEPS + step;
                    if (oi < out_size) out[oi] = (float)id;
                    int oj = Bz * STEPS + oi;
                    if (oj < out_size) out[oj] = logp;
                }
                s_dec[0] = st[(b * 2 + 0) * Sz + id];
                s_dec[1] = st[(b * 2 + 1) * Sz + id];
            }
        }
        __syncthreads();   // publish s_dec for next step's LSTM
    }
}

extern "C" void kernel_launch(void* const* d_in, const int* in_sizes, int n_in,
                              void* d_out, int out_size) {
    const float* st    = (const float*)d_in[0];
    const float* dyn   = (const float*)d_in[1];
    const float* W_s   = (const float*)d_in[2];
    const float* b_s   = (const float*)d_in[3];
    const float* W_d   = (const float*)d_in[4];
    const float* b_d   = (const float*)d_in[5];
    const float* W_dec = (const float*)d_in[6];
    const float* b_dec = (const float*)d_in[7];
    const float* W_ih  = (const float*)d_in[8];
    const float* W_hh  = (const float*)d_in[9];
    const float* b_ih  = (const float*)d_in[10];
    const float* b_hh  = (const float*)d_in[11];
    const float* W_ref = (const float*)d_in[12];
    const float* b_ref = (const float*)d_in[13];
    const float* W_pd  = (const float*)d_in[14];
    const float* b_pd  = (const float*)d_in[15];
    const float* W_q   = (const float*)d_in[16];
    const float* b_q   = (const float*)d_in[17];
    const float* W_att = (const float*)d_in[18];

    coef_kernel<<<1, Hz>>>(W_ref, W_s, b_s, b_ref, W_pd, W_d, b_d, b_pd);
    persist_kernel<<<NB, NT>>>(st, dyn, W_dec, b_dec, W_ih, W_hh, b_ih, b_hh,
                               W_q, b_q, W_att, (float*)d_out, out_size);
}

// round 4
// speedup vs baseline: 1.7773x; 1.4523x over previous
#include <cuda_runtime.h>
#include <math.h>

#define Bz 8
#define Sz 8192
#define Hz 128
#define STEPS 20
#define NBPB 16              // blocks per batch
#define NB (Bz * NBPB)       // 128 blocks (<=148 SMs -> co-resident)
#define NT 512               // 16 warps/block
#define SCHUNK 512           // positions per block (== NT)
#define SROWS 104            // g-rows staged in SMEM (104*512*4 = 213 KB)
#define RROWS (Hz - SROWS)   // 24 g-rows left in L2

typedef unsigned long long ull;

// -------- persistent scratch --------
__device__ __align__(16) float g_rest[(size_t)Bz * RROWS * Sz];  // 6.3 MB, L2-resident
__device__ float g_coef[4 * Hz];
__device__ float g_hh[2][Bz][Hz];
__device__ float g_cc[Bz][Hz];
__device__ float g_pm[Bz][NBPB];
__device__ int   g_pi[Bz][NBPB];
__device__ float g_ps[Bz][NBPB];
__device__ int   g_bmax[Bz];
__device__ unsigned g_bcnt[Bz];
__device__ unsigned g_bgen[Bz];

// -------- batch-local barrier (16 blocks of one batch) --------
__device__ __forceinline__ void batch_barrier(int b) {
    __syncthreads();
    if (threadIdx.x == 0) {
        volatile unsigned* genp = &g_bgen[b];
        unsigned gen = *genp;
        __threadfence();
        unsigned arrived = atomicAdd(&g_bcnt[b], 1u);
        if (arrived == NBPB - 1) {
            g_bcnt[b] = 0;
            __threadfence();
            atomicAdd(&g_bgen[b], 1u);
        } else {
            while (*genp == gen) { }
        }
        __threadfence();
    }
    __syncthreads();
}

// -------- packed f32x2 helpers --------
__device__ __forceinline__ ull f2add(ull a, ull b) {
    ull d; asm("add.rn.f32x2 %0, %1, %2;" : "=l"(d) : "l"(a), "l"(b)); return d;
}
__device__ __forceinline__ ull f2mul(ull a, ull b) {
    ull d; asm("mul.rn.f32x2 %0, %1, %2;" : "=l"(d) : "l"(a), "l"(b)); return d;
}
__device__ __forceinline__ ull f2fma(ull a, ull b, ull c) {
    ull d; asm("fma.rn.f32x2 %0, %1, %2, %3;" : "=l"(d) : "l"(a), "l"(b), "l"(c)); return d;
}
__device__ __forceinline__ ull dup2(float f) {
    ull d; asm("mov.b64 %0, {%1, %2};" : "=l"(d) : "f"(f), "f"(f)); return d;
}
__device__ __forceinline__ void unpack2(ull v, float& lo, float& hi) {
    asm("mov.b64 {%0, %1}, %2;" : "=f"(lo), "=f"(hi) : "l"(v));
}

// packed tanh poly step: NC=4 -> deg-9 (|x|<=0.32), NC=6 -> deg-13 (|x|<=0.55)
template<int NC>
__device__ __forceinline__ ull poly_acc(ull V, ulonglong2 qw, ull A) {
    const ull C1 = dup2(-0.33333334f);
    const ull C2 = dup2( 0.13333334f);
    const ull C3 = dup2(-0.053968254f);
    const ull C4 = dup2( 0.021869489f);
    const ull C5 = dup2(-0.008863236f);
    const ull C6 = dup2( 0.0035921280f);
    const ull ONE = dup2(1.0f);
    ull X = f2add(V, qw.x);
    ull Y = f2mul(X, X);
    ull P;
    if (NC == 6) {
        P = f2fma(Y, C6, C5);
        P = f2fma(P, Y, C4);
        P = f2fma(P, Y, C3);
    } else {
        P = f2fma(Y, C4, C3);
    }
    P = f2fma(P, Y, C2);
    P = f2fma(P, Y, C1);
    P = f2fma(P, Y, ONE);
    return f2fma(qw.y, f2mul(X, P), A);
}

template<int NC, int G0, int G1>
__device__ __forceinline__ ull scan_smem(const float* __restrict__ sb, int pp,
                                         const ulonglong2* __restrict__ qwp, ull A) {
    const ull* p = (const ull*)sb + pp;
    #pragma unroll
    for (int g = G0; g < G1; ++g)
        A = poly_acc<NC>(p[(size_t)g << 8], qwp[g], A);
    return A;
}

template<int NC>
__device__ __forceinline__ ull scan_rest(const ull* __restrict__ rp,
                                         const ulonglong2* __restrict__ qwp, ull A) {
    #pragma unroll 8
    for (int j = 0; j < RROWS; ++j)
        A = poly_acc<NC>(rp[(size_t)j * (Sz / 2)], qwp[j], A);
    return A;
}

__device__ __forceinline__ float sigmoidf(float x) { return 1.f / (1.f + expf(-x)); }

#define SMAX_COMBINE(m, id, ss, mo, io, so)                          \
    if ((mo) > (m) || ((mo) == (m) && (io) < (id))) {                \
        (ss) = (ss) * expf((m) - (mo)) + (so);                       \
        (m) = (mo); (id) = (io);                                     \
    } else {                                                         \
        (ss) = (ss) + (so) * expf((mo) - (m));                       \
    }

// -------- K0: fold per-step projections to rank-3 affine coefficients --------
__global__ void coef_kernel(const float* __restrict__ W_ref, const float* __restrict__ W_s,
                            const float* __restrict__ b_s,   const float* __restrict__ b_ref,
                            const float* __restrict__ W_pd,  const float* __restrict__ W_d,
                            const float* __restrict__ b_d,   const float* __restrict__ b_pd) {
    int g = threadIdx.x;
    float a0 = 0.f, a1 = 0.f, dd = 0.f, c = 0.f;
    for (int h = 0; h < Hz; ++h) {
        float wr = W_ref[g * Hz + h];
        a0 = fmaf(wr, W_s[h * 2 + 0], a0);
        a1 = fmaf(wr, W_s[h * 2 + 1], a1);
        c  = fmaf(wr, b_s[h], c);
        float wp = W_pd[g * Hz + h];
        dd = fmaf(wp, W_d[h], dd);
        c  = fmaf(wp, b_d[h], c);
    }
    c += b_ref[g] + b_pd[g];
    g_coef[g] = a0; g_coef[Hz + g] = a1; g_coef[2 * Hz + g] = dd; g_coef[3 * Hz + g] = c;
}

// -------- persistent decode kernel --------
__global__ __launch_bounds__(NT, 1)
void persist_kernel(const float* __restrict__ st,   const float* __restrict__ dyn,
                    const float* __restrict__ W_dec, const float* __restrict__ b_dec,
                    const float* __restrict__ W_ih,  const float* __restrict__ W_hh,
                    const float* __restrict__ b_ih,  const float* __restrict__ b_hh,
                    const float* __restrict__ W_q,   const float* __restrict__ b_q,
                    const float* __restrict__ W_att,
                    float* __restrict__ out, int out_size) {
    const int blk = blockIdx.x;
    const int b = blk / NBPB;
    const int k = blk % NBPB;
    const int t = threadIdx.x;

    extern __shared__ float s_base[];   // SROWS * 512 floats

    __shared__ float s_coef[4 * Hz];
    __shared__ float s_q[Hz];
    __shared__ float s_watt[Hz];
    __shared__ ulonglong2 s_qw[Hz];     // (q,q),(w,w) packed pairs
    __shared__ float s_dh[Hz];
    __shared__ float s_hhold[Hz];
    __shared__ float s_dec[2];
    __shared__ float s_gate[32];
    __shared__ float s_red[256];
    __shared__ float s_qp[Hz];
    __shared__ float2 s_Ah[256];
    __shared__ float s_wm[8];
    __shared__ int   s_wi[8];
    __shared__ float s_ws[8];
    __shared__ int   s_path;
    __shared__ int   s_imax;

    // ---- phase 0: stage base slice (SROWS rows -> smem, RROWS rows -> L2) ----
    s_coef[t] = g_coef[t];   // NT == 4*Hz == 512
    if (t == 0) s_imax = 0;
    __syncthreads();
    {
        const int s = k * SCHUNK + t;         // this thread's position
        const float x = st[(b * 2 + 0) * Sz + s];
        const float y = st[(b * 2 + 1) * Sz + s];
        const float d = dyn[b * Sz + s];
        float lmax = 0.f;
        #pragma unroll 8
        for (int g = 0; g < SROWS; ++g) {
            float v = fmaf(s_coef[g], x,
                      fmaf(s_coef[Hz + g], y,
                      fmaf(s_coef[2 * Hz + g], d, s_coef[3 * Hz + g])));
            s_base[g * SCHUNK + t] = v;
            lmax = fmaxf(lmax, fabsf(v));
        }
        #pragma unroll
        for (int j = 0; j < RROWS; ++j) {
            int g = SROWS + j;
            float v = fmaf(s_coef[g], x,
                      fmaf(s_coef[Hz + g], y,
                      fmaf(s_coef[2 * Hz + g], d, s_coef[3 * Hz + g])));
            g_rest[((size_t)(b * RROWS + j)) * Sz + s] = v;
            lmax = fmaxf(lmax, fabsf(v));
        }
        atomicMax(&s_imax, __float_as_int(lmax));
    }
    if (t < 8) { int g = k * 8 + t; g_hh[0][b][g] = 0.f; g_cc[b][g] = 0.f; }
    if (t < Hz) s_watt[t] = W_att[t];
    if (t == 0) { s_dec[0] = 0.f; s_dec[1] = 0.f; }
    __syncthreads();
    if (t == 0) atomicMax(&g_bmax[b], s_imax);
    batch_barrier(b);
    const float Mb = __int_as_float(g_bmax[b]);

    for (int step = 0; step < STEPS; ++step) {
        const int p = step & 1;

        // ---- LSTM: this block computes hidden slice g in [8k, 8k+8) ----
        if (t < Hz) {
            s_hhold[t] = g_hh[p][b][t];
            s_dh[t] = fmaf(W_dec[t * 2 + 0], s_dec[0],
                      fmaf(W_dec[t * 2 + 1], s_dec[1], b_dec[t]));
        }
        __syncthreads();
        if (t < 256) {
            int row = t >> 3, l8 = t & 7;
            int q4 = row >> 3, r = row & 7;
            int j = q4 * Hz + k * 8 + r;
            const float* wi = W_ih + j * Hz + l8 * 16;
            const float* wh = W_hh + j * Hz + l8 * 16;
            float acc = 0.f;
            #pragma unroll
            for (int h = 0; h < 16; ++h)
                acc = fmaf(wi[h], s_dh[l8 * 16 + h], fmaf(wh[h], s_hhold[l8 * 16 + h], acc));
            s_red[t] = acc;
        }
        __syncthreads();
        if (t < 32) {
            float gsum = 0.f;
            #pragma unroll
            for (int x = 0; x < 8; ++x) gsum += s_red[t * 8 + x];
            int jj = (t >> 3) * Hz + k * 8 + (t & 7);
            s_gate[t] = gsum + b_ih[jj] + b_hh[jj];
        }
        __syncthreads();
        if (t < 8) {
            int g = k * 8 + t;
            float ig = s_gate[t], fg = s_gate[8 + t], gg = s_gate[16 + t], og = s_gate[24 + t];
            float c  = g_cc[b][g];
            float c2 = fmaf(sigmoidf(fg), c, sigmoidf(ig) * tanhf(gg));
            float h2 = sigmoidf(og) * tanhf(c2);
            g_cc[b][g] = c2;
            g_hh[1 - p][b][g] = h2;
        }
        batch_barrier(b);

        // ---- q = W_q @ hh_new + b_q (redundant per block, coalesced) ----
        if (t < Hz) s_hhold[t] = g_hh[1 - p][b][t];
        __syncthreads();
        {
            int w = t >> 5, l = t & 31;
            #pragma unroll
            for (int r8 = 0; r8 < 8; ++r8) {
                int row = w * 8 + r8;
                const float* wq = W_q + row * Hz;
                float acc = fmaf(wq[l], s_hhold[l],
                            fmaf(wq[l + 32], s_hhold[l + 32],
                            fmaf(wq[l + 64], s_hhold[l + 64],
                                 wq[l + 96] * s_hhold[l + 96])));
                #pragma unroll
                for (int off = 16; off > 0; off >>= 1)
                    acc += __shfl_down_sync(0xffffffffu, acc, off);
                if (l == 0) s_qp[row] = acc;
            }
        }
        __syncthreads();
        if (t < Hz) {
            float qv = s_qp[t] + b_q[t];
            s_q[t] = qv;
            ulonglong2 e; e.x = dup2(qv); e.y = dup2(s_watt[t]);
            s_qw[t] = e;
            float myq = fabsf(qv);
            #pragma unroll
            for (int off = 16; off > 0; off >>= 1)
                myq = fmaxf(myq, __shfl_down_sync(0xffffffffu, myq, off));
            if ((t & 31) == 0) s_wm[t >> 5] = myq;
        }
        __syncthreads();
        if (t == 0) {
            float bound = fmaxf(fmaxf(s_wm[0], s_wm[1]), fmaxf(s_wm[2], s_wm[3])) + Mb;
            s_path = (bound <= 0.32f) ? 0 : ((bound <= 0.55f) ? 1 : 2);
        }
        __syncthreads();

        // ---- attention scan: thread = (position pair pp, g-half gh) ----
        const int pp = t & 255, gh = t >> 8;
        const int path = s_path;
        const ull* rp = (const ull*)g_rest + ((size_t)(b * RROWS) * Sz >> 1)
                      + (k << 8) + pp;
        float a0, a1;
        if (path <= 1) {
            ull A = 0ull;
            if (path == 0) {
                if (gh == 0) {
                    A = scan_smem<4, 0, 64>(s_base, pp, s_qw, A);
                } else {
                    A = scan_rest<4>(rp, s_qw + SROWS, A);
                    A = scan_smem<4, 64, SROWS>(s_base, pp, s_qw, A);
                }
            } else {
                if (gh == 0) {
                    A = scan_smem<6, 0, 64>(s_base, pp, s_qw, A);
                } else {
                    A = scan_rest<6>(rp, s_qw + SROWS, A);
                    A = scan_smem<6, 64, SROWS>(s_base, pp, s_qw, A);
                }
            }
            unpack2(A, a0, a1);
        } else {
            a0 = 0.f; a1 = 0.f;
            const float2* sp = (const float2*)s_base + pp;
            if (gh == 0) {
                for (int g = 0; g < 64; ++g) {
                    float2 v = sp[g << 8];
                    float qv = s_q[g], w = s_watt[g];
                    a0 = fmaf(w, tanhf(v.x + qv), a0);
                    a1 = fmaf(w, tanhf(v.y + qv), a1);
                }
            } else {
                const float2* fp = (const float2*)g_rest
                                 + ((size_t)(b * RROWS) * Sz >> 1) + (k << 8) + pp;
                for (int j = 0; j < RROWS; ++j) {
                    float2 v = fp[(size_t)j * (Sz / 2)];
                    float qv = s_q[SROWS + j], w = s_watt[SROWS + j];
                    a0 = fmaf(w, tanhf(v.x + qv), a0);
                    a1 = fmaf(w, tanhf(v.y + qv), a1);
                }
                for (int g = 64; g < SROWS; ++g) {
                    float2 v = sp[g << 8];
                    float qv = s_q[g], w = s_watt[g];
                    a0 = fmaf(w, tanhf(v.x + qv), a0);
                    a1 = fmaf(w, tanhf(v.y + qv), a1);
                }
            }
        }
        if (gh == 1) s_Ah[pp] = make_float2(a0, a1);
        __syncthreads();

        // ---- reduce to per-block partial (m, id, ssum) over 512 positions ----
        if (gh == 0) {
            float2 o = s_Ah[pp];
            // replicate reference fp32 quantization `attns + 10000.0`
            float aq0 = (a0 + o.x) + 10000.0f;
            float aq1 = (a1 + o.y) + 10000.0f;
            int s0 = k * SCHUNK + 2 * pp;
            float m, ss; int id;
            if (aq1 > aq0) { m = aq1; id = s0 + 1; ss = 1.f + expf(aq0 - aq1); }
            else           { m = aq0; id = s0;     ss = 1.f + expf(aq1 - aq0); }
            #pragma unroll
            for (int off = 16; off > 0; off >>= 1) {
                float mo = __shfl_down_sync(0xffffffffu, m, off);
                int   io = __shfl_down_sync(0xffffffffu, id, off);
                float so = __shfl_down_sync(0xffffffffu, ss, off);
                SMAX_COMBINE(m, id, ss, mo, io, so);
            }
            if ((t & 31) == 0) { int w = t >> 5; s_wm[w] = m; s_wi[w] = id; s_ws[w] = ss; }
        }
        __syncthreads();
        if (t < 32) {
            float m  = (t < 8) ? s_wm[t] : -1e30f;
            int   id = (t < 8) ? s_wi[t] : 0x7FFFFFFF;
            float ss = (t < 8) ? s_ws[t] : 0.f;
            #pragma unroll
            for (int off = 4; off > 0; off >>= 1) {
                float mo = __shfl_down_sync(0xffffffffu, m, off);
                int   io = __shfl_down_sync(0xffffffffu, id, off);
                float so = __shfl_down_sync(0xffffffffu, ss, off);
                SMAX_COMBINE(m, id, ss, mo, io, so);
            }
            if (t == 0) { g_pm[b][k] = m; g_pi[b][k] = id; g_ps[b][k] = ss; }
        }
        batch_barrier(b);

        // ---- combine 16 partials (redundant per block), emit, gather ----
        if (t < 32) {
            float m  = (t < NBPB) ? g_pm[b][t] : -1e30f;
            int   id = (t < NBPB) ? g_pi[b][t] : 0x7FFFFFFF;
            float ss = (t < NBPB) ? g_ps[b][t] : 0.f;
            #pragma unroll
            for (int off = 8; off > 0; off >>= 1) {
                float mo = __shfl_down_sync(0xffffffffu, m, off);
                int   io = __shfl_down_sync(0xffffffffu, id, off);
                float so = __shfl_down_sync(0xffffffffu, ss, off);
                SMAX_COMBINE(m, id, ss, mo, io, so);
            }
            if (t == 0) {
                float logp = -logf(ss);     // log(max softmax)
                if (k == 0) {
                    int oi = b * STEPS + step;
                    if (oi < out_size) out[oi] = (float)id;
                    int oj = Bz * STEPS + oi;
                    if (oj < out_size) out[oj] = logp;
                }
                s_dec[0] = st[(b * 2 + 0) * Sz + id];
                s_dec[1] = st[(b * 2 + 1) * Sz + id];
            }
        }
        __syncthreads();   // publish s_dec for next step's LSTM
    }
}

extern "C" void kernel_launch(void* const* d_in, const int* in_sizes, int n_in,
                              void* d_out, int out_size) {
    const float* st    = (const float*)d_in[0];
    const float* dyn   = (const float*)d_in[1];
    const float* W_s   = (const float*)d_in[2];
    const float* b_s   = (const float*)d_in[3];
    const float* W_d   = (const float*)d_in[4];
    const float* b_d   = (const float*)d_in[5];
    const float* W_dec = (const float*)d_in[6];
    const float* b_dec = (const float*)d_in[7];
    const float* W_ih  = (const float*)d_in[8];
    const float* W_hh  = (const float*)d_in[9];
    const float* b_ih  = (const float*)d_in[10];
    const float* b_hh  = (const float*)d_in[11];
    const float* W_ref = (const float*)d_in[12];
    const float* b_ref = (const float*)d_in[13];
    const float* W_pd  = (const float*)d_in[14];
    const float* b_pd  = (const float*)d_in[15];
    const float* W_q   = (const float*)d_in[16];
    const float* b_q   = (const float*)d_in[17];
    const float* W_att = (const float*)d_in[18];

    const int dyn_smem = SROWS * SCHUNK * (int)sizeof(float);   // 212992 B
    static int attr_set = 0;
    if (!attr_set) {
        cudaFuncSetAttribute(persist_kernel,
                             cudaFuncAttributeMaxDynamicSharedMemorySize, dyn_smem);
        attr_set = 1;
    }

    coef_kernel<<<1, Hz>>>(W_ref, W_s, b_s, b_ref, W_pd, W_d, b_d, b_pd);
    persist_kernel<<<NB, NT, dyn_smem>>>(st, dyn, W_dec, b_dec, W_ih, W_hh,
                                         b_ih, b_hh, W_q, b_q, W_att,
                                         (float*)d_out, out_size);
}

// round 5
// speedup vs baseline: 1.7865x; 1.0052x over previous
#include <cuda_runtime.h>
#include <math.h>

#define Bz 8
#define Sz 8192
#define Hz 128
#define STEPS 20
#define NBPB 16              // blocks per batch
#define NB (Bz * NBPB)       // 128 blocks (<=148 SMs -> co-resident)
#define NT 1024              // 32 warps/block, 1 block/SM
#define SCHUNK 512           // positions per block
#define SROWS 100            // g-rows staged in SMEM (100*512*4 = 200 KB)
#define RROWS (Hz - SROWS)   // 28 g-rows left in L2

typedef unsigned long long ull;

// -------- persistent scratch --------
__device__ __align__(16) float g_rest[(size_t)Bz * RROWS * Sz];  // 7.3 MB, L2-resident
__device__ float g_coef[4 * Hz];
__device__ float g_hh[2][Bz][Hz];
__device__ float g_cc[Bz][Hz];
__device__ float g_pm[Bz][NBPB];
__device__ int   g_pi[Bz][NBPB];
__device__ float g_ps[Bz][NBPB];
__device__ int   g_bmax[Bz];
__device__ unsigned g_bcnt[Bz];
__device__ unsigned g_bgen[Bz];

// -------- batch-local barrier (16 blocks of one batch) --------
__device__ __forceinline__ void batch_barrier(int b) {
    __syncthreads();
    if (threadIdx.x == 0) {
        volatile unsigned* genp = &g_bgen[b];
        unsigned gen = *genp;
        __threadfence();
        unsigned arrived = atomicAdd(&g_bcnt[b], 1u);
        if (arrived == NBPB - 1) {
            g_bcnt[b] = 0;
            __threadfence();
            atomicAdd(&g_bgen[b], 1u);
        } else {
            while (*genp == gen) { }
        }
        __threadfence();
    }
    __syncthreads();
}

// -------- packed f32x2 helpers --------
__device__ __forceinline__ ull f2add(ull a, ull b) {
    ull d; asm("add.rn.f32x2 %0, %1, %2;" : "=l"(d) : "l"(a), "l"(b)); return d;
}
__device__ __forceinline__ ull f2mul(ull a, ull b) {
    ull d; asm("mul.rn.f32x2 %0, %1, %2;" : "=l"(d) : "l"(a), "l"(b)); return d;
}
__device__ __forceinline__ ull f2fma(ull a, ull b, ull c) {
    ull d; asm("fma.rn.f32x2 %0, %1, %2, %3;" : "=l"(d) : "l"(a), "l"(b), "l"(c)); return d;
}
__device__ __forceinline__ ull dup2(float f) {
    ull d; asm("mov.b64 %0, {%1, %2};" : "=l"(d) : "f"(f), "f"(f)); return d;
}
__device__ __forceinline__ void unpack2(ull v, float& lo, float& hi) {
    asm("mov.b64 {%0, %1}, %2;" : "=f"(lo), "=f"(hi) : "l"(v));
}

// packed tanh poly step: NC=4 -> deg-9 (|x|<=0.32), NC=6 -> deg-13 (|x|<=0.55)
template<int NC>
__device__ __forceinline__ ull poly_acc(ull V, ulonglong2 qw, ull A) {
    const ull C1 = dup2(-0.33333334f);
    const ull C2 = dup2( 0.13333334f);
    const ull C3 = dup2(-0.053968254f);
    const ull C4 = dup2( 0.021869489f);
    const ull C5 = dup2(-0.008863236f);
    const ull C6 = dup2( 0.0035921280f);
    const ull ONE = dup2(1.0f);
    ull X = f2add(V, qw.x);
    ull Y = f2mul(X, X);
    ull P;
    if (NC == 6) {
        P = f2fma(Y, C6, C5);
        P = f2fma(P, Y, C4);
        P = f2fma(P, Y, C3);
    } else {
        P = f2fma(Y, C4, C3);
    }
    P = f2fma(P, Y, C2);
    P = f2fma(P, Y, C1);
    P = f2fma(P, Y, ONE);
    return f2fma(qw.y, f2mul(X, P), A);
}

template<int NC, int G0, int G1>
__device__ __forceinline__ ull scan_smem(const float* __restrict__ sb, int pp,
                                         const ulonglong2* __restrict__ qwp, ull A) {
    const ull* p = (const ull*)sb + pp;
    #pragma unroll 8
    for (int g = G0; g < G1; ++g)
        A = poly_acc<NC>(p[(size_t)g << 8], qwp[g], A);
    return A;
}

template<int NC>
__device__ __forceinline__ ull scan_rest(const ull* __restrict__ rp,
                                         const ulonglong2* __restrict__ qwp, ull A) {
    #pragma unroll 7
    for (int j = 0; j < RROWS; ++j)
        A = poly_acc<NC>(rp[(size_t)j * (Sz / 2)], qwp[j], A);
    return A;
}

__device__ __forceinline__ float sigmoidf(float x) { return 1.f / (1.f + expf(-x)); }

#define SMAX_COMBINE(m, id, ss, mo, io, so)                          \
    if ((mo) > (m) || ((mo) == (m) && (io) < (id))) {                \
        (ss) = (ss) * expf((m) - (mo)) + (so);                       \
        (m) = (mo); (id) = (io);                                     \
    } else {                                                         \
        (ss) = (ss) + (so) * expf((mo) - (m));                       \
    }

// -------- K0: fold per-step projections to rank-3 affine coefficients --------
__global__ void coef_kernel(const float* __restrict__ W_ref, const float* __restrict__ W_s,
                            const float* __restrict__ b_s,   const float* __restrict__ b_ref,
                            const float* __restrict__ W_pd,  const float* __restrict__ W_d,
                            const float* __restrict__ b_d,   const float* __restrict__ b_pd) {
    int g = threadIdx.x;
    float a0 = 0.f, a1 = 0.f, dd = 0.f, c = 0.f;
    for (int h = 0; h < Hz; ++h) {
        float wr = W_ref[g * Hz + h];
        a0 = fmaf(wr, W_s[h * 2 + 0], a0);
        a1 = fmaf(wr, W_s[h * 2 + 1], a1);
        c  = fmaf(wr, b_s[h], c);
        float wp = W_pd[g * Hz + h];
        dd = fmaf(wp, W_d[h], dd);
        c  = fmaf(wp, b_d[h], c);
    }
    c += b_ref[g] + b_pd[g];
    g_coef[g] = a0; g_coef[Hz + g] = a1; g_coef[2 * Hz + g] = dd; g_coef[3 * Hz + g] = c;
}

// -------- persistent decode kernel --------
__global__ __launch_bounds__(NT, 1)
void persist_kernel(const float* __restrict__ st,   const float* __restrict__ dyn,
                    const float* __restrict__ W_dec, const float* __restrict__ b_dec,
                    const float* __restrict__ W_ih,  const float* __restrict__ W_hh,
                    const float* __restrict__ b_ih,  const float* __restrict__ b_hh,
                    const float* __restrict__ W_q,   const float* __restrict__ b_q,
                    const float* __restrict__ W_att,
                    float* __restrict__ out, int out_size) {
    const int blk = blockIdx.x;
    const int b = blk / NBPB;
    const int k = blk % NBPB;
    const int t = threadIdx.x;

    extern __shared__ float s_base[];   // SROWS * 512 floats = 200 KB

    __shared__ float s_coef[4 * Hz];
    __shared__ float s_q[Hz];
    __shared__ float s_watt[Hz];
    __shared__ ulonglong2 s_qw[Hz];     // (q,q),(w,w) packed pairs
    __shared__ float s_dh[Hz];
    __shared__ float s_hhold[Hz];
    __shared__ float s_dec[2];
    __shared__ float s_gate[32];
    __shared__ float s_red[256];
    __shared__ float s_qp[Hz];
    __shared__ float2 s_part[3][256];   // partials from gq = 1..3
    __shared__ float s_wm[8];
    __shared__ int   s_wi[8];
    __shared__ float s_ws[8];
    __shared__ int   s_path;
    __shared__ int   s_imax;

    // ---- phase 0: stage base slice (SROWS rows -> smem, RROWS rows -> L2) ----
    if (t < 4 * Hz) s_coef[t] = g_coef[t];
    if (t == 0) s_imax = 0;
    __syncthreads();
    {
        const int sl = t & 511;               // position within chunk
        const int ghalf = t >> 9;             // 0: rows 0..63, 1: rows 64..127
        const int s = k * SCHUNK + sl;
        const float x = st[(b * 2 + 0) * Sz + s];
        const float y = st[(b * 2 + 1) * Sz + s];
        const float d = dyn[b * Sz + s];
        float lmax = 0.f;
        if (ghalf == 0) {
            #pragma unroll 8
            for (int g = 0; g < 64; ++g) {
                float v = fmaf(s_coef[g], x,
                          fmaf(s_coef[Hz + g], y,
                          fmaf(s_coef[2 * Hz + g], d, s_coef[3 * Hz + g])));
                s_base[g * SCHUNK + sl] = v;
                lmax = fmaxf(lmax, fabsf(v));
            }
        } else {
            #pragma unroll 6
            for (int g = 64; g < SROWS; ++g) {
                float v = fmaf(s_coef[g], x,
                          fmaf(s_coef[Hz + g], y,
                          fmaf(s_coef[2 * Hz + g], d, s_coef[3 * Hz + g])));
                s_base[g * SCHUNK + sl] = v;
                lmax = fmaxf(lmax, fabsf(v));
            }
            #pragma unroll 7
            for (int j = 0; j < RROWS; ++j) {
                int g = SROWS + j;
                float v = fmaf(s_coef[g], x,
                          fmaf(s_coef[Hz + g], y,
                          fmaf(s_coef[2 * Hz + g], d, s_coef[3 * Hz + g])));
                g_rest[((size_t)(b * RROWS + j)) * Sz + s] = v;
                lmax = fmaxf(lmax, fabsf(v));
            }
        }
        atomicMax(&s_imax, __float_as_int(lmax));
    }
    if (t < 8) { int g = k * 8 + t; g_hh[0][b][g] = 0.f; g_cc[b][g] = 0.f; }
    if (t < Hz) s_watt[t] = W_att[t];
    if (t == 0) { s_dec[0] = 0.f; s_dec[1] = 0.f; }
    __syncthreads();
    if (t == 0) atomicMax(&g_bmax[b], s_imax);
    batch_barrier(b);
    const float Mb = __int_as_float(g_bmax[b]);

    for (int step = 0; step < STEPS; ++step) {
        const int p = step & 1;

        // ---- LSTM: this block computes hidden slice g in [8k, 8k+8) ----
        if (t < Hz) {
            s_hhold[t] = g_hh[p][b][t];
            s_dh[t] = fmaf(W_dec[t * 2 + 0], s_dec[0],
                      fmaf(W_dec[t * 2 + 1], s_dec[1], b_dec[t]));
        }
        __syncthreads();
        if (t < 256) {
            int row = t >> 3, l8 = t & 7;
            int q4 = row >> 3, r = row & 7;
            int j = q4 * Hz + k * 8 + r;
            const float* wi = W_ih + j * Hz + l8 * 16;
            const float* wh = W_hh + j * Hz + l8 * 16;
            float acc = 0.f;
            #pragma unroll
            for (int h = 0; h < 16; ++h)
                acc = fmaf(wi[h], s_dh[l8 * 16 + h], fmaf(wh[h], s_hhold[l8 * 16 + h], acc));
            s_red[t] = acc;
        }
        __syncthreads();
        if (t < 32) {
            float gsum = 0.f;
            #pragma unroll
            for (int x = 0; x < 8; ++x) gsum += s_red[t * 8 + x];
            int jj = (t >> 3) * Hz + k * 8 + (t & 7);
            s_gate[t] = gsum + b_ih[jj] + b_hh[jj];
        }
        __syncthreads();
        if (t < 8) {
            int g = k * 8 + t;
            float ig = s_gate[t], fg = s_gate[8 + t], gg = s_gate[16 + t], og = s_gate[24 + t];
            float c  = g_cc[b][g];
            float c2 = fmaf(sigmoidf(fg), c, sigmoidf(ig) * tanhf(gg));
            float h2 = sigmoidf(og) * tanhf(c2);
            g_cc[b][g] = c2;
            g_hh[1 - p][b][g] = h2;
        }
        batch_barrier(b);

        // ---- q = W_q @ hh_new + b_q (32 warps x 4 rows, coalesced) ----
        if (t < Hz) s_hhold[t] = g_hh[1 - p][b][t];
        __syncthreads();
        {
            int w = t >> 5, l = t & 31;
            #pragma unroll
            for (int r4 = 0; r4 < 4; ++r4) {
                int row = w * 4 + r4;
                const float* wq = W_q + row * Hz;
                float acc = fmaf(wq[l], s_hhold[l],
                            fmaf(wq[l + 32], s_hhold[l + 32],
                            fmaf(wq[l + 64], s_hhold[l + 64],
                                 wq[l + 96] * s_hhold[l + 96])));
                #pragma unroll
                for (int off = 16; off > 0; off >>= 1)
                    acc += __shfl_down_sync(0xffffffffu, acc, off);
                if (l == 0) s_qp[row] = acc;
            }
        }
        __syncthreads();
        if (t < Hz) {
            float qv = s_qp[t] + b_q[t];
            s_q[t] = qv;
            ulonglong2 e; e.x = dup2(qv); e.y = dup2(s_watt[t]);
            s_qw[t] = e;
            float myq = fabsf(qv);
            #pragma unroll
            for (int off = 16; off > 0; off >>= 1)
                myq = fmaxf(myq, __shfl_down_sync(0xffffffffu, myq, off));
            if ((t & 31) == 0) s_wm[t >> 5] = myq;
        }
        __syncthreads();
        if (t == 0) {
            float bound = fmaxf(fmaxf(s_wm[0], s_wm[1]), fmaxf(s_wm[2], s_wm[3])) + Mb;
            s_path = (bound <= 0.32f) ? 0 : ((bound <= 0.55f) ? 1 : 2);
        }
        __syncthreads();

        // ---- attention scan: thread = (position pair pp, g-quarter gq) ----
        const int pp = t & 255, gq = t >> 8;
        const int path = s_path;
        const ull* rp = (const ull*)g_rest + ((size_t)(b * RROWS) * Sz >> 1)
                      + (k << 8) + pp;
        float a0, a1;
        if (path <= 1) {
            ull A = 0ull;
            if (path == 0) {
                if      (gq == 0) A = scan_smem<4,  0, 32>(s_base, pp, s_qw, A);
                else if (gq == 1) A = scan_smem<4, 32, 64>(s_base, pp, s_qw, A);
                else if (gq == 2) A = scan_smem<4, 64, 96>(s_base, pp, s_qw, A);
                else {
                    A = scan_rest<4>(rp, s_qw + SROWS, A);
                    A = scan_smem<4, 96, SROWS>(s_base, pp, s_qw, A);
                }
            } else {
                if      (gq == 0) A = scan_smem<6,  0, 32>(s_base, pp, s_qw, A);
                else if (gq == 1) A = scan_smem<6, 32, 64>(s_base, pp, s_qw, A);
                else if (gq == 2) A = scan_smem<6, 64, 96>(s_base, pp, s_qw, A);
                else {
                    A = scan_rest<6>(rp, s_qw + SROWS, A);
                    A = scan_smem<6, 96, SROWS>(s_base, pp, s_qw, A);
                }
            }
            unpack2(A, a0, a1);
        } else {
            a0 = 0.f; a1 = 0.f;
            const float2* sp = (const float2*)s_base + pp;
            int lo = gq * 32, hi = (gq == 3) ? SROWS : (gq * 32 + 32);
            for (int g = lo; g < hi; ++g) {
                float2 v = sp[g << 8];
                float qv = s_q[g], w = s_watt[g];
                a0 = fmaf(w, tanhf(v.x + qv), a0);
                a1 = fmaf(w, tanhf(v.y + qv), a1);
            }
            if (gq == 3) {
                const float2* fp = (const float2*)g_rest
                                 + ((size_t)(b * RROWS) * Sz >> 1) + (k << 8) + pp;
                for (int j = 0; j < RROWS; ++j) {
                    float2 v = fp[(size_t)j * (Sz / 2)];
                    float qv = s_q[SROWS + j], w = s_watt[SROWS + j];
                    a0 = fmaf(w, tanhf(v.x + qv), a0);
                    a1 = fmaf(w, tanhf(v.y + qv), a1);
                }
            }
        }
        if (gq > 0) s_part[gq - 1][pp] = make_float2(a0, a1);
        __syncthreads();

        // ---- reduce to per-block partial (m, id, ssum) over 512 positions ----
        if (gq == 0) {
            float2 p1 = s_part[0][pp], p2 = s_part[1][pp], p3 = s_part[2][pp];
            float aq0 = (((a0 + p1.x) + p2.x) + p3.x) + 10000.0f;  // replicate fp32 quantization
            float aq1 = (((a1 + p1.y) + p2.y) + p3.y) + 10000.0f;
            int s0 = k * SCHUNK + 2 * pp;
            float m, ss; int id;
            if (aq1 > aq0) { m = aq1; id = s0 + 1; ss = 1.f + expf(aq0 - aq1); }
            else           { m = aq0; id = s0;     ss = 1.f + expf(aq1 - aq0); }
            #pragma unroll
            for (int off = 16; off > 0; off >>= 1) {
                float mo = __shfl_down_sync(0xffffffffu, m, off);
                int   io = __shfl_down_sync(0xffffffffu, id, off);
                float so = __shfl_down_sync(0xffffffffu, ss, off);
                SMAX_COMBINE(m, id, ss, mo, io, so);
            }
            if ((t & 31) == 0) { int w = t >> 5; s_wm[w] = m; s_wi[w] = id; s_ws[w] = ss; }
        }
        __syncthreads();
        if (t < 32) {
            float m  = (t < 8) ? s_wm[t] : -1e30f;
            int   id = (t < 8) ? s_wi[t] : 0x7FFFFFFF;
            float ss = (t < 8) ? s_ws[t] : 0.f;
            #pragma unroll
            for (int off = 4; off > 0; off >>= 1) {
                float mo = __shfl_down_sync(0xffffffffu, m, off);
                int   io = __shfl_down_sync(0xffffffffu, id, off);
                float so = __shfl_down_sync(0xffffffffu, ss, off);
                SMAX_COMBINE(m, id, ss, mo, io, so);
            }
            if (t == 0) { g_pm[b][k] = m; g_pi[b][k] = id; g_ps[b][k] = ss; }
        }
        batch_barrier(b);

        // ---- combine 16 partials (redundant per block), emit, gather ----
        if (t < 32) {
            float m  = (t < NBPB) ? g_pm[b][t] : -1e30f;
            int   id = (t < NBPB) ? g_pi[b][t] : 0x7FFFFFFF;
            float ss = (t < NBPB) ? g_ps[b][t] : 0.f;
            #pragma unroll
            for (int off = 8; off > 0; off >>= 1) {
                float mo = __shfl_down_sync(0xffffffffu, m, off);
                int   io = __shfl_down_sync(0xffffffffu, id, off);
                float so = __shfl_down_sync(0xffffffffu, ss, off);
                SMAX_COMBINE(m, id, ss, mo, io, so);
            }
            if (t == 0) {
                float logp = -logf(ss);     // log(max softmax)
                if (k == 0) {
                    int oi = b * STEPS + step;
                    if (oi < out_size) out[oi] = (float)id;
                    int oj = Bz * STEPS + oi;
                    if (oj < out_size) out[oj] = logp;
                }
                s_dec[0] = st[(b * 2 + 0) * Sz + id];
                s_dec[1] = st[(b * 2 + 1) * Sz + id];
            }
        }
        __syncthreads();   // publish s_dec for next step's LSTM
    }
}

extern "C" void kernel_launch(void* const* d_in, const int* in_sizes, int n_in,
                              void* d_out, int out_size) {
    const float* st    = (const float*)d_in[0];
    const float* dyn   = (const float*)d_in[1];
    const float* W_s   = (const float*)d_in[2];
    const float* b_s   = (const float*)d_in[3];
    const float* W_d   = (const float*)d_in[4];
    const float* b_d   = (const float*)d_in[5];
    const float* W_dec = (const float*)d_in[6];
    const float* b_dec = (const float*)d_in[7];
    const float* W_ih  = (const float*)d_in[8];
    const float* W_hh  = (const float*)d_in[9];
    const float* b_ih  = (const float*)d_in[10];
    const float* b_hh  = (const float*)d_in[11];
    const float* W_ref = (const float*)d_in[12];
    const float* b_ref = (const float*)d_in[13];
    const float* W_pd  = (const float*)d_in[14];
    const float* b_pd  = (const float*)d_in[15];
    const float* W_q   = (const float*)d_in[16];
    const float* b_q   = (const float*)d_in[17];
    const float* W_att = (const float*)d_in[18];

    const int dyn_smem = SROWS * SCHUNK * (int)sizeof(float);   // 204800 B
    static int attr_set = 0;
    if (!attr_set) {
        cudaFuncSetAttribute(persist_kernel,
                             cudaFuncAttributeMaxDynamicSharedMemorySize, dyn_smem);
        attr_set = 1;
    }

    coef_kernel<<<1, Hz>>>(W_ref, W_s, b_s, b_ref, W_pd, W_d, b_d, b_pd);
    persist_kernel<<<NB, NT, dyn_smem>>>(st, dyn, W_dec, b_dec, W_ih, W_hh,
                                         b_ih, b_hh, W_q, b_q, W_att,
                                         (float*)d_out, out_size);
}

// round 6
// speedup vs baseline: 1.9797x; 1.1081x over previous
#include <cuda_runtime.h>
#include <math.h>

#define Bz 8
#define Sz 8192
#define Hz 128
#define STEPS 20
#define NBPB 16              // blocks per batch
#define NB (Bz * NBPB)       // 128 blocks (<=148 SMs -> co-resident)
#define NT 1024              // 32 warps/block, 1 block/SM
#define SCHUNK 512           // positions per block
#define SROWS 96             // g-rows staged in SMEM (96*512*4 = 192 KB)
#define RROWS 32             // g-rows left in L2

typedef unsigned long long ull;

// -------- persistent scratch --------
__device__ __align__(16) float g_rest[(size_t)Bz * RROWS * Sz];  // 8 MB, L2-resident
__device__ float  g_coef[4 * Hz];
__device__ float2 g_U[4 * Hz];      // W_ih @ W_dec  (512 x 2)
__device__ float  g_V[4 * Hz];      // W_ih @ b_dec + b_ih + b_hh
__device__ float  g_hh[Bz][Hz];
__device__ __align__(16) float4 g_part[Bz][NBPB];   // (m, id-bits, ssum, pad)
__device__ int      g_bmax[Bz];
__device__ unsigned g_bcnt[Bz];
__device__ unsigned g_bgen[Bz];

// -------- batch-local barrier (16 blocks of one batch) --------
__device__ __forceinline__ void batch_barrier(int b) {
    __syncthreads();
    if (threadIdx.x == 0) {
        volatile unsigned* genp = &g_bgen[b];
        unsigned gen = *genp;
        __threadfence();
        unsigned arrived = atomicAdd(&g_bcnt[b], 1u);
        if (arrived == NBPB - 1) {
            g_bcnt[b] = 0;
            __threadfence();
            atomicAdd(&g_bgen[b], 1u);
        } else {
            while (*genp == gen) { }
        }
        __threadfence();
    }
    __syncthreads();
}

// -------- packed f32x2 helpers --------
__device__ __forceinline__ ull f2add(ull a, ull b) {
    ull d; asm("add.rn.f32x2 %0, %1, %2;" : "=l"(d) : "l"(a), "l"(b)); return d;
}
__device__ __forceinline__ ull f2mul(ull a, ull b) {
    ull d; asm("mul.rn.f32x2 %0, %1, %2;" : "=l"(d) : "l"(a), "l"(b)); return d;
}
__device__ __forceinline__ ull f2fma(ull a, ull b, ull c) {
    ull d; asm("fma.rn.f32x2 %0, %1, %2, %3;" : "=l"(d) : "l"(a), "l"(b), "l"(c)); return d;
}
__device__ __forceinline__ ull dup2(float f) {
    ull d; asm("mov.b64 %0, {%1, %2};" : "=l"(d) : "f"(f), "f"(f)); return d;
}
__device__ __forceinline__ ull pack2(float lo, float hi) {
    ull d; asm("mov.b64 %0, {%1, %2};" : "=l"(d) : "f"(lo), "f"(hi)); return d;
}
__device__ __forceinline__ void unpack2(ull v, float& lo, float& hi) {
    asm("mov.b64 {%0, %1}, %2;" : "=f"(lo), "=f"(hi) : "l"(v));
}

// packed tanh poly: NC=4 -> deg-9 (|x|<=0.32, err<9e-8), NC=6 -> deg-13 (|x|<=0.55)
template<int NC>
__device__ __forceinline__ ull poly_acc(ull V, ull qd, ull wd, ull A) {
    const ull C1 = dup2(-0.33333334f);
    const ull C2 = dup2( 0.13333334f);
    const ull C3 = dup2(-0.053968254f);
    const ull C4 = dup2( 0.021869489f);
    const ull C5 = dup2(-0.008863236f);
    const ull C6 = dup2( 0.0035921280f);
    const ull ONE = dup2(1.0f);
    ull X = f2add(V, qd);
    ull Y = f2mul(X, X);
    ull P;
    if (NC == 6) {
        P = f2fma(Y, C6, C5);
        P = f2fma(P, Y, C4);
        P = f2fma(P, Y, C3);
    } else {
        P = f2fma(Y, C4, C3);
    }
    P = f2fma(P, Y, C2);
    P = f2fma(P, Y, C1);
    P = f2fma(P, Y, ONE);
    return f2fma(wd, f2mul(X, P), A);
}

// 16 rows (8 pairs) x 2 packs; dp stride = RowStride ulonglong2 per row
template<int NC, int RS>
__device__ __forceinline__ void scan16(const ulonglong2* __restrict__ dp,
                                       const float4* __restrict__ qp,
                                       ull& A0, ull& A1) {
    #pragma unroll
    for (int i = 0; i < 8; ++i) {
        float4 qw = qp[i];                         // [q_g, q_g1, w_g, w_g1] broadcast
        ull q0 = dup2(qw.x), q1 = dup2(qw.y);
        ull w0 = dup2(qw.z), w1 = dup2(qw.w);
        ulonglong2 v0 = dp[(size_t)(2 * i) * RS];
        ulonglong2 v1 = dp[(size_t)(2 * i + 1) * RS];
        A0 = poly_acc<NC>(v0.x, q0, w0, A0);
        A1 = poly_acc<NC>(v0.y, q0, w0, A1);
        A0 = poly_acc<NC>(v1.x, q1, w1, A0);
        A1 = poly_acc<NC>(v1.y, q1, w1, A1);
    }
}

__device__ __forceinline__ float sigmoidf(float x) { return 1.f / (1.f + expf(-x)); }

#define SMAX_COMBINE(m, id, ss, mo, io, so)                          \
    if ((mo) > (m) || ((mo) == (m) && (io) < (id))) {                \
        (ss) = (ss) * expf((m) - (mo)) + (so);                       \
        (m) = (mo); (id) = (io);                                     \
    } else {                                                         \
        (ss) = (ss) + (so) * expf((mo) - (m));                       \
    }

// -------- K0: fold projections + LSTM input path --------
__global__ void coef_kernel(const float* __restrict__ W_ref, const float* __restrict__ W_s,
                            const float* __restrict__ b_s,   const float* __restrict__ b_ref,
                            const float* __restrict__ W_pd,  const float* __restrict__ W_d,
                            const float* __restrict__ b_d,   const float* __restrict__ b_pd,
                            const float* __restrict__ W_ih,  const float* __restrict__ W_dec,
                            const float* __restrict__ b_dec, const float* __restrict__ b_ih,
                            const float* __restrict__ b_hh) {
    int j = threadIdx.x;   // 512 threads
    // U = W_ih @ W_dec, V = W_ih @ b_dec + b_ih + b_hh
    float ux = 0.f, uy = 0.f, v = b_ih[j] + b_hh[j];
    for (int h = 0; h < Hz; ++h) {
        float wij = W_ih[j * Hz + h];
        ux = fmaf(wij, W_dec[h * 2 + 0], ux);
        uy = fmaf(wij, W_dec[h * 2 + 1], uy);
        v  = fmaf(wij, b_dec[h], v);
    }
    g_U[j] = make_float2(ux, uy);
    g_V[j] = v;

    if (j < Hz) {
        int g = j;
        float a0 = 0.f, a1 = 0.f, dd = 0.f, c = 0.f;
        for (int h = 0; h < Hz; ++h) {
            float wr = W_ref[g * Hz + h];
            a0 = fmaf(wr, W_s[h * 2 + 0], a0);
            a1 = fmaf(wr, W_s[h * 2 + 1], a1);
            c  = fmaf(wr, b_s[h], c);
            float wp = W_pd[g * Hz + h];
            dd = fmaf(wp, W_d[h], dd);
            c  = fmaf(wp, b_d[h], c);
        }
        c += b_ref[g] + b_pd[g];
        g_coef[g] = a0; g_coef[Hz + g] = a1; g_coef[2 * Hz + g] = dd; g_coef[3 * Hz + g] = c;
    }
}

// -------- persistent decode kernel --------
__global__ __launch_bounds__(NT, 1)
void persist_kernel(const float* __restrict__ st,  const float* __restrict__ dyn,
                    const float* __restrict__ W_hh, const float* __restrict__ W_q,
                    const float* __restrict__ b_q,  const float* __restrict__ W_att,
                    float* __restrict__ out, int out_size) {
    const int blk = blockIdx.x;
    const int b = blk / NBPB;
    const int k = blk % NBPB;
    const int t = threadIdx.x;
    const int w = t >> 5, l = t & 31;

    extern __shared__ float s_base[];            // SROWS * 512 floats = 192 KB

    __shared__ __align__(16) ulonglong2 s_acc[8 * 128];   // 16 KB
    __shared__ __align__(16) float4 s_qwf[64];   // [q_g, q_g1, w_g, w_g1]
    __shared__ float s_coef[4 * Hz];
    __shared__ float s_hhold[Hz];
    __shared__ float s_qraw[Hz];
    __shared__ float s_watt[Hz];
    __shared__ float s_gate[32];
    __shared__ float s_cc[8];
    __shared__ float s_dec[2];
    __shared__ float s_wm[4];
    __shared__ int   s_wi[4];
    __shared__ float s_ws[4];
    __shared__ int   s_imax;

    // ---- phase 0: stage base (96 rows smem, 32 rows L2) ----
    if (t < 4 * Hz) s_coef[t] = g_coef[t];
    if (t == 0) s_imax = 0;
    __syncthreads();
    {
        const int sl = t & 511, half = t >> 9;
        const int s = k * SCHUNK + sl;
        const float x = st[(b * 2 + 0) * Sz + s];
        const float y = st[(b * 2 + 1) * Sz + s];
        const float d = dyn[b * Sz + s];
        float lmax = 0.f;
        if (half == 0) {
            #pragma unroll 8
            for (int g = 0; g < 64; ++g) {
                float v = fmaf(s_coef[g], x, fmaf(s_coef[Hz + g], y,
                          fmaf(s_coef[2 * Hz + g], d, s_coef[3 * Hz + g])));
                s_base[g * SCHUNK + sl] = v;
                lmax = fmaxf(lmax, fabsf(v));
            }
        } else {
            #pragma unroll 8
            for (int g = 64; g < SROWS; ++g) {
                float v = fmaf(s_coef[g], x, fmaf(s_coef[Hz + g], y,
                          fmaf(s_coef[2 * Hz + g], d, s_coef[3 * Hz + g])));
                s_base[g * SCHUNK + sl] = v;
                lmax = fmaxf(lmax, fabsf(v));
            }
            #pragma unroll 8
            for (int j = 0; j < RROWS; ++j) {
                int g = SROWS + j;
                float v = fmaf(s_coef[g], x, fmaf(s_coef[Hz + g], y,
                          fmaf(s_coef[2 * Hz + g], d, s_coef[3 * Hz + g])));
                g_rest[((size_t)(b * RROWS + j)) * Sz + s] = v;
                lmax = fmaxf(lmax, fabsf(v));
            }
        }
        atomicMax(&s_imax, __float_as_int(lmax));
    }
    if (t < Hz)  s_hhold[t] = 0.f;
    if (t < Hz)  s_watt[t] = W_att[t];
    if (t < 8)   s_cc[t] = 0.f;
    if (t == 0) { s_dec[0] = 0.f; s_dec[1] = 0.f; }
    __syncthreads();
    if (t == 0) atomicMax(&g_bmax[b], s_imax);
    batch_barrier(b);
    const float Mb = __int_as_float(__ldcg(&g_bmax[b]));

    const int pg = t & 127, rg = t >> 7;     // scan mapping: 128 pack-groups x 8 row-groups

    for (int step = 0; step < STEPS; ++step) {
        // ---- LSTM: warp per gate row (32 rows owned by this block) ----
        {
            int j = (w >> 3) * Hz + k * 8 + (w & 7);
            const float* whr = W_hh + j * Hz;
            float acc = fmaf(whr[l], s_hhold[l],
                        fmaf(whr[l + 32], s_hhold[l + 32],
                        fmaf(whr[l + 64], s_hhold[l + 64],
                             whr[l + 96] * s_hhold[l + 96])));
            #pragma unroll
            for (int off = 16; off > 0; off >>= 1)
                acc += __shfl_down_sync(0xffffffffu, acc, off);
            if (l == 0) {
                float2 u = g_U[j];
                s_gate[w] = acc + fmaf(u.x, s_dec[0], fmaf(u.y, s_dec[1], g_V[j]));
            }
        }
        __syncthreads();
        if (t < 8) {
            float ig = s_gate[t], fg = s_gate[8 + t], gg = s_gate[16 + t], og = s_gate[24 + t];
            float c2 = fmaf(sigmoidf(fg), s_cc[t], sigmoidf(ig) * tanhf(gg));
            float h2 = sigmoidf(og) * tanhf(c2);
            s_cc[t] = c2;
            g_hh[b][k * 8 + t] = h2;
        }
        batch_barrier(b);

        // ---- q phase: gather hh, q = W_q @ hh + b_q, build qw table + path ----
        if (t < Hz) s_hhold[t] = __ldcg(&g_hh[b][t]);
        __syncthreads();
        {
            #pragma unroll
            for (int r4 = 0; r4 < 4; ++r4) {
                int row = w * 4 + r4;
                const float* wq = W_q + row * Hz;
                float acc = fmaf(wq[l], s_hhold[l],
                            fmaf(wq[l + 32], s_hhold[l + 32],
                            fmaf(wq[l + 64], s_hhold[l + 64],
                                 wq[l + 96] * s_hhold[l + 96])));
                #pragma unroll
                for (int off = 16; off > 0; off >>= 1)
                    acc += __shfl_down_sync(0xffffffffu, acc, off);
                if (l == 0) s_qraw[row] = acc + b_q[row];
            }
        }
        __syncthreads();
        if (t < 64)
            s_qwf[t] = make_float4(s_qraw[2 * t], s_qraw[2 * t + 1],
                                   s_watt[2 * t], s_watt[2 * t + 1]);
        if (t < Hz) {
            float mq = fabsf(s_qraw[t]);
            #pragma unroll
            for (int off = 16; off > 0; off >>= 1)
                mq = fmaxf(mq, __shfl_down_sync(0xffffffffu, mq, off));
            if ((t & 31) == 0) s_wm[t >> 5] = mq;
        }
        __syncthreads();
        const float bound = fmaxf(fmaxf(s_wm[0], s_wm[1]), fmaxf(s_wm[2], s_wm[3])) + Mb;
        const int path = (bound <= 0.32f) ? 0 : ((bound <= 0.55f) ? 1 : 2);

        // ---- attention scan: thread = 4 positions (pg) x 16 rows (rg) ----
        ull A0 = 0ull, A1 = 0ull;
        if (path <= 1) {
            if (rg < 6) {
                const ulonglong2* dp = (const ulonglong2*)s_base + (rg * 16) * 128 + pg;
                const float4* qp = s_qwf + rg * 8;
                if (path == 0) scan16<4, 128>(dp, qp, A0, A1);
                else           scan16<6, 128>(dp, qp, A0, A1);
            } else {
                size_t off = ((size_t)(b * RROWS + (rg - 6) * 16) * Sz + k * SCHUNK) >> 2;
                const ulonglong2* dp = (const ulonglong2*)g_rest + off + pg;
                const float4* qp = s_qwf + 48 + (rg - 6) * 8;
                if (path == 0) scan16<4, 2048>(dp, qp, A0, A1);
                else           scan16<6, 2048>(dp, qp, A0, A1);
            }
        } else {
            float f0 = 0.f, f1 = 0.f, f2 = 0.f, f3 = 0.f;
            for (int i = 0; i < 16; ++i) {
                int g = rg * 16 + i;
                const float* r;
                if (rg < 6) r = s_base + g * SCHUNK + 4 * pg;
                else        r = g_rest + (size_t)(b * RROWS + g - SROWS) * Sz + k * SCHUNK + 4 * pg;
                float q = s_qraw[g], wv = s_watt[g];
                f0 = fmaf(wv, tanhf(r[0] + q), f0);
                f1 = fmaf(wv, tanhf(r[1] + q), f1);
                f2 = fmaf(wv, tanhf(r[2] + q), f2);
                f3 = fmaf(wv, tanhf(r[3] + q), f3);
            }
            A0 = pack2(f0, f1); A1 = pack2(f2, f3);
        }
        {
            ulonglong2 vv; vv.x = A0; vv.y = A1;
            s_acc[rg * 128 + pg] = vv;
        }
        __syncthreads();

        // ---- reduce 8 row-groups, then block-level softmax partial ----
        if (t < 128) {
            ull B0 = 0ull, B1 = 0ull;
            #pragma unroll
            for (int r = 0; r < 8; ++r) {
                ulonglong2 v = s_acc[r * 128 + t];
                B0 = f2add(B0, v.x); B1 = f2add(B1, v.y);
            }
            float a0, a1, a2, a3;
            unpack2(B0, a0, a1); unpack2(B1, a2, a3);
            // replicate reference fp32 quantization `attns + 10000.0`
            float aq0 = a0 + 10000.0f, aq1 = a1 + 10000.0f;
            float aq2 = a2 + 10000.0f, aq3 = a3 + 10000.0f;
            int s0 = k * SCHUNK + 4 * t;
            float m, ss; int id;
            if (aq1 > aq0) { m = aq1; id = s0 + 1; ss = expf(aq0 - aq1) + 1.f; }
            else           { m = aq0; id = s0;     ss = 1.f + expf(aq1 - aq0); }
            float m2, ss2; int id2;
            if (aq3 > aq2) { m2 = aq3; id2 = s0 + 3; ss2 = expf(aq2 - aq3) + 1.f; }
            else           { m2 = aq2; id2 = s0 + 2; ss2 = 1.f + expf(aq3 - aq2); }
            SMAX_COMBINE(m, id, ss, m2, id2, ss2);
            #pragma unroll
            for (int off = 16; off > 0; off >>= 1) {
                float mo = __shfl_down_sync(0xffffffffu, m, off);
                int   io = __shfl_down_sync(0xffffffffu, id, off);
                float so = __shfl_down_sync(0xffffffffu, ss, off);
                SMAX_COMBINE(m, id, ss, mo, io, so);
            }
            if ((t & 31) == 0) { s_wm[t >> 5] = m; s_wi[t >> 5] = id; s_ws[t >> 5] = ss; }
        }
        __syncthreads();
        if (t < 32) {
            float m  = (t < 4) ? s_wm[t] : -1e30f;
            int   id = (t < 4) ? s_wi[t] : 0x7FFFFFFF;
            float ss = (t < 4) ? s_ws[t] : 0.f;
            #pragma unroll
            for (int off = 2; off > 0; off >>= 1) {
                float mo = __shfl_down_sync(0xffffffffu, m, off);
                int   io = __shfl_down_sync(0xffffffffu, id, off);
                float so = __shfl_down_sync(0xffffffffu, ss, off);
                SMAX_COMBINE(m, id, ss, mo, io, so);
            }
            if (t == 0)
                g_part[b][k] = make_float4(m, __int_as_float(id), ss, 0.f);
        }
        batch_barrier(b);

        // ---- combine 16 partials (redundant per block), emit, gather ----
        if (t < 32) {
            float m = -1e30f, ss = 0.f; int id = 0x7FFFFFFF;
            if (t < NBPB) {
                float4 v = __ldcg(&g_part[b][t]);
                m = v.x; id = __float_as_int(v.y); ss = v.z;
            }
            #pragma unroll
            for (int off = 8; off > 0; off >>= 1) {
                float mo = __shfl_down_sync(0xffffffffu, m, off);
                int   io = __shfl_down_sync(0xffffffffu, id, off);
                float so = __shfl_down_sync(0xffffffffu, ss, off);
                SMAX_COMBINE(m, id, ss, mo, io, so);
            }
            if (t == 0) {
                float logp = -logf(ss);   // log(max softmax)
                if (k == 0) {
                    int oi = b * STEPS + step;
                    if (oi < out_size) out[oi] = (float)id;
                    int oj = Bz * STEPS + oi;
                    if (oj < out_size) out[oj] = logp;
                }
                s_dec[0] = st[(b * 2 + 0) * Sz + id];
                s_dec[1] = st[(b * 2 + 1) * Sz + id];
            }
        }
        __syncthreads();   // publish s_dec / protect s_hhold for next step
    }
}

extern "C" void kernel_launch(void* const* d_in, const int* in_sizes, int n_in,
                              void* d_out, int out_size) {
    const float* st    = (const float*)d_in[0];
    const float* dyn   = (const float*)d_in[1];
    const float* W_s   = (const float*)d_in[2];
    const float* b_s   = (const float*)d_in[3];
    const float* W_d   = (const float*)d_in[4];
    const float* b_d   = (const float*)d_in[5];
    const float* W_dec = (const float*)d_in[6];
    const float* b_dec = (const float*)d_in[7];
    const float* W_ih  = (const float*)d_in[8];
    const float* W_hh  = (const float*)d_in[9];
    const float* b_ih  = (const float*)d_in[10];
    const float* b_hh  = (const float*)d_in[11];
    const float* W_ref = (const float*)d_in[12];
    const float* b_ref = (const float*)d_in[13];
    const float* W_pd  = (const float*)d_in[14];
    const float* b_pd  = (const float*)d_in[15];
    const float* W_q   = (const float*)d_in[16];
    const float* b_q   = (const float*)d_in[17];
    const float* W_att = (const float*)d_in[18];

    const int dyn_smem = SROWS * SCHUNK * (int)sizeof(float);   // 196608 B
    static int attr_set = 0;
    if (!attr_set) {
        cudaFuncSetAttribute(persist_kernel,
                             cudaFuncAttributeMaxDynamicSharedMemorySize, dyn_smem);
        attr_set = 1;
    }

    coef_kernel<<<1, 4 * Hz>>>(W_ref, W_s, b_s, b_ref, W_pd, W_d, b_d, b_pd,
                               W_ih, W_dec, b_dec, b_ih, b_hh);
    persist_kernel<<<NB, NT, dyn_smem>>>(st, dyn, W_hh, W_q, b_q, W_att,
                                         (float*)d_out, out_size);
}

// round 7
// speedup vs baseline: 2.2890x; 1.1562x over previous
#include <cuda_runtime.h>
#include <math.h>

#define Bz 8
#define Sz 8192
#define Hz 128
#define STEPS 20
#define NBPB 16              // blocks per batch
#define NB (Bz * NBPB)       // 128 blocks (<=148 SMs -> co-resident)
#define NT 1024              // 32 warps/block, 1 block/SM
#define SCHUNK 512           // positions per block
#define SROWS 92             // g-rows staged in SMEM (92*512*4 = 184 KB)
#define RROWS 36             // g-rows left in L2

typedef unsigned long long ull;

// -------- persistent scratch --------
__device__ __align__(16) float g_rest[(size_t)Bz * RROWS * Sz];  // 9.4 MB, L2-resident
__device__ float  g_coef[4 * Hz];
__device__ float2 g_U[4 * Hz];      // W_ih @ W_dec
__device__ float  g_V[4 * Hz];      // W_ih @ b_dec + b_ih + b_hh
__device__ float  g_hh[Bz][Hz];
__device__ __align__(16) float g_qp[Bz][Hz][NBPB];              // q partials
__device__ __align__(16) float4 g_part[Bz][NBPB];               // (m, id-bits, ssum, pad)
__device__ int      g_bmax[Bz];
__device__ unsigned g_bcnt[Bz];
__device__ unsigned g_bgen[Bz];

// -------- batch-local barrier, acquire/release, no threadfence --------
__device__ __forceinline__ void batch_barrier(int b) {
    __syncthreads();
    if (threadIdx.x == 0) {
        unsigned gen;
        asm volatile("ld.acquire.gpu.global.u32 %0, [%1];"
                     : "=r"(gen) : "l"(&g_bgen[b]) : "memory");
        unsigned arrived;
        asm volatile("atom.acq_rel.gpu.global.add.u32 %0, [%1], %2;"
                     : "=r"(arrived) : "l"(&g_bcnt[b]), "r"(1u) : "memory");
        if (arrived == NBPB - 1) {
            asm volatile("st.global.u32 [%0], %1;" :: "l"(&g_bcnt[b]), "r"(0u) : "memory");
            asm volatile("st.release.gpu.global.u32 [%0], %1;"
                         :: "l"(&g_bgen[b]), "r"(gen + 1u) : "memory");
        } else {
            unsigned cur;
            do {
                asm volatile("ld.acquire.gpu.global.u32 %0, [%1];"
                             : "=r"(cur) : "l"(&g_bgen[b]) : "memory");
            } while (cur == gen);
        }
    }
    __syncthreads();
}

// -------- packed f32x2 helpers --------
__device__ __forceinline__ ull f2add(ull a, ull b) {
    ull d; asm("add.rn.f32x2 %0, %1, %2;" : "=l"(d) : "l"(a), "l"(b)); return d;
}
__device__ __forceinline__ ull f2mul(ull a, ull b) {
    ull d; asm("mul.rn.f32x2 %0, %1, %2;" : "=l"(d) : "l"(a), "l"(b)); return d;
}
__device__ __forceinline__ ull f2fma(ull a, ull b, ull c) {
    ull d; asm("fma.rn.f32x2 %0, %1, %2, %3;" : "=l"(d) : "l"(a), "l"(b), "l"(c)); return d;
}
__device__ __forceinline__ ull dup2(float f) {
    ull d; asm("mov.b64 %0, {%1, %2};" : "=l"(d) : "f"(f), "f"(f)); return d;
}
__device__ __forceinline__ ull pack2(float lo, float hi) {
    ull d; asm("mov.b64 %0, {%1, %2};" : "=l"(d) : "f"(lo), "f"(hi)); return d;
}
__device__ __forceinline__ void unpack2(ull v, float& lo, float& hi) {
    asm("mov.b64 {%0, %1}, %2;" : "=f"(lo), "=f"(hi) : "l"(v));
}

// packed tanh poly: NC=4 -> deg-9 (|x|<=0.32, err<9e-8), NC=6 -> deg-13 (|x|<=0.55)
template<int NC>
__device__ __forceinline__ ull poly_acc(ull V, ull qd, ull wd, ull A) {
    const ull C1 = dup2(-0.33333334f);
    const ull C2 = dup2( 0.13333334f);
    const ull C3 = dup2(-0.053968254f);
    const ull C4 = dup2( 0.021869489f);
    const ull C5 = dup2(-0.008863236f);
    const ull C6 = dup2( 0.0035921280f);
    const ull ONE = dup2(1.0f);
    ull X = f2add(V, qd);
    ull Y = f2mul(X, X);
    ull P;
    if (NC == 6) {
        P = f2fma(Y, C6, C5);
        P = f2fma(P, Y, C4);
        P = f2fma(P, Y, C3);
    } else {
        P = f2fma(Y, C4, C3);
    }
    P = f2fma(P, Y, C2);
    P = f2fma(P, Y, C1);
    P = f2fma(P, Y, ONE);
    return f2fma(wd, f2mul(X, P), A);
}

// NPAIR row-pairs, row stride RS (ulonglong2 units)
template<int NC, int NPAIR, int RS>
__device__ __forceinline__ void scanN(const ulonglong2* __restrict__ dp,
                                      const float4* __restrict__ qp,
                                      ull& A0, ull& A1) {
    #pragma unroll
    for (int i = 0; i < NPAIR; ++i) {
        float4 qw = qp[i];
        ull q0 = dup2(qw.x), q1 = dup2(qw.y);
        ull w0 = dup2(qw.z), w1 = dup2(qw.w);
        ulonglong2 v0 = dp[(size_t)(2 * i) * RS];
        ulonglong2 v1 = dp[(size_t)(2 * i + 1) * RS];
        A0 = poly_acc<NC>(v0.x, q0, w0, A0);
        A1 = poly_acc<NC>(v0.y, q0, w0, A1);
        A0 = poly_acc<NC>(v1.x, q1, w1, A0);
        A1 = poly_acc<NC>(v1.y, q1, w1, A1);
    }
}

__device__ __forceinline__ float sigmoidf(float x) { return 1.f / (1.f + expf(-x)); }

#define SMAX_COMBINE(m, id, ss, mo, io, so)                          \
    if ((mo) > (m) || ((mo) == (m) && (io) < (id))) {                \
        (ss) = (ss) * __expf((m) - (mo)) + (so);                     \
        (m) = (mo); (id) = (io);                                     \
    } else {                                                         \
        (ss) = (ss) + (so) * __expf((mo) - (m));                     \
    }

// -------- K0: coalesced fold. 640 blocks x 128 thr: one output row each --------
__global__ void coef_kernel(const float* __restrict__ W_ref, const float* __restrict__ W_s,
                            const float* __restrict__ b_s,   const float* __restrict__ b_ref,
                            const float* __restrict__ W_pd,  const float* __restrict__ W_d,
                            const float* __restrict__ b_d,   const float* __restrict__ b_pd,
                            const float* __restrict__ W_ih,  const float* __restrict__ W_dec,
                            const float* __restrict__ b_dec, const float* __restrict__ b_ih,
                            const float* __restrict__ b_hh) {
    __shared__ float s_r[4][4];
    const int h = threadIdx.x, w = h >> 5, l = h & 31;
    float v0, v1, v2, v3;
    if (blockIdx.x < 512) {
        int j = blockIdx.x;
        float wij = W_ih[j * Hz + h];
        v0 = wij * W_dec[h * 2 + 0];
        v1 = wij * W_dec[h * 2 + 1];
        v2 = wij * b_dec[h];
        v3 = 0.f;
    } else {
        int g = blockIdx.x - 512;
        float wr = W_ref[g * Hz + h];
        float wp = W_pd[g * Hz + h];
        v0 = wr * W_s[h * 2 + 0];
        v1 = wr * W_s[h * 2 + 1];
        v2 = fmaf(wr, b_s[h], wp * b_d[h]);
        v3 = wp * W_d[h];
    }
    #pragma unroll
    for (int off = 16; off > 0; off >>= 1) {
        v0 += __shfl_down_sync(0xffffffffu, v0, off);
        v1 += __shfl_down_sync(0xffffffffu, v1, off);
        v2 += __shfl_down_sync(0xffffffffu, v2, off);
        v3 += __shfl_down_sync(0xffffffffu, v3, off);
    }
    if (l == 0) { s_r[0][w] = v0; s_r[1][w] = v1; s_r[2][w] = v2; s_r[3][w] = v3; }
    __syncthreads();
    if (h == 0) {
        float r0 = s_r[0][0] + s_r[0][1] + s_r[0][2] + s_r[0][3];
        float r1 = s_r[1][0] + s_r[1][1] + s_r[1][2] + s_r[1][3];
        float r2 = s_r[2][0] + s_r[2][1] + s_r[2][2] + s_r[2][3];
        float r3 = s_r[3][0] + s_r[3][1] + s_r[3][2] + s_r[3][3];
        if (blockIdx.x < 512) {
            int j = blockIdx.x;
            g_U[j] = make_float2(r0, r1);
            g_V[j] = r2 + b_ih[j] + b_hh[j];
        } else {
            int g = blockIdx.x - 512;
            g_coef[g] = r0;
            g_coef[Hz + g] = r1;
            g_coef[2 * Hz + g] = r3;
            g_coef[3 * Hz + g] = r2 + b_ref[g] + b_pd[g];
        }
    }
}

// -------- persistent decode kernel --------
__global__ __launch_bounds__(NT, 1)
void persist_kernel(const float* __restrict__ st,  const float* __restrict__ dyn,
                    const float* __restrict__ W_hh, const float* __restrict__ W_q,
                    const float* __restrict__ b_q,  const float* __restrict__ W_att,
                    float* __restrict__ out, int out_size) {
    const int blk = blockIdx.x;
    const int b = blk / NBPB;
    const int k = blk % NBPB;
    const int t = threadIdx.x;
    const int w = t >> 5, l = t & 31;

    extern __shared__ float s_base[];                 // SROWS*512 floats = 184 KB

    __shared__ __align__(16) ulonglong2 s_acc[8 * 128];  // 16 KB (phase-0: reused as coef)
    __shared__ float s_whh[32 * Hz];                  // 16 KB: this block's 32 gate rows
    __shared__ float s_wq[Hz * 8];                    // 4 KB: W_q[:, 8k..8k+8)
    __shared__ __align__(16) float4 s_qwf[64];        // [q_g, q_g1, w_g, w_g1]
    __shared__ __align__(16) float4 s_uv[32];         // (ux, uy, v, 0) per gate row
    __shared__ float s_hhold[Hz];
    __shared__ float s_qraw[Hz];
    __shared__ float s_watt[Hz];
    __shared__ float s_bq[Hz];
    __shared__ float s_gate[32];
    __shared__ float s_cc[8];
    __shared__ float s_dec[2];
    __shared__ float s_wm[4];
    __shared__ int   s_wi[4];
    __shared__ float s_ws[4];
    __shared__ int   s_imax;

    // ---- phase 0: stage base (92 rows smem, 36 rows L2) + weights ----
    float* s_coef = (float*)s_acc;                    // overlay, phase 0 only
    if (t < 4 * Hz) s_coef[t] = g_coef[t];
    if (t == 0) s_imax = 0;
    // weight staging
    for (int idx = t; idx < 32 * Hz; idx += NT) {     // W_hh slice, by staged warp-row
        int ww = idx >> 7, col = idx & 127;
        int j = (ww >> 3) * Hz + k * 8 + (ww & 7);
        s_whh[idx] = W_hh[j * Hz + col];
    }
    if (t < Hz * 8) {                                  // W_q column slice
        int r = t >> 3, c = t & 7;
        s_wq[t] = W_q[r * Hz + k * 8 + c];
    }
    if (t < 32) {
        int j = (t >> 3) * Hz + k * 8 + (t & 7);
        float2 u = g_U[j];
        s_uv[t] = make_float4(u.x, u.y, g_V[j], 0.f);
    }
    if (t < Hz) { s_hhold[t] = 0.f; s_watt[t] = W_att[t]; s_bq[t] = b_q[t]; }
    if (t < 8)   s_cc[t] = 0.f;
    if (t == 0) { s_dec[0] = 0.f; s_dec[1] = 0.f; }
    __syncthreads();
    {
        const int sl = t & 511, half = t >> 9;
        const int s = k * SCHUNK + sl;
        const float x = st[(b * 2 + 0) * Sz + s];
        const float y = st[(b * 2 + 1) * Sz + s];
        const float d = dyn[b * Sz + s];
        float lmax = 0.f;
        if (half == 0) {
            #pragma unroll 8
            for (int g = 0; g < 64; ++g) {
                float v = fmaf(s_coef[g], x, fmaf(s_coef[Hz + g], y,
                          fmaf(s_coef[2 * Hz + g], d, s_coef[3 * Hz + g])));
                s_base[g * SCHUNK + sl] = v;
                lmax = fmaxf(lmax, fabsf(v));
            }
        } else {
            #pragma unroll 7
            for (int g = 64; g < SROWS; ++g) {
                float v = fmaf(s_coef[g], x, fmaf(s_coef[Hz + g], y,
                          fmaf(s_coef[2 * Hz + g], d, s_coef[3 * Hz + g])));
                s_base[g * SCHUNK + sl] = v;
                lmax = fmaxf(lmax, fabsf(v));
            }
            #pragma unroll 6
            for (int j = 0; j < RROWS; ++j) {
                int g = SROWS + j;
                float v = fmaf(s_coef[g], x, fmaf(s_coef[Hz + g], y,
                          fmaf(s_coef[2 * Hz + g], d, s_coef[3 * Hz + g])));
                g_rest[((size_t)(b * RROWS + j)) * Sz + s] = v;
                lmax = fmaxf(lmax, fabsf(v));
            }
        }
        atomicMax(&s_imax, __float_as_int(lmax));
    }
    __syncthreads();
    if (t == 0) atomicMax(&g_bmax[b], s_imax);
    batch_barrier(b);
    const float Mb = __int_as_float(__ldcg(&g_bmax[b]));

    const int pg = t & 127, rg = t >> 7;

    for (int step = 0; step < STEPS; ++step) {
        // ---- LSTM gates: warp per gate row, all from smem ----
        {
            const float* whr = s_whh + w * Hz;
            float acc = fmaf(whr[l], s_hhold[l],
                        fmaf(whr[l + 32], s_hhold[l + 32],
                        fmaf(whr[l + 64], s_hhold[l + 64],
                             whr[l + 96] * s_hhold[l + 96])));
            #pragma unroll
            for (int off = 16; off > 0; off >>= 1)
                acc += __shfl_down_sync(0xffffffffu, acc, off);
            if (l == 0) {
                float4 uv = s_uv[w];
                s_gate[w] = acc + fmaf(uv.x, s_dec[0], fmaf(uv.y, s_dec[1], uv.z));
            }
        }
        __syncthreads();
        // ---- warp 0: nonlinearity + q-partials (no extra block sync) ----
        if (w == 0) {
            float h2v = 0.f;
            if (l < 8) {
                float ig = s_gate[l], fg = s_gate[8 + l],
                      gg = s_gate[16 + l], og = s_gate[24 + l];
                float c2 = fmaf(sigmoidf(fg), s_cc[l], sigmoidf(ig) * tanhf(gg));
                h2v = sigmoidf(og) * tanhf(c2);
                s_cc[l] = c2;
                g_hh[b][k * 8 + l] = h2v;
            }
            __syncwarp();
            float h2a[8];
            #pragma unroll
            for (int c = 0; c < 8; ++c)
                h2a[c] = __shfl_sync(0xffffffffu, h2v, c);
            #pragma unroll
            for (int rr = 0; rr < 4; ++rr) {
                int r = l * 4 + rr;
                const float* wqr = s_wq + r * 8;
                float qp = 0.f;
                #pragma unroll
                for (int c = 0; c < 8; ++c) qp = fmaf(wqr[c], h2a[c], qp);
                if (k == 0) qp += s_bq[r];
                g_qp[b][r][k] = qp;
            }
        }
        batch_barrier(b);

        // ---- assemble q; prefetch next-step hh into register ----
        float hregv = 0.f;
        if (t < Hz) {
            hregv = __ldcg(&g_hh[b][t]);
            const float4* qpp = (const float4*)&g_qp[b][t][0];
            float4 p0 = __ldcg(qpp), p1 = __ldcg(qpp + 1),
                   p2 = __ldcg(qpp + 2), p3 = __ldcg(qpp + 3);
            float q = (((p0.x + p0.y) + (p0.z + p0.w)) + ((p1.x + p1.y) + (p1.z + p1.w)))
                    + (((p2.x + p2.y) + (p2.z + p2.w)) + ((p3.x + p3.y) + (p3.z + p3.w)));
            s_qraw[t] = q;
            float mq = fabsf(q);
            #pragma unroll
            for (int off = 16; off > 0; off >>= 1)
                mq = fmaxf(mq, __shfl_down_sync(0xffffffffu, mq, off));
            if (l == 0) s_wm[w] = mq;
        }
        __syncthreads();
        if (t < 64)
            s_qwf[t] = make_float4(s_qraw[2 * t], s_qraw[2 * t + 1],
                                   s_watt[2 * t], s_watt[2 * t + 1]);
        __syncthreads();
        const float bound = fmaxf(fmaxf(s_wm[0], s_wm[1]), fmaxf(s_wm[2], s_wm[3])) + Mb;
        const int path = (bound <= 0.32f) ? 0 : ((bound <= 0.55f) ? 1 : 2);

        // ---- attention scan: thread = 4 positions (pg) x 16 rows (rg) ----
        ull A0 = 0ull, A1 = 0ull;
        const ulonglong2* restBase = (const ulonglong2*)g_rest
                                   + (size_t)(b * RROWS) * (Sz / 4) + k * 128 + pg;
        if (path <= 1) {
            if (rg < 5) {
                const ulonglong2* dp = (const ulonglong2*)s_base + (rg * 16) * 128 + pg;
                if (path == 0) scanN<4, 8, 128>(dp, s_qwf + rg * 8, A0, A1);
                else           scanN<6, 8, 128>(dp, s_qwf + rg * 8, A0, A1);
            } else if (rg == 5) {
                const ulonglong2* dp = (const ulonglong2*)s_base + 80 * 128 + pg;
                if (path == 0) {
                    scanN<4, 6, 128>(dp, s_qwf + 40, A0, A1);
                    scanN<4, 2, 2048>(restBase, s_qwf + 46, A0, A1);
                } else {
                    scanN<6, 6, 128>(dp, s_qwf + 40, A0, A1);
                    scanN<6, 2, 2048>(restBase, s_qwf + 46, A0, A1);
                }
            } else {
                const ulonglong2* dp = restBase + (size_t)((rg - 6) * 16 + 4) * 2048;
                if (path == 0) scanN<4, 8, 2048>(dp, s_qwf + rg * 8, A0, A1);
                else           scanN<6, 8, 2048>(dp, s_qwf + rg * 8, A0, A1);
            }
        } else {
            float f0 = 0.f, f1 = 0.f, f2 = 0.f, f3 = 0.f;
            for (int i = 0; i < 16; ++i) {
                int g = rg * 16 + i;
                const float* r;
                if (g < SROWS) r = s_base + g * SCHUNK + 4 * pg;
                else           r = g_rest + (size_t)(b * RROWS + g - SROWS) * Sz
                                 + k * SCHUNK + 4 * pg;
                float q = s_qraw[g], wv = s_watt[g];
                f0 = fmaf(wv, tanhf(r[0] + q), f0);
                f1 = fmaf(wv, tanhf(r[1] + q), f1);
                f2 = fmaf(wv, tanhf(r[2] + q), f2);
                f3 = fmaf(wv, tanhf(r[3] + q), f3);
            }
            A0 = pack2(f0, f1); A1 = pack2(f2, f3);
        }
        {
            ulonglong2 vv; vv.x = A0; vv.y = A1;
            s_acc[rg * 128 + pg] = vv;
        }
        __syncthreads();

        // ---- reduce 8 row-groups -> block softmax partial ----
        if (t < 128) {
            ull B0 = 0ull, B1 = 0ull;
            #pragma unroll
            for (int r = 0; r < 8; ++r) {
                ulonglong2 v = s_acc[r * 128 + t];
                B0 = f2add(B0, v.x); B1 = f2add(B1, v.y);
            }
            float a0, a1, a2, a3;
            unpack2(B0, a0, a1); unpack2(B1, a2, a3);
            // replicate reference fp32 quantization `attns + 10000.0`
            float aq0 = a0 + 10000.0f, aq1 = a1 + 10000.0f;
            float aq2 = a2 + 10000.0f, aq3 = a3 + 10000.0f;
            int s0 = k * SCHUNK + 4 * t;
            float m, ss; int id;
            if (aq1 > aq0) { m = aq1; id = s0 + 1; ss = __expf(aq0 - aq1) + 1.f; }
            else           { m = aq0; id = s0;     ss = 1.f + __expf(aq1 - aq0); }
            float m2, ss2; int id2;
            if (aq3 > aq2) { m2 = aq3; id2 = s0 + 3; ss2 = __expf(aq2 - aq3) + 1.f; }
            else           { m2 = aq2; id2 = s0 + 2; ss2 = 1.f + __expf(aq3 - aq2); }
            SMAX_COMBINE(m, id, ss, m2, id2, ss2);
            #pragma unroll
            for (int off = 16; off > 0; off >>= 1) {
                float mo = __shfl_down_sync(0xffffffffu, m, off);
                int   io = __shfl_down_sync(0xffffffffu, id, off);
                float so = __shfl_down_sync(0xffffffffu, ss, off);
                SMAX_COMBINE(m, id, ss, mo, io, so);
            }
            if (l == 0) { s_wm[w] = m; s_wi[w] = id; s_ws[w] = ss; }
        }
        __syncthreads();
        if (t < 32) {
            float m  = (t < 4) ? s_wm[t] : -1e30f;
            int   id = (t < 4) ? s_wi[t] : 0x7FFFFFFF;
            float ss = (t < 4) ? s_ws[t] : 0.f;
            #pragma unroll
            for (int off = 2; off > 0; off >>= 1) {
                float mo = __shfl_down_sync(0xffffffffu, m, off);
                int   io = __shfl_down_sync(0xffffffffu, id, off);
                float so = __shfl_down_sync(0xffffffffu, ss, off);
                SMAX_COMBINE(m, id, ss, mo, io, so);
            }
            if (t == 0)
                g_part[b][k] = make_float4(m, __int_as_float(id), ss, 0.f);
        }
        batch_barrier(b);

        // ---- combine 16 partials (redundant per block), emit, gather ----
        if (t < 32) {
            float m = -1e30f, ss = 0.f; int id = 0x7FFFFFFF;
            if (t < NBPB) {
                float4 v = __ldcg(&g_part[b][t]);
                m = v.x; id = __float_as_int(v.y); ss = v.z;
            }
            #pragma unroll
            for (int off = 8; off > 0; off >>= 1) {
                float mo = __shfl_down_sync(0xffffffffu, m, off);
                int   io = __shfl_down_sync(0xffffffffu, id, off);
                float so = __shfl_down_sync(0xffffffffu, ss, off);
                SMAX_COMBINE(m, id, ss, mo, io, so);
            }
            if (t == 0) {
                float logp = -__logf(ss);   // log(max softmax)
                if (k == 0) {
                    int oi = b * STEPS + step;
                    if (oi < out_size) out[oi] = (float)id;
                    int oj = Bz * STEPS + oi;
                    if (oj < out_size) out[oj] = logp;
                }
                s_dec[0] = st[(b * 2 + 0) * Sz + id];
                s_dec[1] = st[(b * 2 + 1) * Sz + id];
            }
        }
        if (t < Hz) s_hhold[t] = hregv;   // publish next-step hh
        __syncthreads();
    }
}

extern "C" void kernel_launch(void* const* d_in, const int* in_sizes, int n_in,
                              void* d_out, int out_size) {
    const float* st    = (const float*)d_in[0];
    const float* dyn   = (const float*)d_in[1];
    const float* W_s   = (const float*)d_in[2];
    const float* b_s   = (const float*)d_in[3];
    const float* W_d   = (const float*)d_in[4];
    const float* b_d   = (const float*)d_in[5];
    const float* W_dec = (const float*)d_in[6];
    const float* b_dec = (const float*)d_in[7];
    const float* W_ih  = (const float*)d_in[8];
    const float* W_hh  = (const float*)d_in[9];
    const float* b_ih  = (const float*)d_in[10];
    const float* b_hh  = (const float*)d_in[11];
    const float* W_ref = (const float*)d_in[12];
    const float* b_ref = (const float*)d_in[13];
    const float* W_pd  = (const float*)d_in[14];
    const float* b_pd  = (const float*)d_in[15];
    const float* W_q   = (const float*)d_in[16];
    const float* b_q   = (const float*)d_in[17];
    const float* W_att = (const float*)d_in[18];

    const int dyn_smem = SROWS * SCHUNK * (int)sizeof(float);   // 188416 B
    static int attr_set = 0;
    if (!attr_set) {
        cudaFuncSetAttribute(persist_kernel,
                             cudaFuncAttributeMaxDynamicSharedMemorySize, dyn_smem);
        attr_set = 1;
    }

    coef_kernel<<<640, 128>>>(W_ref, W_s, b_s, b_ref, W_pd, W_d, b_d, b_pd,
                              W_ih, W_dec, b_dec, b_ih, b_hh);
    persist_kernel<<<NB, NT, dyn_smem>>>(st, dyn, W_hh, W_q, b_q, W_att,
                                         (float*)d_out, out_size);
}

// round 8
// speedup vs baseline: 2.6530x; 1.1590x over previous
#include <cuda_runtime.h>
#include <math.h>

#define Bz 8
#define Sz 8192
#define Hz 128
#define STEPS 20
#define NBPB 16              // blocks per batch
#define NB (Bz * NBPB)       // 128 blocks (<=148 SMs -> co-resident)
#define NT 1024              // 32 warps/block, 1 block/SM
#define SCHUNK 512           // positions per block
#define SROWS 88             // g-rows staged in SMEM (88*512*4 = 176 KB)
#define RROWS 40             // g-rows left in L2

typedef unsigned long long ull;

// -------- persistent scratch --------
__device__ __align__(16) float g_rest[(size_t)Bz * RROWS * Sz];  // 10.5 MB, L2-resident
__device__ float  g_coef[4 * Hz];
__device__ float2 g_U[4 * Hz];      // W_ih @ W_dec
__device__ float  g_V[4 * Hz];      // W_ih @ b_dec + b_ih + b_hh
__device__ float  g_pg[Bz][4 * Hz];                              // gate partials W_hh@h
__device__ __align__(16) float4 g_part[Bz][NBPB];                // (m, id-bits, ssum, pad)
__device__ int      g_bmax[Bz];
__device__ unsigned g_bcnt[Bz];
__device__ unsigned g_bgen[Bz];

// -------- batch-local barrier, acquire/release --------
__device__ __forceinline__ void batch_barrier(int b) {
    __syncthreads();
    if (threadIdx.x == 0) {
        unsigned gen;
        asm volatile("ld.acquire.gpu.global.u32 %0, [%1];"
                     : "=r"(gen) : "l"(&g_bgen[b]) : "memory");
        unsigned arrived;
        asm volatile("atom.acq_rel.gpu.global.add.u32 %0, [%1], %2;"
                     : "=r"(arrived) : "l"(&g_bcnt[b]), "r"(1u) : "memory");
        if (arrived == NBPB - 1) {
            asm volatile("st.global.u32 [%0], %1;" :: "l"(&g_bcnt[b]), "r"(0u) : "memory");
            asm volatile("st.release.gpu.global.u32 [%0], %1;"
                         :: "l"(&g_bgen[b]), "r"(gen + 1u) : "memory");
        } else {
            unsigned cur;
            do {
                asm volatile("ld.acquire.gpu.global.u32 %0, [%1];"
                             : "=r"(cur) : "l"(&g_bgen[b]) : "memory");
            } while (cur == gen);
        }
    }
    __syncthreads();
}

// -------- packed f32x2 helpers --------
__device__ __forceinline__ ull f2add(ull a, ull b) {
    ull d; asm("add.rn.f32x2 %0, %1, %2;" : "=l"(d) : "l"(a), "l"(b)); return d;
}
__device__ __forceinline__ ull f2mul(ull a, ull b) {
    ull d; asm("mul.rn.f32x2 %0, %1, %2;" : "=l"(d) : "l"(a), "l"(b)); return d;
}
__device__ __forceinline__ ull f2fma(ull a, ull b, ull c) {
    ull d; asm("fma.rn.f32x2 %0, %1, %2, %3;" : "=l"(d) : "l"(a), "l"(b), "l"(c)); return d;
}
__device__ __forceinline__ ull dup2(float f) {
    ull d; asm("mov.b64 %0, {%1, %2};" : "=l"(d) : "f"(f), "f"(f)); return d;
}
__device__ __forceinline__ ull pack2(float lo, float hi) {
    ull d; asm("mov.b64 %0, {%1, %2};" : "=l"(d) : "f"(lo), "f"(hi)); return d;
}
__device__ __forceinline__ void unpack2(ull v, float& lo, float& hi) {
    asm("mov.b64 {%0, %1}, %2;" : "=f"(lo), "=f"(hi) : "l"(v));
}

// packed tanh poly: NC=3 deg-7 (|x|<=0.23), NC=4 deg-9 (|x|<=0.32), NC=6 deg-13 (|x|<=0.55)
template<int NC>
__device__ __forceinline__ ull poly_acc(ull V, ull qd, ull wd, ull A) {
    const ull C1 = dup2(-0.33333334f);
    const ull C2 = dup2( 0.13333334f);
    const ull C3 = dup2(-0.053968254f);
    const ull C4 = dup2( 0.021869489f);
    const ull C5 = dup2(-0.008863236f);
    const ull C6 = dup2( 0.0035921280f);
    const ull ONE = dup2(1.0f);
    ull X = f2add(V, qd);
    ull Y = f2mul(X, X);
    ull P;
    if (NC == 6) {
        P = f2fma(Y, C6, C5);
        P = f2fma(P, Y, C4);
        P = f2fma(P, Y, C3);
        P = f2fma(P, Y, C2);
    } else if (NC == 4) {
        P = f2fma(Y, C4, C3);
        P = f2fma(P, Y, C2);
    } else {
        P = f2fma(Y, C3, C2);
    }
    P = f2fma(P, Y, C1);
    P = f2fma(P, Y, ONE);
    return f2fma(wd, f2mul(X, P), A);
}

// NPAIR row-pairs, row stride RS (ulonglong2 units)
template<int NC, int NPAIR, int RS>
__device__ __forceinline__ void scanN(const ulonglong2* __restrict__ dp,
                                      const float4* __restrict__ qp,
                                      ull& A0, ull& A1) {
    #pragma unroll
    for (int i = 0; i < NPAIR; ++i) {
        float4 qw = qp[i];
        ull q0 = dup2(qw.x), q1 = dup2(qw.y);
        ull w0 = dup2(qw.z), w1 = dup2(qw.w);
        ulonglong2 v0 = dp[(size_t)(2 * i) * RS];
        ulonglong2 v1 = dp[(size_t)(2 * i + 1) * RS];
        A0 = poly_acc<NC>(v0.x, q0, w0, A0);
        A1 = poly_acc<NC>(v0.y, q0, w0, A1);
        A0 = poly_acc<NC>(v1.x, q1, w1, A0);
        A1 = poly_acc<NC>(v1.y, q1, w1, A1);
    }
}

// full per-thread scan over 16 rows (rg selects smem vs L2 rows)
template<int NC>
__device__ __forceinline__ void scan_all(int rg, int pg, const float* s_base,
                                         const float4* s_qwf,
                                         const ulonglong2* restBase,
                                         ull& A0, ull& A1) {
    if (rg < 5) {
        const ulonglong2* dp = (const ulonglong2*)s_base + (rg * 16) * 128 + pg;
        scanN<NC, 8, 128>(dp, s_qwf + rg * 8, A0, A1);
    } else if (rg == 5) {
        const ulonglong2* dp = (const ulonglong2*)s_base + 80 * 128 + pg;
        scanN<NC, 4, 128>(dp, s_qwf + 40, A0, A1);
        scanN<NC, 4, 2048>(restBase, s_qwf + 44, A0, A1);
    } else {
        const ulonglong2* dp = restBase + (size_t)((rg - 6) * 16 + 8) * 2048;
        scanN<NC, 8, 2048>(dp, s_qwf + rg * 8, A0, A1);
    }
}

__device__ __forceinline__ float sigmoidf(float x) { return 1.f / (1.f + expf(-x)); }

#define SMAX_COMBINE(m, id, ss, mo, io, so)                          \
    if ((mo) > (m) || ((mo) == (m) && (io) < (id))) {                \
        (ss) = (ss) * __expf((m) - (mo)) + (so);                     \
        (m) = (mo); (id) = (io);                                     \
    } else {                                                         \
        (ss) = (ss) + (so) * __expf((mo) - (m));                     \
    }

// -------- K0: coalesced fold. 640 blocks x 128 thr: one output row each --------
__global__ void coef_kernel(const float* __restrict__ W_ref, const float* __restrict__ W_s,
                            const float* __restrict__ b_s,   const float* __restrict__ b_ref,
                            const float* __restrict__ W_pd,  const float* __restrict__ W_d,
                            const float* __restrict__ b_d,   const float* __restrict__ b_pd,
                            const float* __restrict__ W_ih,  const float* __restrict__ W_dec,
                            const float* __restrict__ b_dec, const float* __restrict__ b_ih,
                            const float* __restrict__ b_hh) {
    __shared__ float s_r[4][4];
    const int h = threadIdx.x, w = h >> 5, l = h & 31;
    float v0, v1, v2, v3;
    if (blockIdx.x < 512) {
        int j = blockIdx.x;
        float wij = W_ih[j * Hz + h];
        v0 = wij * W_dec[h * 2 + 0];
        v1 = wij * W_dec[h * 2 + 1];
        v2 = wij * b_dec[h];
        v3 = 0.f;
    } else {
        int g = blockIdx.x - 512;
        float wr = W_ref[g * Hz + h];
        float wp = W_pd[g * Hz + h];
        v0 = wr * W_s[h * 2 + 0];
        v1 = wr * W_s[h * 2 + 1];
        v2 = fmaf(wr, b_s[h], wp * b_d[h]);
        v3 = wp * W_d[h];
    }
    #pragma unroll
    for (int off = 16; off > 0; off >>= 1) {
        v0 += __shfl_down_sync(0xffffffffu, v0, off);
        v1 += __shfl_down_sync(0xffffffffu, v1, off);
        v2 += __shfl_down_sync(0xffffffffu, v2, off);
        v3 += __shfl_down_sync(0xffffffffu, v3, off);
    }
    if (l == 0) { s_r[0][w] = v0; s_r[1][w] = v1; s_r[2][w] = v2; s_r[3][w] = v3; }
    __syncthreads();
    if (h == 0) {
        float r0 = s_r[0][0] + s_r[0][1] + s_r[0][2] + s_r[0][3];
        float r1 = s_r[1][0] + s_r[1][1] + s_r[1][2] + s_r[1][3];
        float r2 = s_r[2][0] + s_r[2][1] + s_r[2][2] + s_r[2][3];
        float r3 = s_r[3][0] + s_r[3][1] + s_r[3][2] + s_r[3][3];
        if (blockIdx.x < 512) {
            int j = blockIdx.x;
            g_U[j] = make_float2(r0, r1);
            g_V[j] = r2 + b_ih[j] + b_hh[j];
        } else {
            int g = blockIdx.x - 512;
            g_coef[g] = r0;
            g_coef[Hz + g] = r1;
            g_coef[2 * Hz + g] = r3;
            g_coef[3 * Hz + g] = r2 + b_ref[g] + b_pd[g];
        }
    }
}

// -------- persistent decode kernel --------
__global__ __launch_bounds__(NT, 1)
void persist_kernel(const float* __restrict__ st,  const float* __restrict__ dyn,
                    const float* __restrict__ W_hh, const float* __restrict__ W_q,
                    const float* __restrict__ b_q,  const float* __restrict__ W_att,
                    float* __restrict__ out, int out_size) {
    const int blk = blockIdx.x;
    const int b = blk / NBPB;
    const int k = blk % NBPB;
    const int t = threadIdx.x;
    const int w = t >> 5, l = t & 31;

    extern __shared__ float s_base[];                 // SROWS*512 floats = 176 KB

    __shared__ __align__(16) ulonglong2 s_acc[8 * 128];   // 16 KB (phase-0 overlay: coef)
    __shared__ float s_whh[32 * Hz];                  // 16 KB: this block's 32 gate rows
    __shared__ __align__(16) float4 s_uvv[4 * Hz];    // 8 KB: (ux, uy, V, 0) all 512 rows
    __shared__ __align__(16) float4 s_qwf[64];        // [q_g, q_g1, w_g, w_g1]
    __shared__ float s_hhold[Hz];
    __shared__ float s_c[Hz];
    __shared__ float s_qraw[Hz];
    __shared__ float s_watt[Hz];
    __shared__ float s_bq[Hz];
    __shared__ float s_dec[2];
    __shared__ float s_wm[4];
    __shared__ int   s_wi[4];
    __shared__ float s_ws[4];
    __shared__ int   s_imax;

    // ---- phase 0: stage base (88 rows smem, 40 rows L2) + weights ----
    float* s_coef = (float*)s_acc;                    // overlay, phase 0 only
    if (t < 4 * Hz) s_coef[t] = g_coef[t];
    if (t == 0) s_imax = 0;
    for (int idx = t; idx < 32 * Hz; idx += NT) {     // W_hh slice: warp ww -> its gate row
        int ww = idx >> 7, col = idx & 127;
        int j = (ww >> 3) * Hz + k * 8 + (ww & 7);
        s_whh[idx] = W_hh[j * Hz + col];
    }
    if (t < 4 * Hz) {                                  // U/V for ALL 512 gate rows
        float2 u = g_U[t];
        s_uvv[t] = make_float4(u.x, u.y, g_V[t], 0.f);
    }
    if (t < Hz) {
        s_hhold[t] = 0.f; s_c[t] = 0.f;
        s_watt[t] = W_att[t]; s_bq[t] = b_q[t];
    }
    __syncthreads();
    {
        const int sl = t & 511, half = t >> 9;
        const int s = k * SCHUNK + sl;
        const float x = st[(b * 2 + 0) * Sz + s];
        const float y = st[(b * 2 + 1) * Sz + s];
        const float d = dyn[b * Sz + s];
        float lmax = 0.f;
        if (half == 0) {
            #pragma unroll 8
            for (int g = 0; g < 64; ++g) {
                float v = fmaf(s_coef[g], x, fmaf(s_coef[Hz + g], y,
                          fmaf(s_coef[2 * Hz + g], d, s_coef[3 * Hz + g])));
                s_base[g * SCHUNK + sl] = v;
                lmax = fmaxf(lmax, fabsf(v));
            }
        } else {
            #pragma unroll 6
            for (int g = 64; g < SROWS; ++g) {
                float v = fmaf(s_coef[g], x, fmaf(s_coef[Hz + g], y,
                          fmaf(s_coef[2 * Hz + g], d, s_coef[3 * Hz + g])));
                s_base[g * SCHUNK + sl] = v;
                lmax = fmaxf(lmax, fabsf(v));
            }
            #pragma unroll 8
            for (int j = 0; j < RROWS; ++j) {
                int g = SROWS + j;
                float v = fmaf(s_coef[g], x, fmaf(s_coef[Hz + g], y,
                          fmaf(s_coef[2 * Hz + g], d, s_coef[3 * Hz + g])));
                g_rest[((size_t)(b * RROWS + j)) * Sz + s] = v;
                lmax = fmaxf(lmax, fabsf(v));
            }
        }
        atomicMax(&s_imax, __float_as_int(lmax));
    }
    __syncthreads();
    if (t == 0) atomicMax(&g_bmax[b], s_imax);
    batch_barrier(b);
    const float Mb = __int_as_float(__ldcg(&g_bmax[b]));

    const int pg = t & 127, rg = t >> 7;
    const ulonglong2* restBase = (const ulonglong2*)g_rest
                               + (size_t)(b * RROWS) * (Sz / 4) + k * 128 + pg;

    for (int step = 0; step <= STEPS; ++step) {
        // ---- post-barrier: combine prev partials (warp 31) + pgate loads (t<128) ----
        float pg0 = 0.f, pg1 = 0.f, pg2 = 0.f, pg3 = 0.f;
        if (step > 0) {
            if (t < Hz) {
                pg0 = __ldcg(&g_pg[b][t]);
                pg1 = __ldcg(&g_pg[b][Hz + t]);
                pg2 = __ldcg(&g_pg[b][2 * Hz + t]);
                pg3 = __ldcg(&g_pg[b][3 * Hz + t]);
            }
            if (w == 31) {
                float m = -1e30f, ss = 0.f; int id = 0x7FFFFFFF;
                if (l < NBPB) {
                    float4 v = __ldcg(&g_part[b][l]);
                    m = v.x; id = __float_as_int(v.y); ss = v.z;
                }
                #pragma unroll
                for (int off = 8; off > 0; off >>= 1) {
                    float mo = __shfl_down_sync(0xffffffffu, m, off);
                    int   io = __shfl_down_sync(0xffffffffu, id, off);
                    float so = __shfl_down_sync(0xffffffffu, ss, off);
                    SMAX_COMBINE(m, id, ss, mo, io, so);
                }
                if (l == 0) {
                    if (k == 0) {
                        float logp = -__logf(ss);
                        int oi = b * STEPS + (step - 1);
                        if (oi < out_size) out[oi] = (float)id;
                        int oj = Bz * STEPS + oi;
                        if (oj < out_size) out[oj] = logp;
                    }
                    s_dec[0] = st[(b * 2 + 0) * Sz + id];
                    s_dec[1] = st[(b * 2 + 1) * Sz + id];
                }
            }
        } else if (t == 0) { s_dec[0] = 0.f; s_dec[1] = 0.f; }
        __syncthreads();
        if (step == STEPS) break;

        // ---- LSTM finish + h update (redundant per block, bitwise identical) ----
        if (t < Hz) {
            float d0 = s_dec[0], d1 = s_dec[1];
            float4 u0 = s_uvv[t],            u1 = s_uvv[Hz + t],
                   u2 = s_uvv[2 * Hz + t],   u3 = s_uvv[3 * Hz + t];
            float gi = pg0 + fmaf(u0.x, d0, fmaf(u0.y, d1, u0.z));
            float gf = pg1 + fmaf(u1.x, d0, fmaf(u1.y, d1, u1.z));
            float gc = pg2 + fmaf(u2.x, d0, fmaf(u2.y, d1, u2.z));
            float go = pg3 + fmaf(u3.x, d0, fmaf(u3.y, d1, u3.z));
            float c2 = fmaf(sigmoidf(gf), s_c[t], sigmoidf(gi) * tanhf(gc));
            float h2 = sigmoidf(go) * tanhf(c2);
            s_c[t] = c2;
            s_hhold[t] = h2;
        }
        __syncthreads();

        // ---- q = W_q @ h + b_q (redundant; W_q stays L2-hot) ----
        {
            #pragma unroll
            for (int r4 = 0; r4 < 4; ++r4) {
                int row = w * 4 + r4;
                const float* wq = W_q + row * Hz;
                float acc = fmaf(__ldcg(wq + l),      s_hhold[l],
                            fmaf(__ldcg(wq + l + 32), s_hhold[l + 32],
                            fmaf(__ldcg(wq + l + 64), s_hhold[l + 64],
                                 __ldcg(wq + l + 96) * s_hhold[l + 96])));
                #pragma unroll
                for (int off = 16; off > 0; off >>= 1)
                    acc += __shfl_down_sync(0xffffffffu, acc, off);
                if (l == 0) s_qraw[row] = acc + s_bq[row];
            }
        }
        __syncthreads();
        if (t < 64)
            s_qwf[t] = make_float4(s_qraw[2 * t], s_qraw[2 * t + 1],
                                   s_watt[2 * t], s_watt[2 * t + 1]);
        if (t < Hz) {
            float mq = fabsf(s_qraw[t]);
            #pragma unroll
            for (int off = 16; off > 0; off >>= 1)
                mq = fmaxf(mq, __shfl_down_sync(0xffffffffu, mq, off));
            if (l == 0) s_wm[w] = mq;
        }
        __syncthreads();
        const float bound = fmaxf(fmaxf(s_wm[0], s_wm[1]), fmaxf(s_wm[2], s_wm[3])) + Mb;
        const int path = (bound <= 0.23f) ? 0
                       : (bound <= 0.32f) ? 1
                       : (bound <= 0.55f) ? 2 : 3;

        // ---- attention scan: thread = 4 positions (pg) x 16 rows (rg) ----
        ull A0 = 0ull, A1 = 0ull;
        if (path == 0)      scan_all<3>(rg, pg, s_base, s_qwf, restBase, A0, A1);
        else if (path == 1) scan_all<4>(rg, pg, s_base, s_qwf, restBase, A0, A1);
        else if (path == 2) scan_all<6>(rg, pg, s_base, s_qwf, restBase, A0, A1);
        else {
            float f0 = 0.f, f1 = 0.f, f2 = 0.f, f3 = 0.f;
            for (int i = 0; i < 16; ++i) {
                int g = rg * 16 + i;
                const float* r;
                if (g < SROWS) r = s_base + g * SCHUNK + 4 * pg;
                else           r = g_rest + (size_t)(b * RROWS + g - SROWS) * Sz
                                 + k * SCHUNK + 4 * pg;
                float q = s_qraw[g], wv = s_watt[g];
                f0 = fmaf(wv, tanhf(r[0] + q), f0);
                f1 = fmaf(wv, tanhf(r[1] + q), f1);
                f2 = fmaf(wv, tanhf(r[2] + q), f2);
                f3 = fmaf(wv, tanhf(r[3] + q), f3);
            }
            A0 = pack2(f0, f1); A1 = pack2(f2, f3);
        }
        {
            ulonglong2 vv; vv.x = A0; vv.y = A1;
            s_acc[rg * 128 + pg] = vv;
        }
        __syncthreads();

        // ---- reduce 8 row-groups -> block softmax partial ----
        if (t < 128) {
            ull B0 = 0ull, B1 = 0ull;
            #pragma unroll
            for (int r = 0; r < 8; ++r) {
                ulonglong2 v = s_acc[r * 128 + t];
                B0 = f2add(B0, v.x); B1 = f2add(B1, v.y);
            }
            float a0, a1, a2, a3;
            unpack2(B0, a0, a1); unpack2(B1, a2, a3);
            // replicate reference fp32 quantization `attns + 10000.0`
            float aq0 = a0 + 10000.0f, aq1 = a1 + 10000.0f;
            float aq2 = a2 + 10000.0f, aq3 = a3 + 10000.0f;
            int s0 = k * SCHUNK + 4 * t;
            float m, ss; int id;
            if (aq1 > aq0) { m = aq1; id = s0 + 1; ss = __expf(aq0 - aq1) + 1.f; }
            else           { m = aq0; id = s0;     ss = 1.f + __expf(aq1 - aq0); }
            float m2, ss2; int id2;
            if (aq3 > aq2) { m2 = aq3; id2 = s0 + 3; ss2 = __expf(aq2 - aq3) + 1.f; }
            else           { m2 = aq2; id2 = s0 + 2; ss2 = 1.f + __expf(aq3 - aq2); }
            SMAX_COMBINE(m, id, ss, m2, id2, ss2);
            #pragma unroll
            for (int off = 16; off > 0; off >>= 1) {
                float mo = __shfl_down_sync(0xffffffffu, m, off);
                int   io = __shfl_down_sync(0xffffffffu, id, off);
                float so = __shfl_down_sync(0xffffffffu, ss, off);
                SMAX_COMBINE(m, id, ss, mo, io, so);
            }
            if (l == 0) { s_wm[w] = m; s_wi[w] = id; s_ws[w] = ss; }
        }
        __syncthreads();
        if (t < 32) {
            float m  = (t < 4) ? s_wm[t] : -1e30f;
            int   id = (t < 4) ? s_wi[t] : 0x7FFFFFFF;
            float ss = (t < 4) ? s_ws[t] : 0.f;
            #pragma unroll
            for (int off = 2; off > 0; off >>= 1) {
                float mo = __shfl_down_sync(0xffffffffu, m, off);
                int   io = __shfl_down_sync(0xffffffffu, id, off);
                float so = __shfl_down_sync(0xffffffffu, ss, off);
                SMAX_COMBINE(m, id, ss, mo, io, so);
            }
            if (t == 0)
                g_part[b][k] = make_float4(m, __int_as_float(id), ss, 0.f);
        }
        // ---- pre-barrier: this block's 32 gate rows for NEXT step ----
        {
            const float* whr = s_whh + w * Hz;
            float acc = fmaf(whr[l], s_hhold[l],
                        fmaf(whr[l + 32], s_hhold[l + 32],
                        fmaf(whr[l + 64], s_hhold[l + 64],
                             whr[l + 96] * s_hhold[l + 96])));
            #pragma unroll
            for (int off = 16; off > 0; off >>= 1)
                acc += __shfl_down_sync(0xffffffffu, acc, off);
            if (l == 0) {
                int j = (w >> 3) * Hz + k * 8 + (w & 7);
                g_pg[b][j] = acc;
            }
        }
        batch_barrier(b);
    }
}

extern "C" void kernel_launch(void* const* d_in, const int* in_sizes, int n_in,
                              void* d_out, int out_size) {
    const float* st    = (const float*)d_in[0];
    const float* dyn   = (const float*)d_in[1];
    const float* W_s   = (const float*)d_in[2];
    const float* b_s   = (const float*)d_in[3];
    const float* W_d   = (const float*)d_in[4];
    const float* b_d   = (const float*)d_in[5];
    const float* W_dec = (const float*)d_in[6];
    const float* b_dec = (const float*)d_in[7];
    const float* W_ih  = (const float*)d_in[8];
    const float* W_hh  = (const float*)d_in[9];
    const float* b_ih  = (const float*)d_in[10];
    const float* b_hh  = (const float*)d_in[11];
    const float* W_ref = (const float*)d_in[12];
    const float* b_ref = (const float*)d_in[13];
    const float* W_pd  = (const float*)d_in[14];
    const float* b_pd  = (const float*)d_in[15];
    const float* W_q   = (const float*)d_in[16];
    const float* b_q   = (const float*)d_in[17];
    const float* W_att = (const float*)d_in[18];

    const int dyn_smem = SROWS * SCHUNK * (int)sizeof(float);   // 180224 B
    static int attr_set = 0;
    if (!attr_set) {
        cudaFuncSetAttribute(persist_kernel,
                             cudaFuncAttributeMaxDynamicSharedMemorySize, dyn_smem);
        attr_set = 1;
    }

    coef_kernel<<<640, 128>>>(W_ref, W_s, b_s, b_ref, W_pd, W_d, b_d, b_pd,
                              W_ih, W_dec, b_dec, b_ih, b_hh);
    persist_kernel<<<NB, NT, dyn_smem>>>(st, dyn, W_hh, W_q, b_q, W_att,
                                         (float*)d_out, out_size);
}

// round 9
// speedup vs baseline: 2.6577x; 1.0017x over previous
#include <cuda_runtime.h>
#include <math.h>

#define Bz 8
#define Sz 8192
#define Hz 128
#define STEPS 20
#define NBPB 16              // blocks per batch
#define NB (Bz * NBPB)       // 128 blocks (<=148 SMs -> co-resident)
#define NT 1024              // 32 warps/block, 1 block/SM
#define SCHUNK 512           // positions per block
#define SROWS 88             // g-rows staged in SMEM (88*512*4 = 176 KB)
#define RROWS 40             // g-rows left in L2

typedef unsigned long long ull;

// -------- persistent scratch --------
__device__ __align__(16) float g_rest[(size_t)Bz * RROWS * Sz];  // 10.5 MB, L2-resident
__device__ float  g_coef[4 * Hz];
__device__ float2 g_U[4 * Hz];      // W_ih @ W_dec
__device__ float  g_V[4 * Hz];      // W_ih @ b_dec + b_ih + b_hh
__device__ float  g_pg[Bz][4 * Hz];                              // gate partials W_hh@h
__device__ __align__(16) float4 g_part[Bz][NBPB];                // (m, id-bits, ssum, pad)
__device__ int      g_bmax[Bz];
__device__ unsigned g_bcnt[Bz];
__device__ unsigned g_bgen[Bz];

// -------- batch-local barrier, acquire/release --------
__device__ __forceinline__ void batch_barrier(int b) {
    __syncthreads();
    if (threadIdx.x == 0) {
        unsigned gen;
        asm volatile("ld.acquire.gpu.global.u32 %0, [%1];"
                     : "=r"(gen) : "l"(&g_bgen[b]) : "memory");
        unsigned arrived;
        asm volatile("atom.acq_rel.gpu.global.add.u32 %0, [%1], %2;"
                     : "=r"(arrived) : "l"(&g_bcnt[b]), "r"(1u) : "memory");
        if (arrived == NBPB - 1) {
            asm volatile("st.global.u32 [%0], %1;" :: "l"(&g_bcnt[b]), "r"(0u) : "memory");
            asm volatile("st.release.gpu.global.u32 [%0], %1;"
                         :: "l"(&g_bgen[b]), "r"(gen + 1u) : "memory");
        } else {
            unsigned cur;
            do {
                asm volatile("ld.acquire.gpu.global.u32 %0, [%1];"
                             : "=r"(cur) : "l"(&g_bgen[b]) : "memory");
            } while (cur == gen);
        }
    }
    __syncthreads();
}

// -------- packed f32x2 helpers --------
__device__ __forceinline__ ull f2add(ull a, ull b) {
    ull d; asm("add.rn.f32x2 %0, %1, %2;" : "=l"(d) : "l"(a), "l"(b)); return d;
}
__device__ __forceinline__ ull f2mul(ull a, ull b) {
    ull d; asm("mul.rn.f32x2 %0, %1, %2;" : "=l"(d) : "l"(a), "l"(b)); return d;
}
__device__ __forceinline__ ull f2fma(ull a, ull b, ull c) {
    ull d; asm("fma.rn.f32x2 %0, %1, %2, %3;" : "=l"(d) : "l"(a), "l"(b), "l"(c)); return d;
}
__device__ __forceinline__ ull dup2(float f) {
    ull d; asm("mov.b64 %0, {%1, %2};" : "=l"(d) : "f"(f), "f"(f)); return d;
}
__device__ __forceinline__ ull pack2(float lo, float hi) {
    ull d; asm("mov.b64 %0, {%1, %2};" : "=l"(d) : "f"(lo), "f"(hi)); return d;
}
__device__ __forceinline__ void unpack2(ull v, float& lo, float& hi) {
    asm("mov.b64 {%0, %1}, %2;" : "=f"(lo), "=f"(hi) : "l"(v));
}

// packed tanh poly: NC=3 deg-7 (|x|<=0.23), NC=4 deg-9 (|x|<=0.32), NC=6 deg-13 (|x|<=0.55)
template<int NC>
__device__ __forceinline__ ull poly_acc(ull V, ull qd, ull wd, ull A) {
    const ull C1 = dup2(-0.33333334f);
    const ull C2 = dup2( 0.13333334f);
    const ull C3 = dup2(-0.053968254f);
    const ull C4 = dup2( 0.021869489f);
    const ull C5 = dup2(-0.008863236f);
    const ull C6 = dup2( 0.0035921280f);
    const ull ONE = dup2(1.0f);
    ull X = f2add(V, qd);
    ull Y = f2mul(X, X);
    ull P;
    if (NC == 6) {
        P = f2fma(Y, C6, C5);
        P = f2fma(P, Y, C4);
        P = f2fma(P, Y, C3);
        P = f2fma(P, Y, C2);
    } else if (NC == 4) {
        P = f2fma(Y, C4, C3);
        P = f2fma(P, Y, C2);
    } else {
        P = f2fma(Y, C3, C2);
    }
    P = f2fma(P, Y, C1);
    P = f2fma(P, Y, ONE);
    return f2fma(wd, f2mul(X, P), A);
}

// NPAIR row-pairs, row stride RS (ulonglong2 units)
template<int NC, int NPAIR, int RS>
__device__ __forceinline__ void scanN(const ulonglong2* __restrict__ dp,
                                      const float4* __restrict__ qp,
                                      ull& A0, ull& A1) {
    #pragma unroll
    for (int i = 0; i < NPAIR; ++i) {
        float4 qw = qp[i];
        ull q0 = dup2(qw.x), q1 = dup2(qw.y);
        ull w0 = dup2(qw.z), w1 = dup2(qw.w);
        ulonglong2 v0 = dp[(size_t)(2 * i) * RS];
        ulonglong2 v1 = dp[(size_t)(2 * i + 1) * RS];
        A0 = poly_acc<NC>(v0.x, q0, w0, A0);
        A1 = poly_acc<NC>(v0.y, q0, w0, A1);
        A0 = poly_acc<NC>(v1.x, q1, w1, A0);
        A1 = poly_acc<NC>(v1.y, q1, w1, A1);
    }
}

// full per-thread scan over 16 rows (rg selects smem vs L2 rows)
template<int NC>
__device__ __forceinline__ void scan_all(int rg, int pg, const float* s_base,
                                         const float4* s_qwf,
                                         const ulonglong2* restBase,
                                         ull& A0, ull& A1) {
    if (rg < 5) {
        const ulonglong2* dp = (const ulonglong2*)s_base + (rg * 16) * 128 + pg;
        scanN<NC, 8, 128>(dp, s_qwf + rg * 8, A0, A1);
    } else if (rg == 5) {
        const ulonglong2* dp = (const ulonglong2*)s_base + 80 * 128 + pg;
        scanN<NC, 4, 128>(dp, s_qwf + 40, A0, A1);
        scanN<NC, 4, 2048>(restBase, s_qwf + 44, A0, A1);
    } else {
        const ulonglong2* dp = restBase + (size_t)((rg - 6) * 16 + 8) * 2048;
        scanN<NC, 8, 2048>(dp, s_qwf + rg * 8, A0, A1);
    }
}

__device__ __forceinline__ float sigmoidf(float x) { return 1.f / (1.f + expf(-x)); }

#define SMAX_COMBINE(m, id, ss, mo, io, so)                          \
    if ((mo) > (m) || ((mo) == (m) && (io) < (id))) {                \
        (ss) = (ss) * __expf((m) - (mo)) + (so);                     \
        (m) = (mo); (id) = (io);                                     \
    } else {                                                         \
        (ss) = (ss) + (so) * __expf((mo) - (m));                     \
    }

// -------- K0: coalesced fold. 640 blocks x 128 thr: one output row each --------
__global__ void coef_kernel(const float* __restrict__ W_ref, const float* __restrict__ W_s,
                            const float* __restrict__ b_s,   const float* __restrict__ b_ref,
                            const float* __restrict__ W_pd,  const float* __restrict__ W_d,
                            const float* __restrict__ b_d,   const float* __restrict__ b_pd,
                            const float* __restrict__ W_ih,  const float* __restrict__ W_dec,
                            const float* __restrict__ b_dec, const float* __restrict__ b_ih,
                            const float* __restrict__ b_hh) {
    __shared__ float s_r[4][4];
    const int h = threadIdx.x, w = h >> 5, l = h & 31;
    float v0, v1, v2, v3;
    if (blockIdx.x < 512) {
        int j = blockIdx.x;
        float wij = W_ih[j * Hz + h];
        v0 = wij * W_dec[h * 2 + 0];
        v1 = wij * W_dec[h * 2 + 1];
        v2 = wij * b_dec[h];
        v3 = 0.f;
    } else {
        int g = blockIdx.x - 512;
        float wr = W_ref[g * Hz + h];
        float wp = W_pd[g * Hz + h];
        v0 = wr * W_s[h * 2 + 0];
        v1 = wr * W_s[h * 2 + 1];
        v2 = fmaf(wr, b_s[h], wp * b_d[h]);
        v3 = wp * W_d[h];
    }
    #pragma unroll
    for (int off = 16; off > 0; off >>= 1) {
        v0 += __shfl_down_sync(0xffffffffu, v0, off);
        v1 += __shfl_down_sync(0xffffffffu, v1, off);
        v2 += __shfl_down_sync(0xffffffffu, v2, off);
        v3 += __shfl_down_sync(0xffffffffu, v3, off);
    }
    if (l == 0) { s_r[0][w] = v0; s_r[1][w] = v1; s_r[2][w] = v2; s_r[3][w] = v3; }
    __syncthreads();
    if (h == 0) {
        float r0 = s_r[0][0] + s_r[0][1] + s_r[0][2] + s_r[0][3];
        float r1 = s_r[1][0] + s_r[1][1] + s_r[1][2] + s_r[1][3];
        float r2 = s_r[2][0] + s_r[2][1] + s_r[2][2] + s_r[2][3];
        float r3 = s_r[3][0] + s_r[3][1] + s_r[3][2] + s_r[3][3];
        if (blockIdx.x < 512) {
            int j = blockIdx.x;
            g_U[j] = make_float2(r0, r1);
            g_V[j] = r2 + b_ih[j] + b_hh[j];
        } else {
            int g = blockIdx.x - 512;
            g_coef[g] = r0;
            g_coef[Hz + g] = r1;
            g_coef[2 * Hz + g] = r3;
            g_coef[3 * Hz + g] = r2 + b_ref[g] + b_pd[g];
        }
    }
}

// -------- persistent decode kernel --------
__global__ __launch_bounds__(NT, 1)
void persist_kernel(const float* __restrict__ st,  const float* __restrict__ dyn,
                    const float* __restrict__ W_hh, const float* __restrict__ W_q,
                    const float* __restrict__ b_q,  const float* __restrict__ W_att,
                    float* __restrict__ out, int out_size) {
    const int blk = blockIdx.x;
    const int b = blk / NBPB;
    const int k = blk % NBPB;
    const int t = threadIdx.x;
    const int w = t >> 5, l = t & 31;

    extern __shared__ float s_base[];                 // SROWS*512 floats = 176 KB

    __shared__ __align__(16) ulonglong2 s_acc[8 * 128];   // 16 KB (phase-0 overlay: coef)
    __shared__ float s_whh[32 * Hz];                  // 16 KB: this block's 32 gate rows
    __shared__ __align__(16) float4 s_uvv[4 * Hz];    // 8 KB: (ux, uy, V, 0) all 512 rows
    __shared__ __align__(16) float4 s_qwf[64];        // [q_g, q_g1, w_g, w_g1]
    __shared__ float s_hhold[Hz];
    __shared__ float s_c[Hz];
    __shared__ float s_qraw[Hz];
    __shared__ float s_watt[Hz];
    __shared__ float s_bq[Hz];
    __shared__ float s_dec[2];
    __shared__ float s_wm[4];
    __shared__ int   s_wi[4];
    __shared__ float s_ws[4];
    __shared__ int   s_imax;

    // ---- phase 0: stage base (88 rows smem, 40 rows L2) + weights ----
    float* s_coef = (float*)s_acc;                    // overlay, phase 0 only
    if (t < 4 * Hz) s_coef[t] = g_coef[t];
    if (t == 0) s_imax = 0;
    for (int idx = t; idx < 32 * Hz; idx += NT) {     // W_hh slice: warp ww -> its gate row
        int ww = idx >> 7, col = idx & 127;
        int j = (ww >> 3) * Hz + k * 8 + (ww & 7);
        s_whh[idx] = W_hh[j * Hz + col];
    }
    if (t < 4 * Hz) {                                  // U/V for ALL 512 gate rows
        float2 u = g_U[t];
        s_uvv[t] = make_float4(u.x, u.y, g_V[t], 0.f);
    }
    if (t < Hz) {
        s_hhold[t] = 0.f; s_c[t] = 0.f;
        s_watt[t] = W_att[t]; s_bq[t] = b_q[t];
    }
    __syncthreads();
    {
        const int sl = t & 511, half = t >> 9;
        const int s = k * SCHUNK + sl;
        const float x = st[(b * 2 + 0) * Sz + s];
        const float y = st[(b * 2 + 1) * Sz + s];
        const float d = dyn[b * Sz + s];
        float lmax = 0.f;
        if (half == 0) {
            #pragma unroll 8
            for (int g = 0; g < 64; ++g) {
                float v = fmaf(s_coef[g], x, fmaf(s_coef[Hz + g], y,
                          fmaf(s_coef[2 * Hz + g], d, s_coef[3 * Hz + g])));
                s_base[g * SCHUNK + sl] = v;
                lmax = fmaxf(lmax, fabsf(v));
            }
        } else {
            #pragma unroll 6
            for (int g = 64; g < SROWS; ++g) {
                float v = fmaf(s_coef[g], x, fmaf(s_coef[Hz + g], y,
                          fmaf(s_coef[2 * Hz + g], d, s_coef[3 * Hz + g])));
                s_base[g * SCHUNK + sl] = v;
                lmax = fmaxf(lmax, fabsf(v));
            }
            #pragma unroll 8
            for (int j = 0; j < RROWS; ++j) {
                int g = SROWS + j;
                float v = fmaf(s_coef[g], x, fmaf(s_coef[Hz + g], y,
                          fmaf(s_coef[2 * Hz + g], d, s_coef[3 * Hz + g])));
                g_rest[((size_t)(b * RROWS + j)) * Sz + s] = v;
                lmax = fmaxf(lmax, fabsf(v));
            }
        }
        atomicMax(&s_imax, __float_as_int(lmax));
    }
    __syncthreads();
    if (t == 0) atomicMax(&g_bmax[b], s_imax);
    batch_barrier(b);
    const float Mb = __int_as_float(__ldcg(&g_bmax[b]));

    const int pg = t & 127, rg = t >> 7;
    const ulonglong2* restBase = (const ulonglong2*)g_rest
                               + (size_t)(b * RROWS) * (Sz / 4) + k * 128 + pg;

    for (int step = 0; step <= STEPS; ++step) {
        // ---- post-barrier: combine prev partials (warp 31) + pgate loads (t<128) ----
        float pg0 = 0.f, pg1 = 0.f, pg2 = 0.f, pg3 = 0.f;
        if (step > 0) {
            if (t < Hz) {
                pg0 = __ldcg(&g_pg[b][t]);
                pg1 = __ldcg(&g_pg[b][Hz + t]);
                pg2 = __ldcg(&g_pg[b][2 * Hz + t]);
                pg3 = __ldcg(&g_pg[b][3 * Hz + t]);
            }
            if (w == 31) {
                float m = -1e30f, ss = 0.f; int id = 0x7FFFFFFF;
                if (l < NBPB) {
                    float4 v = __ldcg(&g_part[b][l]);
                    m = v.x; id = __float_as_int(v.y); ss = v.z;
                }
                #pragma unroll
                for (int off = 8; off > 0; off >>= 1) {
                    float mo = __shfl_down_sync(0xffffffffu, m, off);
                    int   io = __shfl_down_sync(0xffffffffu, id, off);
                    float so = __shfl_down_sync(0xffffffffu, ss, off);
                    SMAX_COMBINE(m, id, ss, mo, io, so);
                }
                if (l == 0) {
                    if (k == 0) {
                        float logp = -__logf(ss);
                        int oi = b * STEPS + (step - 1);
                        if (oi < out_size) out[oi] = (float)id;
                        int oj = Bz * STEPS + oi;
                        if (oj < out_size) out[oj] = logp;
                    }
                    s_dec[0] = st[(b * 2 + 0) * Sz + id];
                    s_dec[1] = st[(b * 2 + 1) * Sz + id];
                }
            }
        } else if (t == 0) { s_dec[0] = 0.f; s_dec[1] = 0.f; }
        __syncthreads();
        if (step == STEPS) break;

        // ---- LSTM finish + h update (redundant per block, bitwise identical) ----
        if (t < Hz) {
            float d0 = s_dec[0], d1 = s_dec[1];
            float4 u0 = s_uvv[t],            u1 = s_uvv[Hz + t],
                   u2 = s_uvv[2 * Hz + t],   u3 = s_uvv[3 * Hz + t];
            float gi = pg0 + fmaf(u0.x, d0, fmaf(u0.y, d1, u0.z));
            float gf = pg1 + fmaf(u1.x, d0, fmaf(u1.y, d1, u1.z));
            float gc = pg2 + fmaf(u2.x, d0, fmaf(u2.y, d1, u2.z));
            float go = pg3 + fmaf(u3.x, d0, fmaf(u3.y, d1, u3.z));
            float c2 = fmaf(sigmoidf(gf), s_c[t], sigmoidf(gi) * tanhf(gc));
            float h2 = sigmoidf(go) * tanhf(c2);
            s_c[t] = c2;
            s_hhold[t] = h2;
        }
        __syncthreads();

        // ---- q = W_q @ h + b_q (redundant; W_q stays L2-hot) ----
        {
            #pragma unroll
            for (int r4 = 0; r4 < 4; ++r4) {
                int row = w * 4 + r4;
                const float* wq = W_q + row * Hz;
                float acc = fmaf(__ldcg(wq + l),      s_hhold[l],
                            fmaf(__ldcg(wq + l + 32), s_hhold[l + 32],
                            fmaf(__ldcg(wq + l + 64), s_hhold[l + 64],
                                 __ldcg(wq + l + 96) * s_hhold[l + 96])));
                #pragma unroll
                for (int off = 16; off > 0; off >>= 1)
                    acc += __shfl_down_sync(0xffffffffu, acc, off);
                if (l == 0) s_qraw[row] = acc + s_bq[row];
            }
        }
        __syncthreads();
        if (t < 64)
            s_qwf[t] = make_float4(s_qraw[2 * t], s_qraw[2 * t + 1],
                                   s_watt[2 * t], s_watt[2 * t + 1]);
        if (t < Hz) {
            float mq = fabsf(s_qraw[t]);
            #pragma unroll
            for (int off = 16; off > 0; off >>= 1)
                mq = fmaxf(mq, __shfl_down_sync(0xffffffffu, mq, off));
            if (l == 0) s_wm[w] = mq;
        }
        __syncthreads();
        const float bound = fmaxf(fmaxf(s_wm[0], s_wm[1]), fmaxf(s_wm[2], s_wm[3])) + Mb;
        const int path = (bound <= 0.23f) ? 0
                       : (bound <= 0.32f) ? 1
                       : (bound <= 0.55f) ? 2 : 3;

        // ---- attention scan: thread = 4 positions (pg) x 16 rows (rg) ----
        ull A0 = 0ull, A1 = 0ull;
        if (path == 0)      scan_all<3>(rg, pg, s_base, s_qwf, restBase, A0, A1);
        else if (path == 1) scan_all<4>(rg, pg, s_base, s_qwf, restBase, A0, A1);
        else if (path == 2) scan_all<6>(rg, pg, s_base, s_qwf, restBase, A0, A1);
        else {
            float f0 = 0.f, f1 = 0.f, f2 = 0.f, f3 = 0.f;
            for (int i = 0; i < 16; ++i) {
                int g = rg * 16 + i;
                const float* r;
                if (g < SROWS) r = s_base + g * SCHUNK + 4 * pg;
                else           r = g_rest + (size_t)(b * RROWS + g - SROWS) * Sz
                                 + k * SCHUNK + 4 * pg;
                float q = s_qraw[g], wv = s_watt[g];
                f0 = fmaf(wv, tanhf(r[0] + q), f0);
                f1 = fmaf(wv, tanhf(r[1] + q), f1);
                f2 = fmaf(wv, tanhf(r[2] + q), f2);
                f3 = fmaf(wv, tanhf(r[3] + q), f3);
            }
            A0 = pack2(f0, f1); A1 = pack2(f2, f3);
        }
        {
            ulonglong2 vv; vv.x = A0; vv.y = A1;
            s_acc[rg * 128 + pg] = vv;
        }
        __syncthreads();

        // ---- reduce 8 row-groups -> block softmax partial ----
        if (t < 128) {
            ull B0 = 0ull, B1 = 0ull;
            #pragma unroll
            for (int r = 0; r < 8; ++r) {
                ulonglong2 v = s_acc[r * 128 + t];
                B0 = f2add(B0, v.x); B1 = f2add(B1, v.y);
            }
            float a0, a1, a2, a3;
            unpack2(B0, a0, a1); unpack2(B1, a2, a3);
            // replicate reference fp32 quantization `attns + 10000.0`
            float aq0 = a0 + 10000.0f, aq1 = a1 + 10000.0f;
            float aq2 = a2 + 10000.0f, aq3 = a3 + 10000.0f;
            int s0 = k * SCHUNK + 4 * t;
            float m, ss; int id;
            if (aq1 > aq0) { m = aq1; id = s0 + 1; ss = __expf(aq0 - aq1) + 1.f; }
            else           { m = aq0; id = s0;     ss = 1.f + __expf(aq1 - aq0); }
            float m2, ss2; int id2;
            if (aq3 > aq2) { m2 = aq3; id2 = s0 + 3; ss2 = __expf(aq2 - aq3) + 1.f; }
            else           { m2 = aq2; id2 = s0 + 2; ss2 = 1.f + __expf(aq3 - aq2); }
            SMAX_COMBINE(m, id, ss, m2, id2, ss2);
            #pragma unroll
            for (int off = 16; off > 0; off >>= 1) {
                float mo = __shfl_down_sync(0xffffffffu, m, off);
                int   io = __shfl_down_sync(0xffffffffu, id, off);
                float so = __shfl_down_sync(0xffffffffu, ss, off);
                SMAX_COMBINE(m, id, ss, mo, io, so);
            }
            if (l == 0) { s_wm[w] = m; s_wi[w] = id; s_ws[w] = ss; }
        }
        __syncthreads();
        if (t < 32) {
            float m  = (t < 4) ? s_wm[t] : -1e30f;
            int   id = (t < 4) ? s_wi[t] : 0x7FFFFFFF;
            float ss = (t < 4) ? s_ws[t] : 0.f;
            #pragma unroll
            for (int off = 2; off > 0; off >>= 1) {
                float mo = __shfl_down_sync(0xffffffffu, m, off);
                int   io = __shfl_down_sync(0xffffffffu, id, off);
                float so = __shfl_down_sync(0xffffffffu, ss, off);
                SMAX_COMBINE(m, id, ss, mo, io, so);
            }
            if (t == 0)
                g_part[b][k] = make_float4(m, __int_as_float(id), ss, 0.f);
        }
        // ---- pre-barrier: this block's 32 gate rows for NEXT step ----
        {
            const float* whr = s_whh + w * Hz;
            float acc = fmaf(whr[l], s_hhold[l],
                        fmaf(whr[l + 32], s_hhold[l + 32],
                        fmaf(whr[l + 64], s_hhold[l + 64],
                             whr[l + 96] * s_hhold[l + 96])));
            #pragma unroll
            for (int off = 16; off > 0; off >>= 1)
                acc += __shfl_down_sync(0xffffffffu, acc, off);
            if (l == 0) {
                int j = (w >> 3) * Hz + k * 8 + (w & 7);
                g_pg[b][j] = acc;
            }
        }
        batch_barrier(b);
    }
}

extern "C" void kernel_launch(void* const* d_in, const int* in_sizes, int n_in,
                              void* d_out, int out_size) {
    const float* st    = (const float*)d_in[0];
    const float* dyn   = (const float*)d_in[1];
    const float* W_s   = (const float*)d_in[2];
    const float* b_s   = (const float*)d_in[3];
    const float* W_d   = (const float*)d_in[4];
    const float* b_d   = (const float*)d_in[5];
    const float* W_dec = (const float*)d_in[6];
    const float* b_dec = (const float*)d_in[7];
    const float* W_ih  = (const float*)d_in[8];
    const float* W_hh  = (const float*)d_in[9];
    const float* b_ih  = (const float*)d_in[10];
    const float* b_hh  = (const float*)d_in[11];
    const float* W_ref = (const float*)d_in[12];
    const float* b_ref = (const float*)d_in[13];
    const float* W_pd  = (const float*)d_in[14];
    const float* b_pd  = (const float*)d_in[15];
    const float* W_q   = (const float*)d_in[16];
    const float* b_q   = (const float*)d_in[17];
    const float* W_att = (const float*)d_in[18];

    const int dyn_smem = SROWS * SCHUNK * (int)sizeof(float);   // 180224 B
    static int attr_set = 0;
    if (!attr_set) {
        cudaFuncSetAttribute(persist_kernel,
                             cudaFuncAttributeMaxDynamicSharedMemorySize, dyn_smem);
        attr_set = 1;
    }

    coef_kernel<<<640, 128>>>(W_ref, W_s, b_s, b_ref, W_pd, W_d, b_d, b_pd,
                              W_ih, W_dec, b_dec, b_ih, b_hh);
    persist_kernel<<<NB, NT, dyn_smem>>>(st, dyn, W_hh, W_q, b_q, W_att,
                                         (float*)d_out, out_size);
}

// round 10
// speedup vs baseline: 3.0704x; 1.1553x over previous
#include <cuda_runtime.h>
#include <math.h>

#define Bz 8
#define Sz 8192
#define Hz 128
#define STEPS 20
#define NBPB 16              // blocks per batch
#define NB (Bz * NBPB)       // 128 blocks (<=148 SMs -> co-resident)
#define NT 1024              // 32 warps/block
#define SCHUNK 512           // positions per block

typedef unsigned long long ull;

// -------- persistent scratch --------
__device__ float  g_coef[4 * Hz];   // a0 | a1 | dd | C
__device__ float2 g_U[4 * Hz];      // W_ih @ W_dec
__device__ float  g_V[4 * Hz];      // W_ih @ b_dec + b_ih + b_hh
__device__ float  g_pg[Bz][4 * Hz];                 // gate partials W_hh@h
__device__ __align__(16) float4 g_part[Bz][NBPB];   // (m, id-bits, ssum, pad)
__device__ int      g_bmax[Bz];
__device__ unsigned g_bcnt[Bz];
__device__ unsigned g_bgen[Bz];

// -------- batch-local barrier, acquire/release --------
__device__ __forceinline__ void batch_barrier(int b) {
    __syncthreads();
    if (threadIdx.x == 0) {
        unsigned gen;
        asm volatile("ld.acquire.gpu.global.u32 %0, [%1];"
                     : "=r"(gen) : "l"(&g_bgen[b]) : "memory");
        unsigned arrived;
        asm volatile("atom.acq_rel.gpu.global.add.u32 %0, [%1], %2;"
                     : "=r"(arrived) : "l"(&g_bcnt[b]), "r"(1u) : "memory");
        if (arrived == NBPB - 1) {
            asm volatile("st.global.u32 [%0], %1;" :: "l"(&g_bcnt[b]), "r"(0u) : "memory");
            asm volatile("st.release.gpu.global.u32 [%0], %1;"
                         :: "l"(&g_bgen[b]), "r"(gen + 1u) : "memory");
        } else {
            unsigned cur;
            do {
                asm volatile("ld.acquire.gpu.global.u32 %0, [%1];"
                             : "=r"(cur) : "l"(&g_bgen[b]) : "memory");
            } while (cur == gen);
        }
    }
    __syncthreads();
}

// -------- packed f32x2 helpers --------
__device__ __forceinline__ ull f2add(ull a, ull b) {
    ull d; asm("add.rn.f32x2 %0, %1, %2;" : "=l"(d) : "l"(a), "l"(b)); return d;
}
__device__ __forceinline__ ull f2mul(ull a, ull b) {
    ull d; asm("mul.rn.f32x2 %0, %1, %2;" : "=l"(d) : "l"(a), "l"(b)); return d;
}
__device__ __forceinline__ ull f2fma(ull a, ull b, ull c) {
    ull d; asm("fma.rn.f32x2 %0, %1, %2, %3;" : "=l"(d) : "l"(a), "l"(b), "l"(c)); return d;
}
__device__ __forceinline__ ull dup2(float f) {
    ull d; asm("mov.b64 %0, {%1, %2};" : "=l"(d) : "f"(f), "f"(f)); return d;
}
__device__ __forceinline__ ull pack2(float lo, float hi) {
    ull d; asm("mov.b64 %0, {%1, %2};" : "=l"(d) : "f"(lo), "f"(hi)); return d;
}
__device__ __forceinline__ void unpack2(ull v, float& lo, float& hi) {
    asm("mov.b64 {%0, %1}, %2;" : "=f"(lo), "=f"(hi) : "l"(v));
}

// tanh Taylor tail: NC=3 deg-7 (|x|<=0.23), NC=4 deg-9 (|x|<=0.32), NC=6 deg-13 (|x|<=0.55)
template<int NC>
__device__ __forceinline__ ull poly_core(ull X, ull wd, ull A) {
    const ull C1 = dup2(-0.33333334f);
    const ull C2 = dup2( 0.13333334f);
    const ull C3 = dup2(-0.053968254f);
    const ull C4 = dup2( 0.021869489f);
    const ull C5 = dup2(-0.008863236f);
    const ull C6 = dup2( 0.0035921280f);
    const ull ONE = dup2(1.0f);
    ull Y = f2mul(X, X);
    ull P;
    if (NC == 6) {
        P = f2fma(Y, C6, C5);
        P = f2fma(P, Y, C4);
        P = f2fma(P, Y, C3);
        P = f2fma(P, Y, C2);
    } else if (NC == 4) {
        P = f2fma(Y, C4, C3);
        P = f2fma(P, Y, C2);
    } else {
        P = f2fma(Y, C3, C2);
    }
    P = f2fma(P, Y, C1);
    P = f2fma(P, Y, ONE);
    return f2fma(wd, f2mul(X, P), A);
}

// scan 16 rows for 4 positions held in register packs; tables are smem broadcasts
template<int NC>
__device__ __forceinline__ void scan16(int g0,
                                       ull XV0, ull XV1, ull YV0, ull YV1,
                                       ull DV0, ull DV1,
                                       const ulonglong2* __restrict__ s_ad,
                                       const ulonglong2* __restrict__ s_dw,
                                       const ull* __restrict__ s_qd,
                                       ull& A0, ull& A1) {
    #pragma unroll
    for (int i = 0; i < 16; ++i) {
        int g = g0 + i;
        ulonglong2 ad = s_ad[g];      // {dup(a0), dup(a1)}
        ulonglong2 dw = s_dw[g];      // {dup(dd), dup(w)}
        ull qd = s_qd[g];             // dup(q + C)
        ull X0 = f2fma(ad.x, XV0, qd);
        X0 = f2fma(ad.y, YV0, X0);
        X0 = f2fma(dw.x, DV0, X0);
        ull X1 = f2fma(ad.x, XV1, qd);
        X1 = f2fma(ad.y, YV1, X1);
        X1 = f2fma(dw.x, DV1, X1);
        A0 = poly_core<NC>(X0, dw.y, A0);
        A1 = poly_core<NC>(X1, dw.y, A1);
    }
}

__device__ __forceinline__ float sigmoidf(float x) { return 1.f / (1.f + expf(-x)); }

#define SMAX_COMBINE(m, id, ss, mo, io, so)                          \
    if ((mo) > (m) || ((mo) == (m) && (io) < (id))) {                \
        (ss) = (ss) * __expf((m) - (mo)) + (so);                     \
        (m) = (mo); (id) = (io);                                     \
    } else {                                                         \
        (ss) = (ss) + (so) * __expf((mo) - (m));                     \
    }

// -------- K0: coalesced fold. 640 blocks x 128 thr: one output row each --------
__global__ void coef_kernel(const float* __restrict__ W_ref, const float* __restrict__ W_s,
                            const float* __restrict__ b_s,   const float* __restrict__ b_ref,
                            const float* __restrict__ W_pd,  const float* __restrict__ W_d,
                            const float* __restrict__ b_d,   const float* __restrict__ b_pd,
                            const float* __restrict__ W_ih,  const float* __restrict__ W_dec,
                            const float* __restrict__ b_dec, const float* __restrict__ b_ih,
                            const float* __restrict__ b_hh) {
    __shared__ float s_r[4][4];
    const int h = threadIdx.x, w = h >> 5, l = h & 31;
    float v0, v1, v2, v3;
    if (blockIdx.x < 512) {
        int j = blockIdx.x;
        float wij = W_ih[j * Hz + h];
        v0 = wij * W_dec[h * 2 + 0];
        v1 = wij * W_dec[h * 2 + 1];
        v2 = wij * b_dec[h];
        v3 = 0.f;
    } else {
        int g = blockIdx.x - 512;
        float wr = W_ref[g * Hz + h];
        float wp = W_pd[g * Hz + h];
        v0 = wr * W_s[h * 2 + 0];
        v1 = wr * W_s[h * 2 + 1];
        v2 = fmaf(wr, b_s[h], wp * b_d[h]);
        v3 = wp * W_d[h];
    }
    #pragma unroll
    for (int off = 16; off > 0; off >>= 1) {
        v0 += __shfl_down_sync(0xffffffffu, v0, off);
        v1 += __shfl_down_sync(0xffffffffu, v1, off);
        v2 += __shfl_down_sync(0xffffffffu, v2, off);
        v3 += __shfl_down_sync(0xffffffffu, v3, off);
    }
    if (l == 0) { s_r[0][w] = v0; s_r[1][w] = v1; s_r[2][w] = v2; s_r[3][w] = v3; }
    __syncthreads();
    if (h == 0) {
        float r0 = s_r[0][0] + s_r[0][1] + s_r[0][2] + s_r[0][3];
        float r1 = s_r[1][0] + s_r[1][1] + s_r[1][2] + s_r[1][3];
        float r2 = s_r[2][0] + s_r[2][1] + s_r[2][2] + s_r[2][3];
        float r3 = s_r[3][0] + s_r[3][1] + s_r[3][2] + s_r[3][3];
        if (blockIdx.x < 512) {
            int j = blockIdx.x;
            g_U[j] = make_float2(r0, r1);
            g_V[j] = r2 + b_ih[j] + b_hh[j];
        } else {
            int g = blockIdx.x - 512;
            g_coef[g] = r0;                               // a0
            g_coef[Hz + g] = r1;                          // a1
            g_coef[2 * Hz + g] = r3;                      // dd
            g_coef[3 * Hz + g] = r2 + b_ref[g] + b_pd[g]; // C
        }
    }
}

// -------- persistent decode kernel --------
__global__ __launch_bounds__(NT, 1)
void persist_kernel(const float* __restrict__ st,  const float* __restrict__ dyn,
                    const float* __restrict__ W_hh, const float* __restrict__ W_q,
                    const float* __restrict__ b_q,  const float* __restrict__ W_att,
                    float* __restrict__ out, int out_size) {
    const int blk = blockIdx.x;
    const int b = blk / NBPB;
    const int k = blk % NBPB;
    const int t = threadIdx.x;
    const int w = t >> 5, l = t & 31;
    const int pg = t & 127, rg = t >> 7;

    extern __shared__ float dsm[];
    float* s_wq = dsm;                                   // 64 KB: W_q 128x128
    ulonglong2* s_acc = (ulonglong2*)(dsm + Hz * Hz);    // 16 KB

    __shared__ float s_whh[32 * Hz];                     // 16 KB: block's 32 gate rows
    __shared__ __align__(16) float4 s_uvv[4 * Hz];       // 8 KB
    __shared__ __align__(16) ulonglong2 s_ad[Hz];        // {dup a0, dup a1}
    __shared__ __align__(16) ulonglong2 s_dw[Hz];        // {dup dd, dup w}
    __shared__ ull   s_qd[Hz];                           // dup(q + C)
    __shared__ float s_a0[Hz], s_a1[Hz], s_dd[Hz], s_w[Hz], s_Cg[Hz], s_qc[Hz];
    __shared__ float s_qraw[Hz], s_bq[Hz];
    __shared__ float s_hhold[Hz], s_c[Hz];
    __shared__ float s_dec[2];
    __shared__ float s_wm[4];
    __shared__ int   s_wi[4];
    __shared__ float s_ws[4];
    __shared__ int   s_imax;

    // ---- phase 0: tables + weights + per-thread position data ----
    if (t < Hz) {
        float a0 = g_coef[t], a1 = g_coef[Hz + t];
        float dd = g_coef[2 * Hz + t], C = g_coef[3 * Hz + t];
        float wv = W_att[t];
        s_a0[t] = a0; s_a1[t] = a1; s_dd[t] = dd; s_Cg[t] = C; s_w[t] = wv;
        ulonglong2 e; e.x = dup2(a0); e.y = dup2(a1); s_ad[t] = e;
        ulonglong2 f; f.x = dup2(dd); f.y = dup2(wv); s_dw[t] = f;
        s_hhold[t] = 0.f; s_c[t] = 0.f; s_bq[t] = b_q[t];
    }
    for (int idx = t; idx < Hz * Hz; idx += NT) s_wq[idx] = W_q[idx];
    for (int idx = t; idx < 32 * Hz; idx += NT) {
        int ww = idx >> 7, col = idx & 127;
        int j = (ww >> 3) * Hz + k * 8 + (ww & 7);
        s_whh[idx] = W_hh[j * Hz + col];
    }
    if (t < 4 * Hz) {
        float2 u = g_U[t];
        s_uvv[t] = make_float4(u.x, u.y, g_V[t], 0.f);
    }
    if (t == 0) s_imax = 0;
    __syncthreads();

    // position data (4 positions per thread; replicated across rg groups)
    const int s0 = k * SCHUNK + 4 * pg;
    const float4 x4 = *(const float4*)(st + (b * 2 + 0) * Sz + s0);
    const float4 y4 = *(const float4*)(st + (b * 2 + 1) * Sz + s0);
    const float4 d4 = *(const float4*)(dyn + b * Sz + s0);
    const ull XV0 = pack2(x4.x, x4.y), XV1 = pack2(x4.z, x4.w);
    const ull YV0 = pack2(y4.x, y4.y), YV1 = pack2(y4.z, y4.w);
    const ull DV0 = pack2(d4.x, d4.y), DV1 = pack2(d4.z, d4.w);

    // Mu = max |a0 x + a1 y + dd d| over this thread's positions x its 16 rows
    {
        float lmax = 0.f;
        #pragma unroll 4
        for (int i = 0; i < 16; ++i) {
            int g = rg * 16 + i;
            float a0 = s_a0[g], a1 = s_a1[g], dd = s_dd[g];
            float u0 = fmaf(a0, x4.x, fmaf(a1, y4.x, dd * d4.x));
            float u1 = fmaf(a0, x4.y, fmaf(a1, y4.y, dd * d4.y));
            float u2 = fmaf(a0, x4.z, fmaf(a1, y4.z, dd * d4.z));
            float u3 = fmaf(a0, x4.w, fmaf(a1, y4.w, dd * d4.w));
            lmax = fmaxf(lmax, fmaxf(fmaxf(fabsf(u0), fabsf(u1)),
                                     fmaxf(fabsf(u2), fabsf(u3))));
        }
        atomicMax(&s_imax, __float_as_int(lmax));
    }
    __syncthreads();
    if (t == 0) atomicMax(&g_bmax[b], s_imax);
    batch_barrier(b);
    const float Mb = __int_as_float(__ldcg(&g_bmax[b]));

    for (int step = 0; step <= STEPS; ++step) {
        // ---- post-barrier: pgate loads (t<128) + combine prev partials (warp 31) ----
        float pg0 = 0.f, pg1 = 0.f, pg2 = 0.f, pg3 = 0.f;
        if (step > 0) {
            if (t < Hz) {
                pg0 = __ldcg(&g_pg[b][t]);
                pg1 = __ldcg(&g_pg[b][Hz + t]);
                pg2 = __ldcg(&g_pg[b][2 * Hz + t]);
                pg3 = __ldcg(&g_pg[b][3 * Hz + t]);
            }
            if (w == 31) {
                float m = -1e30f, ss = 0.f; int id = 0x7FFFFFFF;
                if (l < NBPB) {
                    float4 v = __ldcg(&g_part[b][l]);
                    m = v.x; id = __float_as_int(v.y); ss = v.z;
                }
                #pragma unroll
                for (int off = 8; off > 0; off >>= 1) {
                    float mo = __shfl_down_sync(0xffffffffu, m, off);
                    int   io = __shfl_down_sync(0xffffffffu, id, off);
                    float so = __shfl_down_sync(0xffffffffu, ss, off);
                    SMAX_COMBINE(m, id, ss, mo, io, so);
                }
                if (l == 0) {
                    if (k == 0) {
                        float logp = -__logf(ss);
                        int oi = b * STEPS + (step - 1);
                        if (oi < out_size) out[oi] = (float)id;
                        int oj = Bz * STEPS + oi;
                        if (oj < out_size) out[oj] = logp;
                    }
                    s_dec[0] = st[(b * 2 + 0) * Sz + id];
                    s_dec[1] = st[(b * 2 + 1) * Sz + id];
                }
            }
        } else if (t == 0) { s_dec[0] = 0.f; s_dec[1] = 0.f; }
        __syncthreads();
        if (step == STEPS) break;

        // ---- LSTM finish + h update (redundant per block, bitwise identical) ----
        if (t < Hz) {
            float d0 = s_dec[0], d1 = s_dec[1];
            float4 u0 = s_uvv[t],          u1 = s_uvv[Hz + t],
                   u2 = s_uvv[2 * Hz + t], u3 = s_uvv[3 * Hz + t];
            float gi = pg0 + fmaf(u0.x, d0, fmaf(u0.y, d1, u0.z));
            float gf = pg1 + fmaf(u1.x, d0, fmaf(u1.y, d1, u1.z));
            float gc = pg2 + fmaf(u2.x, d0, fmaf(u2.y, d1, u2.z));
            float go = pg3 + fmaf(u3.x, d0, fmaf(u3.y, d1, u3.z));
            float c2 = fmaf(sigmoidf(gf), s_c[t], sigmoidf(gi) * tanhf(gc));
            float h2 = sigmoidf(go) * tanhf(c2);
            s_c[t] = c2;
            s_hhold[t] = h2;
        }
        __syncthreads();

        // ---- q = W_q @ h + b_q (all from smem; redundant per block) ----
        {
            #pragma unroll
            for (int r4 = 0; r4 < 4; ++r4) {
                int row = w * 4 + r4;
                const float* wq = s_wq + row * Hz;
                float acc = fmaf(wq[l],      s_hhold[l],
                            fmaf(wq[l + 32], s_hhold[l + 32],
                            fmaf(wq[l + 64], s_hhold[l + 64],
                                 wq[l + 96] * s_hhold[l + 96])));
                #pragma unroll
                for (int off = 16; off > 0; off >>= 1)
                    acc += __shfl_down_sync(0xffffffffu, acc, off);
                if (l == 0) s_qraw[row] = acc + s_bq[row];
            }
        }
        __syncthreads();
        if (t < Hz) {
            float qc = s_qraw[t] + s_Cg[t];
            s_qc[t] = qc;
            s_qd[t] = dup2(qc);
            float mq = fabsf(qc);
            #pragma unroll
            for (int off = 16; off > 0; off >>= 1)
                mq = fmaxf(mq, __shfl_down_sync(0xffffffffu, mq, off));
            if (l == 0) s_wm[w] = mq;
        }
        __syncthreads();
        const float bound = fmaxf(fmaxf(s_wm[0], s_wm[1]), fmaxf(s_wm[2], s_wm[3])) + Mb;
        const int path = (bound <= 0.23f) ? 0
                       : (bound <= 0.32f) ? 1
                       : (bound <= 0.55f) ? 2 : 3;

        // ---- attention scan: on-the-fly base, 4 positions x 16 rows/thread ----
        ull A0 = 0ull, A1 = 0ull;
        if (path == 0)
            scan16<3>(rg * 16, XV0, XV1, YV0, YV1, DV0, DV1, s_ad, s_dw, s_qd, A0, A1);
        else if (path == 1)
            scan16<4>(rg * 16, XV0, XV1, YV0, YV1, DV0, DV1, s_ad, s_dw, s_qd, A0, A1);
        else if (path == 2)
            scan16<6>(rg * 16, XV0, XV1, YV0, YV1, DV0, DV1, s_ad, s_dw, s_qd, A0, A1);
        else {
            float f0 = 0.f, f1 = 0.f, f2 = 0.f, f3 = 0.f;
            for (int i = 0; i < 16; ++i) {
                int g = rg * 16 + i;
                float a0 = s_a0[g], a1 = s_a1[g], dd = s_dd[g];
                float qc = s_qc[g], wv = s_w[g];
                f0 = fmaf(wv, tanhf(fmaf(a0, x4.x, fmaf(a1, y4.x, fmaf(dd, d4.x, qc)))), f0);
                f1 = fmaf(wv, tanhf(fmaf(a0, x4.y, fmaf(a1, y4.y, fmaf(dd, d4.y, qc)))), f1);
                f2 = fmaf(wv, tanhf(fmaf(a0, x4.z, fmaf(a1, y4.z, fmaf(dd, d4.z, qc)))), f2);
                f3 = fmaf(wv, tanhf(fmaf(a0, x4.w, fmaf(a1, y4.w, fmaf(dd, d4.w, qc)))), f3);
            }
            A0 = pack2(f0, f1); A1 = pack2(f2, f3);
        }
        {
            ulonglong2 vv; vv.x = A0; vv.y = A1;
            s_acc[rg * 128 + pg] = vv;
        }
        __syncthreads();

        // ---- reduce 8 row-groups -> block softmax partial ----
        if (t < 128) {
            ull B0 = 0ull, B1 = 0ull;
            #pragma unroll
            for (int r = 0; r < 8; ++r) {
                ulonglong2 v = s_acc[r * 128 + t];
                B0 = f2add(B0, v.x); B1 = f2add(B1, v.y);
            }
            float a0, a1, a2, a3;
            unpack2(B0, a0, a1); unpack2(B1, a2, a3);
            // replicate reference fp32 quantization `attns + 10000.0`
            float aq0 = a0 + 10000.0f, aq1 = a1 + 10000.0f;
            float aq2 = a2 + 10000.0f, aq3 = a3 + 10000.0f;
            int sb = k * SCHUNK + 4 * t;
            float m, ss; int id;
            if (aq1 > aq0) { m = aq1; id = sb + 1; ss = __expf(aq0 - aq1) + 1.f; }
            else           { m = aq0; id = sb;     ss = 1.f + __expf(aq1 - aq0); }
            float m2, ss2; int id2;
            if (aq3 > aq2) { m2 = aq3; id2 = sb + 3; ss2 = __expf(aq2 - aq3) + 1.f; }
            else           { m2 = aq2; id2 = sb + 2; ss2 = 1.f + __expf(aq3 - aq2); }
            SMAX_COMBINE(m, id, ss, m2, id2, ss2);
            #pragma unroll
            for (int off = 16; off > 0; off >>= 1) {
                float mo = __shfl_down_sync(0xffffffffu, m, off);
                int   io = __shfl_down_sync(0xffffffffu, id, off);
                float so = __shfl_down_sync(0xffffffffu, ss, off);
                SMAX_COMBINE(m, id, ss, mo, io, so);
            }
            if (l == 0) { s_wm[w] = m; s_wi[w] = id; s_ws[w] = ss; }
        }
        __syncthreads();
        if (t < 32) {
            float m  = (t < 4) ? s_wm[t] : -1e30f;
            int   id = (t < 4) ? s_wi[t] : 0x7FFFFFFF;
            float ss = (t < 4) ? s_ws[t] : 0.f;
            #pragma unroll
            for (int off = 2; off > 0; off >>= 1) {
                float mo = __shfl_down_sync(0xffffffffu, m, off);
                int   io = __shfl_down_sync(0xffffffffu, id, off);
                float so = __shfl_down_sync(0xffffffffu, ss, off);
                SMAX_COMBINE(m, id, ss, mo, io, so);
            }
            if (t == 0)
                g_part[b][k] = make_float4(m, __int_as_float(id), ss, 0.f);
        }
        // ---- pre-barrier: this block's 32 gate rows for NEXT step ----
        {
            const float* whr = s_whh + w * Hz;
            float acc = fmaf(whr[l],      s_hhold[l],
                        fmaf(whr[l + 32], s_hhold[l + 32],
                        fmaf(whr[l + 64], s_hhold[l + 64],
                             whr[l + 96] * s_hhold[l + 96])));
            #pragma unroll
            for (int off = 16; off > 0; off >>= 1)
                acc += __shfl_down_sync(0xffffffffu, acc, off);
            if (l == 0) {
                int j = (w >> 3) * Hz + k * 8 + (w & 7);
                g_pg[b][j] = acc;
            }
        }
        batch_barrier(b);
    }
}

extern "C" void kernel_launch(void* const* d_in, const int* in_sizes, int n_in,
                              void* d_out, int out_size) {
    const float* st    = (const float*)d_in[0];
    const float* dyn   = (const float*)d_in[1];
    const float* W_s   = (const float*)d_in[2];
    const float* b_s   = (const float*)d_in[3];
    const float* W_d   = (const float*)d_in[4];
    const float* b_d   = (const float*)d_in[5];
    const float* W_dec = (const float*)d_in[6];
    const float* b_dec = (const float*)d_in[7];
    const float* W_ih  = (const float*)d_in[8];
    const float* W_hh  = (const float*)d_in[9];
    const float* b_ih  = (const float*)d_in[10];
    const float* b_hh  = (const float*)d_in[11];
    const float* W_ref = (const float*)d_in[12];
    const float* b_ref = (const float*)d_in[13];
    const float* W_pd  = (const float*)d_in[14];
    const float* b_pd  = (const float*)d_in[15];
    const float* W_q   = (const float*)d_in[16];
    const float* b_q   = (const float*)d_in[17];
    const float* W_att = (const float*)d_in[18];

    const int dyn_smem = (Hz * Hz) * (int)sizeof(float) + 8 * 128 * 16;  // 64K + 16K
    static int attr_set = 0;
    if (!attr_set) {
        cudaFuncSetAttribute(persist_kernel,
                             cudaFuncAttributeMaxDynamicSharedMemorySize, dyn_smem);
        attr_set = 1;
    }

    coef_kernel<<<640, 128>>>(W_ref, W_s, b_s, b_ref, W_pd, W_d, b_d, b_pd,
                              W_ih, W_dec, b_dec, b_ih, b_hh);
    persist_kernel<<<NB, NT, dyn_smem>>>(st, dyn, W_hh, W_q, b_q, W_att,
                                         (float*)d_out, out_size);
}

// round 11
// speedup vs baseline: 3.1287x; 1.0190x over previous
#include <cuda_runtime.h>
#include <math.h>

#define Bz 8
#define Sz 8192
#define Hz 128
#define STEPS 20
#define NBPB 16              // blocks per batch
#define NB (Bz * NBPB)       // 128 blocks (<=148 SMs -> co-resident)
#define NT 1024              // 32 warps/block
#define SCHUNK 512           // positions per block

typedef unsigned long long ull;

// -------- persistent scratch --------
__device__ float  g_coef[4 * Hz];   // a0 | a1 | dd | C
__device__ float2 g_U[4 * Hz];      // W_ih @ W_dec
__device__ float  g_V[4 * Hz];      // W_ih @ b_dec + b_ih + b_hh
__device__ float  g_pg[Bz][4 * Hz];                 // gate partials W_hh@h
__device__ __align__(16) float4 g_part[Bz][NBPB];   // (m, id-bits, ssum, pad)
__device__ int      g_bmax[Bz];
__device__ int      g_dnz[Bz];                      // dynamic-nonzero flag
__device__ unsigned g_bcnt[Bz];
__device__ unsigned g_bgen[Bz];

// -------- batch-local barrier, acquire/release --------
__device__ __forceinline__ void batch_barrier(int b) {
    __syncthreads();
    if (threadIdx.x == 0) {
        unsigned gen;
        asm volatile("ld.acquire.gpu.global.u32 %0, [%1];"
                     : "=r"(gen) : "l"(&g_bgen[b]) : "memory");
        unsigned arrived;
        asm volatile("atom.acq_rel.gpu.global.add.u32 %0, [%1], %2;"
                     : "=r"(arrived) : "l"(&g_bcnt[b]), "r"(1u) : "memory");
        if (arrived == NBPB - 1) {
            asm volatile("st.global.u32 [%0], %1;" :: "l"(&g_bcnt[b]), "r"(0u) : "memory");
            asm volatile("st.release.gpu.global.u32 [%0], %1;"
                         :: "l"(&g_bgen[b]), "r"(gen + 1u) : "memory");
        } else {
            unsigned cur;
            do {
                asm volatile("ld.acquire.gpu.global.u32 %0, [%1];"
                             : "=r"(cur) : "l"(&g_bgen[b]) : "memory");
            } while (cur == gen);
        }
    }
    __syncthreads();
}

// -------- packed f32x2 helpers --------
__device__ __forceinline__ ull f2add(ull a, ull b) {
    ull d; asm("add.rn.f32x2 %0, %1, %2;" : "=l"(d) : "l"(a), "l"(b)); return d;
}
__device__ __forceinline__ ull f2mul(ull a, ull b) {
    ull d; asm("mul.rn.f32x2 %0, %1, %2;" : "=l"(d) : "l"(a), "l"(b)); return d;
}
__device__ __forceinline__ ull f2fma(ull a, ull b, ull c) {
    ull d; asm("fma.rn.f32x2 %0, %1, %2, %3;" : "=l"(d) : "l"(a), "l"(b), "l"(c)); return d;
}
__device__ __forceinline__ ull dup2(float f) {
    ull d; asm("mov.b64 %0, {%1, %2};" : "=l"(d) : "f"(f), "f"(f)); return d;
}
__device__ __forceinline__ ull pack2(float lo, float hi) {
    ull d; asm("mov.b64 %0, {%1, %2};" : "=l"(d) : "f"(lo), "f"(hi)); return d;
}
__device__ __forceinline__ void unpack2(ull v, float& lo, float& hi) {
    asm("mov.b64 {%0, %1}, %2;" : "=f"(lo), "=f"(hi) : "l"(v));
}

// tanh Taylor tail: NC=3 deg-7 (|x|<=0.23), NC=4 deg-9 (|x|<=0.32), NC=6 deg-13 (|x|<=0.55)
template<int NC>
__device__ __forceinline__ ull poly_core(ull X, ull wd, ull A) {
    const ull C1 = dup2(-0.33333334f);
    const ull C2 = dup2( 0.13333334f);
    const ull C3 = dup2(-0.053968254f);
    const ull C4 = dup2( 0.021869489f);
    const ull C5 = dup2(-0.008863236f);
    const ull C6 = dup2( 0.0035921280f);
    const ull ONE = dup2(1.0f);
    ull Y = f2mul(X, X);
    ull P;
    if (NC == 6) {
        P = f2fma(Y, C6, C5);
        P = f2fma(P, Y, C4);
        P = f2fma(P, Y, C3);
        P = f2fma(P, Y, C2);
    } else if (NC == 4) {
        P = f2fma(Y, C4, C3);
        P = f2fma(P, Y, C2);
    } else {
        P = f2fma(Y, C3, C2);
    }
    P = f2fma(P, Y, C1);
    P = f2fma(P, Y, ONE);
    return f2fma(wd, f2mul(X, P), A);
}

// 16 rows x 4 positions per thread; one LDS.128 per row; ALU dup expansion
template<int NC, bool HASD>
__device__ __forceinline__ void scan16b(int g0,
                                        ull XV0, ull XV1, ull YV0, ull YV1,
                                        ull DV0, ull DV1,
                                        const float4* __restrict__ s_tab4,
                                        const float* __restrict__ s_ddt,
                                        ull& A0, ull& A1) {
    #pragma unroll
    for (int i = 0; i < 16; ++i) {
        int g = g0 + i;
        float4 v = s_tab4[g];                 // {a0, a1, q+C, w}
        ull a0d = dup2(v.x), a1d = dup2(v.y);
        ull qd  = dup2(v.z), wd  = dup2(v.w);
        ull X0 = f2fma(a1d, YV0, qd);
        ull X1 = f2fma(a1d, YV1, qd);
        X0 = f2fma(a0d, XV0, X0);
        X1 = f2fma(a0d, XV1, X1);
        if (HASD) {
            ull ddd = dup2(s_ddt[g]);
            X0 = f2fma(ddd, DV0, X0);
            X1 = f2fma(ddd, DV1, X1);
        }
        A0 = poly_core<NC>(X0, wd, A0);
        A1 = poly_core<NC>(X1, wd, A1);
    }
}

__device__ __forceinline__ float sigmoidf(float x) { return 1.f / (1.f + expf(-x)); }

#define SMAX_COMBINE(m, id, ss, mo, io, so)                          \
    if ((mo) > (m) || ((mo) == (m) && (io) < (id))) {                \
        (ss) = (ss) * __expf((m) - (mo)) + (so);                     \
        (m) = (mo); (id) = (io);                                     \
    } else {                                                         \
        (ss) = (ss) + (so) * __expf((mo) - (m));                     \
    }

// -------- K0: coalesced fold. 640 blocks x 128 thr: one output row each --------
__global__ void coef_kernel(const float* __restrict__ W_ref, const float* __restrict__ W_s,
                            const float* __restrict__ b_s,   const float* __restrict__ b_ref,
                            const float* __restrict__ W_pd,  const float* __restrict__ W_d,
                            const float* __restrict__ b_d,   const float* __restrict__ b_pd,
                            const float* __restrict__ W_ih,  const float* __restrict__ W_dec,
                            const float* __restrict__ b_dec, const float* __restrict__ b_ih,
                            const float* __restrict__ b_hh) {
    __shared__ float s_r[4][4];
    const int h = threadIdx.x, w = h >> 5, l = h & 31;
    float v0, v1, v2, v3;
    if (blockIdx.x < 512) {
        int j = blockIdx.x;
        float wij = W_ih[j * Hz + h];
        v0 = wij * W_dec[h * 2 + 0];
        v1 = wij * W_dec[h * 2 + 1];
        v2 = wij * b_dec[h];
        v3 = 0.f;
    } else {
        int g = blockIdx.x - 512;
        float wr = W_ref[g * Hz + h];
        float wp = W_pd[g * Hz + h];
        v0 = wr * W_s[h * 2 + 0];
        v1 = wr * W_s[h * 2 + 1];
        v2 = fmaf(wr, b_s[h], wp * b_d[h]);
        v3 = wp * W_d[h];
    }
    #pragma unroll
    for (int off = 16; off > 0; off >>= 1) {
        v0 += __shfl_down_sync(0xffffffffu, v0, off);
        v1 += __shfl_down_sync(0xffffffffu, v1, off);
        v2 += __shfl_down_sync(0xffffffffu, v2, off);
        v3 += __shfl_down_sync(0xffffffffu, v3, off);
    }
    if (l == 0) { s_r[0][w] = v0; s_r[1][w] = v1; s_r[2][w] = v2; s_r[3][w] = v3; }
    __syncthreads();
    if (h == 0) {
        float r0 = s_r[0][0] + s_r[0][1] + s_r[0][2] + s_r[0][3];
        float r1 = s_r[1][0] + s_r[1][1] + s_r[1][2] + s_r[1][3];
        float r2 = s_r[2][0] + s_r[2][1] + s_r[2][2] + s_r[2][3];
        float r3 = s_r[3][0] + s_r[3][1] + s_r[3][2] + s_r[3][3];
        if (blockIdx.x < 512) {
            int j = blockIdx.x;
            g_U[j] = make_float2(r0, r1);
            g_V[j] = r2 + b_ih[j] + b_hh[j];
        } else {
            int g = blockIdx.x - 512;
            g_coef[g] = r0;                               // a0
            g_coef[Hz + g] = r1;                          // a1
            g_coef[2 * Hz + g] = r3;                      // dd
            g_coef[3 * Hz + g] = r2 + b_ref[g] + b_pd[g]; // C
        }
    }
}

// -------- persistent decode kernel --------
__global__ __launch_bounds__(NT, 1)
void persist_kernel(const float* __restrict__ st,  const float* __restrict__ dyn,
                    const float* __restrict__ W_hh, const float* __restrict__ W_q,
                    const float* __restrict__ b_q,  const float* __restrict__ W_att,
                    float* __restrict__ out, int out_size) {
    const int blk = blockIdx.x;
    const int b = blk / NBPB;
    const int k = blk % NBPB;
    const int t = threadIdx.x;
    const int w = t >> 5, l = t & 31;
    const int pg = t & 127, rg = t >> 7;

    extern __shared__ float dsm[];
    float* s_wq = dsm;                                   // 64 KB: W_q 128x128
    ulonglong2* s_acc = (ulonglong2*)(dsm + Hz * Hz);    // 16 KB

    __shared__ float s_whh[32 * Hz];                     // 16 KB: block's 32 gate rows
    __shared__ __align__(16) float4 s_uvv[4 * Hz];       // 8 KB
    __shared__ __align__(16) float4 s_tab4[Hz];          // {a0, a1, q+C, w} per step
    __shared__ float s_a0[Hz], s_a1[Hz], s_dd[Hz], s_w[Hz], s_Cg[Hz], s_qc[Hz];
    __shared__ float s_qraw[Hz], s_bq[Hz];
    __shared__ float s_hhold[Hz], s_c[Hz];
    __shared__ float s_dec[2];
    __shared__ float s_wm[4];
    __shared__ int   s_wi[4];
    __shared__ float s_ws[4];
    __shared__ int   s_imax;
    __shared__ int   s_dnz;

    // ---- phase 0: tables + weights + per-thread position data ----
    if (t < Hz) {
        float a0 = g_coef[t], a1 = g_coef[Hz + t];
        float dd = g_coef[2 * Hz + t], C = g_coef[3 * Hz + t];
        float wv = W_att[t];
        s_a0[t] = a0; s_a1[t] = a1; s_dd[t] = dd; s_Cg[t] = C; s_w[t] = wv;
        s_hhold[t] = 0.f; s_c[t] = 0.f; s_bq[t] = b_q[t];
    }
    for (int idx = t; idx < Hz * Hz; idx += NT) s_wq[idx] = W_q[idx];
    for (int idx = t; idx < 32 * Hz; idx += NT) {
        int ww = idx >> 7, col = idx & 127;
        int j = (ww >> 3) * Hz + k * 8 + (ww & 7);
        s_whh[idx] = W_hh[j * Hz + col];
    }
    if (t < 4 * Hz) {
        float2 u = g_U[t];
        s_uvv[t] = make_float4(u.x, u.y, g_V[t], 0.f);
    }
    if (t == 0) { s_imax = 0; s_dnz = 0; }
    __syncthreads();

    // position data (4 positions per thread; replicated across rg groups)
    const int s0 = k * SCHUNK + 4 * pg;
    const float4 x4 = *(const float4*)(st + (b * 2 + 0) * Sz + s0);
    const float4 y4 = *(const float4*)(st + (b * 2 + 1) * Sz + s0);
    const float4 d4 = *(const float4*)(dyn + b * Sz + s0);
    const ull XV0 = pack2(x4.x, x4.y), XV1 = pack2(x4.z, x4.w);
    const ull YV0 = pack2(y4.x, y4.y), YV1 = pack2(y4.z, y4.w);
    const ull DV0 = pack2(d4.x, d4.y), DV1 = pack2(d4.z, d4.w);

    // Mu = max |a0 x + a1 y + dd d| over this thread's positions x its 16 rows
    {
        float lmax = 0.f;
        #pragma unroll 4
        for (int i = 0; i < 16; ++i) {
            int g = rg * 16 + i;
            float a0 = s_a0[g], a1 = s_a1[g], dd = s_dd[g];
            float u0 = fmaf(a0, x4.x, fmaf(a1, y4.x, dd * d4.x));
            float u1 = fmaf(a0, x4.y, fmaf(a1, y4.y, dd * d4.y));
            float u2 = fmaf(a0, x4.z, fmaf(a1, y4.z, dd * d4.z));
            float u3 = fmaf(a0, x4.w, fmaf(a1, y4.w, dd * d4.w));
            lmax = fmaxf(lmax, fmaxf(fmaxf(fabsf(u0), fabsf(u1)),
                                     fmaxf(fabsf(u2), fabsf(u3))));
        }
        atomicMax(&s_imax, __float_as_int(lmax));
        if (rg == 0) {
            int nz = (d4.x != 0.f || d4.y != 0.f || d4.z != 0.f || d4.w != 0.f) ? 1 : 0;
            if (nz) s_dnz = 1;
        }
    }
    __syncthreads();
    if (t == 0) {
        atomicMax(&g_bmax[b], s_imax);
        if (s_dnz) atomicMax(&g_dnz[b], 1);
    }
    batch_barrier(b);
    const float Mb = __int_as_float(__ldcg(&g_bmax[b]));
    const bool hasd = __ldcg(&g_dnz[b]) != 0;

    for (int step = 0; step <= STEPS; ++step) {
        // ---- post-barrier: pgate loads (t<128) + combine prev partials (warp 31) ----
        float pg0 = 0.f, pg1 = 0.f, pg2 = 0.f, pg3 = 0.f;
        if (step > 0) {
            if (t < Hz) {
                pg0 = __ldcg(&g_pg[b][t]);
                pg1 = __ldcg(&g_pg[b][Hz + t]);
                pg2 = __ldcg(&g_pg[b][2 * Hz + t]);
                pg3 = __ldcg(&g_pg[b][3 * Hz + t]);
            }
            if (w == 31) {
                float m = -1e30f, ss = 0.f; int id = 0x7FFFFFFF;
                if (l < NBPB) {
                    float4 v = __ldcg(&g_part[b][l]);
                    m = v.x; id = __float_as_int(v.y); ss = v.z;
                }
                #pragma unroll
                for (int off = 8; off > 0; off >>= 1) {
                    float mo = __shfl_down_sync(0xffffffffu, m, off);
                    int   io = __shfl_down_sync(0xffffffffu, id, off);
                    float so = __shfl_down_sync(0xffffffffu, ss, off);
                    SMAX_COMBINE(m, id, ss, mo, io, so);
                }
                if (l == 0) {
                    if (k == 0) {
                        float logp = -__logf(ss);
                        int oi = b * STEPS + (step - 1);
                        if (oi < out_size) out[oi] = (float)id;
                        int oj = Bz * STEPS + oi;
                        if (oj < out_size) out[oj] = logp;
                    }
                    s_dec[0] = st[(b * 2 + 0) * Sz + id];
                    s_dec[1] = st[(b * 2 + 1) * Sz + id];
                }
            }
        } else if (t == 0) { s_dec[0] = 0.f; s_dec[1] = 0.f; }
        __syncthreads();
        if (step == STEPS) break;

        // ---- LSTM finish + h update (redundant per block, bitwise identical) ----
        if (t < Hz) {
            float d0 = s_dec[0], d1 = s_dec[1];
            float4 u0 = s_uvv[t],          u1 = s_uvv[Hz + t],
                   u2 = s_uvv[2 * Hz + t], u3 = s_uvv[3 * Hz + t];
            float gi = pg0 + fmaf(u0.x, d0, fmaf(u0.y, d1, u0.z));
            float gf = pg1 + fmaf(u1.x, d0, fmaf(u1.y, d1, u1.z));
            float gc = pg2 + fmaf(u2.x, d0, fmaf(u2.y, d1, u2.z));
            float go = pg3 + fmaf(u3.x, d0, fmaf(u3.y, d1, u3.z));
            float c2 = fmaf(sigmoidf(gf), s_c[t], sigmoidf(gi) * tanhf(gc));
            float h2 = sigmoidf(go) * tanhf(c2);
            s_c[t] = c2;
            s_hhold[t] = h2;
        }
        __syncthreads();

        // ---- q = W_q @ h + b_q (all from smem; redundant per block) ----
        {
            #pragma unroll
            for (int r4 = 0; r4 < 4; ++r4) {
                int row = w * 4 + r4;
                const float* wq = s_wq + row * Hz;
                float acc = fmaf(wq[l],      s_hhold[l],
                            fmaf(wq[l + 32], s_hhold[l + 32],
                            fmaf(wq[l + 64], s_hhold[l + 64],
                                 wq[l + 96] * s_hhold[l + 96])));
                #pragma unroll
                for (int off = 16; off > 0; off >>= 1)
                    acc += __shfl_down_sync(0xffffffffu, acc, off);
                if (l == 0) s_qraw[row] = acc + s_bq[row];
            }
        }
        __syncthreads();
        if (t < Hz) {
            float qc = s_qraw[t] + s_Cg[t];
            s_qc[t] = qc;
            s_tab4[t] = make_float4(s_a0[t], s_a1[t], qc, s_w[t]);
            float mq = fabsf(qc);
            #pragma unroll
            for (int off = 16; off > 0; off >>= 1)
                mq = fmaxf(mq, __shfl_down_sync(0xffffffffu, mq, off));
            if (l == 0) s_wm[w] = mq;
        }
        __syncthreads();
        const float bound = fmaxf(fmaxf(s_wm[0], s_wm[1]), fmaxf(s_wm[2], s_wm[3])) + Mb;
        const int path = (bound <= 0.23f) ? 0
                       : (bound <= 0.32f) ? 1
                       : (bound <= 0.55f) ? 2 : 3;

        // ---- attention scan: on-the-fly base, 4 positions x 16 rows/thread ----
        ull A0 = 0ull, A1 = 0ull;
        if (path <= 2) {
            if (!hasd) {
                if (path == 0)
                    scan16b<3, false>(rg * 16, XV0, XV1, YV0, YV1, DV0, DV1, s_tab4, s_dd, A0, A1);
                else if (path == 1)
                    scan16b<4, false>(rg * 16, XV0, XV1, YV0, YV1, DV0, DV1, s_tab4, s_dd, A0, A1);
                else
                    scan16b<6, false>(rg * 16, XV0, XV1, YV0, YV1, DV0, DV1, s_tab4, s_dd, A0, A1);
            } else {
                if (path == 0)
                    scan16b<3, true>(rg * 16, XV0, XV1, YV0, YV1, DV0, DV1, s_tab4, s_dd, A0, A1);
                else if (path == 1)
                    scan16b<4, true>(rg * 16, XV0, XV1, YV0, YV1, DV0, DV1, s_tab4, s_dd, A0, A1);
                else
                    scan16b<6, true>(rg * 16, XV0, XV1, YV0, YV1, DV0, DV1, s_tab4, s_dd, A0, A1);
            }
        } else {
            float f0 = 0.f, f1 = 0.f, f2 = 0.f, f3 = 0.f;
            for (int i = 0; i < 16; ++i) {
                int g = rg * 16 + i;
                float a0 = s_a0[g], a1 = s_a1[g], dd = s_dd[g];
                float qc = s_qc[g], wv = s_w[g];
                f0 = fmaf(wv, tanhf(fmaf(a0, x4.x, fmaf(a1, y4.x, fmaf(dd, d4.x, qc)))), f0);
                f1 = fmaf(wv, tanhf(fmaf(a0, x4.y, fmaf(a1, y4.y, fmaf(dd, d4.y, qc)))), f1);
                f2 = fmaf(wv, tanhf(fmaf(a0, x4.z, fmaf(a1, y4.z, fmaf(dd, d4.z, qc)))), f2);
                f3 = fmaf(wv, tanhf(fmaf(a0, x4.w, fmaf(a1, y4.w, fmaf(dd, d4.w, qc)))), f3);
            }
            A0 = pack2(f0, f1); A1 = pack2(f2, f3);
        }
        {
            ulonglong2 vv; vv.x = A0; vv.y = A1;
            s_acc[rg * 128 + pg] = vv;
        }
        __syncthreads();

        // ---- reduce 8 row-groups -> block softmax partial ----
        if (t < 128) {
            ull B0 = 0ull, B1 = 0ull;
            #pragma unroll
            for (int r = 0; r < 8; ++r) {
                ulonglong2 v = s_acc[r * 128 + t];
                B0 = f2add(B0, v.x); B1 = f2add(B1, v.y);
            }
            float a0, a1, a2, a3;
            unpack2(B0, a0, a1); unpack2(B1, a2, a3);
            // replicate reference fp32 quantization `attns + 10000.0`
            float aq0 = a0 + 10000.0f, aq1 = a1 + 10000.0f;
            float aq2 = a2 + 10000.0f, aq3 = a3 + 10000.0f;
            int sb = k * SCHUNK + 4 * t;
            float m, ss; int id;
            if (aq1 > aq0) { m = aq1; id = sb + 1; ss = __expf(aq0 - aq1) + 1.f; }
            else           { m = aq0; id = sb;     ss = 1.f + __expf(aq1 - aq0); }
            float m2, ss2; int id2;
            if (aq3 > aq2) { m2 = aq3; id2 = sb + 3; ss2 = __expf(aq2 - aq3) + 1.f; }
            else           { m2 = aq2; id2 = sb + 2; ss2 = 1.f + __expf(aq3 - aq2); }
            SMAX_COMBINE(m, id, ss, m2, id2, ss2);
            #pragma unroll
            for (int off = 16; off > 0; off >>= 1) {
                float mo = __shfl_down_sync(0xffffffffu, m, off);
                int   io = __shfl_down_sync(0xffffffffu, id, off);
                float so = __shfl_down_sync(0xffffffffu, ss, off);
                SMAX_COMBINE(m, id, ss, mo, io, so);
            }
            if (l == 0) { s_wm[w] = m; s_wi[w] = id; s_ws[w] = ss; }
        }
        __syncthreads();
        if (t < 32) {
            float m  = (t < 4) ? s_wm[t] : -1e30f;
            int   id = (t < 4) ? s_wi[t] : 0x7FFFFFFF;
            float ss = (t < 4) ? s_ws[t] : 0.f;
            #pragma unroll
            for (int off = 2; off > 0; off >>= 1) {
                float mo = __shfl_down_sync(0xffffffffu, m, off);
                int   io = __shfl_down_sync(0xffffffffu, id, off);
                float so = __shfl_down_sync(0xffffffffu, ss, off);
                SMAX_COMBINE(m, id, ss, mo, io, so);
            }
            if (t == 0)
                g_part[b][k] = make_float4(m, __int_as_float(id), ss, 0.f);
        }
        // ---- pre-barrier: this block's 32 gate rows for NEXT step ----
        {
            const float* whr = s_whh + w * Hz;
            float acc = fmaf(whr[l],      s_hhold[l],
                        fmaf(whr[l + 32], s_hhold[l + 32],
                        fmaf(whr[l + 64], s_hhold[l + 64],
                             whr[l + 96] * s_hhold[l + 96])));
            #pragma unroll
            for (int off = 16; off > 0; off >>= 1)
                acc += __shfl_down_sync(0xffffffffu, acc, off);
            if (l == 0) {
                int j = (w >> 3) * Hz + k * 8 + (w & 7);
                g_pg[b][j] = acc;
            }
        }
        batch_barrier(b);
    }
}

extern "C" void kernel_launch(void* const* d_in, const int* in_sizes, int n_in,
                              void* d_out, int out_size) {
    const float* st    = (const float*)d_in[0];
    const float* dyn   = (const float*)d_in[1];
    const float* W_s   = (const float*)d_in[2];
    const float* b_s   = (const float*)d_in[3];
    const float* W_d   = (const float*)d_in[4];
    const float* b_d   = (const float*)d_in[5];
    const float* W_dec = (const float*)d_in[6];
    const float* b_dec = (const float*)d_in[7];
    const float* W_ih  = (const float*)d_in[8];
    const float* W_hh  = (const float*)d_in[9];
    const float* b_ih  = (const float*)d_in[10];
    const float* b_hh  = (const float*)d_in[11];
    const float* W_ref = (const float*)d_in[12];
    const float* b_ref = (const float*)d_in[13];
    const float* W_pd  = (const float*)d_in[14];
    const float* b_pd  = (const float*)d_in[15];
    const float* W_q   = (const float*)d_in[16];
    const float* b_q   = (const float*)d_in[17];
    const float* W_att = (const float*)d_in[18];

    const int dyn_smem = (Hz * Hz) * (int)sizeof(float) + 8 * 128 * 16;  // 64K + 16K
    static int attr_set = 0;
    if (!attr_set) {
        cudaFuncSetAttribute(persist_kernel,
                             cudaFuncAttributeMaxDynamicSharedMemorySize, dyn_smem);
        attr_set = 1;
    }

    coef_kernel<<<640, 128>>>(W_ref, W_s, b_s, b_ref, W_pd, W_d, b_d, b_pd,
                              W_ih, W_dec, b_dec, b_ih, b_hh);
    persist_kernel<<<NB, NT, dyn_smem>>>(st, dyn, W_hh, W_q, b_q, W_att,
                                         (float*)d_out, out_size);
}

// round 12
// speedup vs baseline: 3.2284x; 1.0319x over previous
#include <cuda_runtime.h>
#include <math.h>

#define Bz 8
#define Sz 8192
#define Hz 128
#define STEPS 20
#define NBPB 16              // blocks per batch
#define NB (Bz * NBPB)       // 128 blocks (<=148 SMs -> co-resident)
#define NT 1024              // 32 warps/block
#define SCHUNK 512           // positions per block

typedef unsigned long long ull;

// -------- persistent scratch --------
__device__ float  g_coef[4 * Hz];   // a0 | a1 | dd | C
__device__ float2 g_U[4 * Hz];      // W_ih @ W_dec
__device__ float  g_V[4 * Hz];      // W_ih @ b_dec + b_ih + b_hh
__device__ __align__(16) float4 g_pg4[2][Bz][Hz];     // gate partials {i,f,c,o}, dbl-buffered
__device__ __align__(16) float4 g_part2[2][Bz][NBPB]; // {m, id-bits, ssum, tag-bits}
__device__ int      g_bmax[Bz];
__device__ int      g_dnz[Bz];
__device__ unsigned g_bcnt[Bz];
__device__ unsigned g_bgen[Bz];

// -------- batch-local barrier (used only at init and teardown) --------
__device__ __forceinline__ void batch_barrier(int b) {
    __syncthreads();
    if (threadIdx.x == 0) {
        unsigned gen;
        asm volatile("ld.acquire.gpu.global.u32 %0, [%1];"
                     : "=r"(gen) : "l"(&g_bgen[b]) : "memory");
        unsigned arrived;
        asm volatile("atom.acq_rel.gpu.global.add.u32 %0, [%1], %2;"
                     : "=r"(arrived) : "l"(&g_bcnt[b]), "r"(1u) : "memory");
        if (arrived == NBPB - 1) {
            asm volatile("st.global.u32 [%0], %1;" :: "l"(&g_bcnt[b]), "r"(0u) : "memory");
            asm volatile("st.release.gpu.global.u32 [%0], %1;"
                         :: "l"(&g_bgen[b]), "r"(gen + 1u) : "memory");
        } else {
            unsigned cur;
            do {
                asm volatile("ld.acquire.gpu.global.u32 %0, [%1];"
                             : "=r"(cur) : "l"(&g_bgen[b]) : "memory");
            } while (cur == gen);
        }
    }
    __syncthreads();
}

// -------- packed f32x2 helpers --------
__device__ __forceinline__ ull f2add(ull a, ull b) {
    ull d; asm("add.rn.f32x2 %0, %1, %2;" : "=l"(d) : "l"(a), "l"(b)); return d;
}
__device__ __forceinline__ ull f2mul(ull a, ull b) {
    ull d; asm("mul.rn.f32x2 %0, %1, %2;" : "=l"(d) : "l"(a), "l"(b)); return d;
}
__device__ __forceinline__ ull f2fma(ull a, ull b, ull c) {
    ull d; asm("fma.rn.f32x2 %0, %1, %2, %3;" : "=l"(d) : "l"(a), "l"(b), "l"(c)); return d;
}
__device__ __forceinline__ ull dup2(float f) {
    ull d; asm("mov.b64 %0, {%1, %2};" : "=l"(d) : "f"(f), "f"(f)); return d;
}
__device__ __forceinline__ ull pack2(float lo, float hi) {
    ull d; asm("mov.b64 %0, {%1, %2};" : "=l"(d) : "f"(lo), "f"(hi)); return d;
}
__device__ __forceinline__ void unpack2(ull v, float& lo, float& hi) {
    asm("mov.b64 {%0, %1}, %2;" : "=f"(lo), "=f"(hi) : "l"(v));
}

// tanh Taylor tail: NC=3 deg-7 (|x|<=0.23), NC=4 deg-9 (|x|<=0.32), NC=6 deg-13 (|x|<=0.55)
template<int NC>
__device__ __forceinline__ ull poly_core(ull X, ull wd, ull A) {
    const ull C1 = dup2(-0.33333334f);
    const ull C2 = dup2( 0.13333334f);
    const ull C3 = dup2(-0.053968254f);
    const ull C4 = dup2( 0.021869489f);
    const ull C5 = dup2(-0.008863236f);
    const ull C6 = dup2( 0.0035921280f);
    const ull ONE = dup2(1.0f);
    ull Y = f2mul(X, X);
    ull P;
    if (NC == 6) {
        P = f2fma(Y, C6, C5);
        P = f2fma(P, Y, C4);
        P = f2fma(P, Y, C3);
        P = f2fma(P, Y, C2);
    } else if (NC == 4) {
        P = f2fma(Y, C4, C3);
        P = f2fma(P, Y, C2);
    } else {
        P = f2fma(Y, C3, C2);
    }
    P = f2fma(P, Y, C1);
    P = f2fma(P, Y, ONE);
    return f2fma(wd, f2mul(X, P), A);
}

// 16 rows x 4 positions per thread; one LDS.128 per row; ALU dup expansion
template<int NC, bool HASD>
__device__ __forceinline__ void scan16b(int g0,
                                        ull XV0, ull XV1, ull YV0, ull YV1,
                                        ull DV0, ull DV1,
                                        const float4* __restrict__ s_tab4,
                                        const float* __restrict__ s_ddt,
                                        ull& A0, ull& A1) {
    #pragma unroll
    for (int i = 0; i < 16; ++i) {
        int g = g0 + i;
        float4 v = s_tab4[g];                 // {a0, a1, q+C, w}
        ull a0d = dup2(v.x), a1d = dup2(v.y);
        ull qd  = dup2(v.z), wd  = dup2(v.w);
        ull X0 = f2fma(a1d, YV0, qd);
        ull X1 = f2fma(a1d, YV1, qd);
        X0 = f2fma(a0d, XV0, X0);
        X1 = f2fma(a0d, XV1, X1);
        if (HASD) {
            ull ddd = dup2(s_ddt[g]);
            X0 = f2fma(ddd, DV0, X0);
            X1 = f2fma(ddd, DV1, X1);
        }
        A0 = poly_core<NC>(X0, wd, A0);
        A1 = poly_core<NC>(X1, wd, A1);
    }
}

__device__ __forceinline__ float sigmoidf(float x) { return 1.f / (1.f + expf(-x)); }

#define SMAX_COMBINE(m, id, ss, mo, io, so)                          \
    if ((mo) > (m) || ((mo) == (m) && (io) < (id))) {                \
        (ss) = (ss) * __expf((m) - (mo)) + (so);                     \
        (m) = (mo); (id) = (io);                                     \
    } else {                                                         \
        (ss) = (ss) + (so) * __expf((mo) - (m));                     \
    }

// -------- K0: coalesced fold. 640 blocks x 128 thr: one output row each --------
__global__ void coef_kernel(const float* __restrict__ W_ref, const float* __restrict__ W_s,
                            const float* __restrict__ b_s,   const float* __restrict__ b_ref,
                            const float* __restrict__ W_pd,  const float* __restrict__ W_d,
                            const float* __restrict__ b_d,   const float* __restrict__ b_pd,
                            const float* __restrict__ W_ih,  const float* __restrict__ W_dec,
                            const float* __restrict__ b_dec, const float* __restrict__ b_ih,
                            const float* __restrict__ b_hh) {
    __shared__ float s_r[4][4];
    const int h = threadIdx.x, w = h >> 5, l = h & 31;
    float v0, v1, v2, v3;
    if (blockIdx.x < 512) {
        int j = blockIdx.x;
        float wij = W_ih[j * Hz + h];
        v0 = wij * W_dec[h * 2 + 0];
        v1 = wij * W_dec[h * 2 + 1];
        v2 = wij * b_dec[h];
        v3 = 0.f;
    } else {
        int g = blockIdx.x - 512;
        float wr = W_ref[g * Hz + h];
        float wp = W_pd[g * Hz + h];
        v0 = wr * W_s[h * 2 + 0];
        v1 = wr * W_s[h * 2 + 1];
        v2 = fmaf(wr, b_s[h], wp * b_d[h]);
        v3 = wp * W_d[h];
    }
    #pragma unroll
    for (int off = 16; off > 0; off >>= 1) {
        v0 += __shfl_down_sync(0xffffffffu, v0, off);
        v1 += __shfl_down_sync(0xffffffffu, v1, off);
        v2 += __shfl_down_sync(0xffffffffu, v2, off);
        v3 += __shfl_down_sync(0xffffffffu, v3, off);
    }
    if (l == 0) { s_r[0][w] = v0; s_r[1][w] = v1; s_r[2][w] = v2; s_r[3][w] = v3; }
    __syncthreads();
    if (h == 0) {
        float r0 = s_r[0][0] + s_r[0][1] + s_r[0][2] + s_r[0][3];
        float r1 = s_r[1][0] + s_r[1][1] + s_r[1][2] + s_r[1][3];
        float r2 = s_r[2][0] + s_r[2][1] + s_r[2][2] + s_r[2][3];
        float r3 = s_r[3][0] + s_r[3][1] + s_r[3][2] + s_r[3][3];
        if (blockIdx.x < 512) {
            int j = blockIdx.x;
            g_U[j] = make_float2(r0, r1);
            g_V[j] = r2 + b_ih[j] + b_hh[j];
        } else {
            int g = blockIdx.x - 512;
            g_coef[g] = r0;                               // a0
            g_coef[Hz + g] = r1;                          // a1
            g_coef[2 * Hz + g] = r3;                      // dd
            g_coef[3 * Hz + g] = r2 + b_ref[g] + b_pd[g]; // C
        }
    }
}

// -------- persistent decode kernel --------
__global__ __launch_bounds__(NT, 1)
void persist_kernel(const float* __restrict__ st,  const float* __restrict__ dyn,
                    const float* __restrict__ W_hh, const float* __restrict__ W_q,
                    const float* __restrict__ b_q,  const float* __restrict__ W_att,
                    float* __restrict__ out, int out_size) {
    const int blk = blockIdx.x;
    const int b = blk / NBPB;
    const int k = blk % NBPB;
    const int t = threadIdx.x;
    const int w = t >> 5, l = t & 31;
    const int pg = t & 127, rg = t >> 7;

    extern __shared__ float dsm[];
    float* s_wq = dsm;                                   // 64 KB: W_q 128x128
    ulonglong2* s_acc = (ulonglong2*)(dsm + Hz * Hz);    // 16 KB

    __shared__ float s_whh[32 * Hz];                     // 16 KB: block's 32 gate rows
    __shared__ __align__(16) float4 s_uvv[4 * Hz];       // 8 KB
    __shared__ __align__(16) float4 s_tab4[Hz];          // {a0, a1, q+C, w} per step
    __shared__ float s_a0[Hz], s_a1[Hz], s_dd[Hz], s_w[Hz], s_Cg[Hz], s_qc[Hz];
    __shared__ float s_qraw[Hz], s_bq[Hz];
    __shared__ float s_hhold[Hz], s_c[Hz];
    __shared__ float s_dec[2];
    __shared__ float s_wm[4];
    __shared__ int   s_wi[4];
    __shared__ float s_ws[4];
    __shared__ int   s_imax;
    __shared__ int   s_dnz;

    // ---- phase 0: tables + weights + per-thread position data ----
    if (t < Hz) {
        float a0 = g_coef[t], a1 = g_coef[Hz + t];
        float dd = g_coef[2 * Hz + t], C = g_coef[3 * Hz + t];
        float wv = W_att[t];
        s_a0[t] = a0; s_a1[t] = a1; s_dd[t] = dd; s_Cg[t] = C; s_w[t] = wv;
        s_hhold[t] = 0.f; s_c[t] = 0.f; s_bq[t] = b_q[t];
    }
    for (int idx = t; idx < Hz * Hz; idx += NT) s_wq[idx] = W_q[idx];
    for (int idx = t; idx < 32 * Hz; idx += NT) {
        int ww = idx >> 7, col = idx & 127;
        int j = (ww >> 3) * Hz + k * 8 + (ww & 7);
        s_whh[idx] = W_hh[j * Hz + col];
    }
    if (t < 4 * Hz) {
        float2 u = g_U[t];
        s_uvv[t] = make_float4(u.x, u.y, g_V[t], 0.f);
    }
    if (t == 0) { s_imax = 0; s_dnz = 0; }
    __syncthreads();

    // position data (4 positions per thread; replicated across rg groups)
    const int s0 = k * SCHUNK + 4 * pg;
    const float4 x4 = *(const float4*)(st + (b * 2 + 0) * Sz + s0);
    const float4 y4 = *(const float4*)(st + (b * 2 + 1) * Sz + s0);
    const float4 d4 = *(const float4*)(dyn + b * Sz + s0);
    const ull XV0 = pack2(x4.x, x4.y), XV1 = pack2(x4.z, x4.w);
    const ull YV0 = pack2(y4.x, y4.y), YV1 = pack2(y4.z, y4.w);
    const ull DV0 = pack2(d4.x, d4.y), DV1 = pack2(d4.z, d4.w);

    // Mu = max |a0 x + a1 y + dd d| over this thread's positions x its 16 rows
    {
        float lmax = 0.f;
        #pragma unroll 4
        for (int i = 0; i < 16; ++i) {
            int g = rg * 16 + i;
            float a0 = s_a0[g], a1 = s_a1[g], dd = s_dd[g];
            float u0 = fmaf(a0, x4.x, fmaf(a1, y4.x, dd * d4.x));
            float u1 = fmaf(a0, x4.y, fmaf(a1, y4.y, dd * d4.y));
            float u2 = fmaf(a0, x4.z, fmaf(a1, y4.z, dd * d4.z));
            float u3 = fmaf(a0, x4.w, fmaf(a1, y4.w, dd * d4.w));
            lmax = fmaxf(lmax, fmaxf(fmaxf(fabsf(u0), fabsf(u1)),
                                     fmaxf(fabsf(u2), fabsf(u3))));
        }
        atomicMax(&s_imax, __float_as_int(lmax));
        if (rg == 0) {
            int nz = (d4.x != 0.f || d4.y != 0.f || d4.z != 0.f || d4.w != 0.f) ? 1 : 0;
            if (nz) s_dnz = 1;
        }
    }
    __syncthreads();
    if (t == 0) {
        atomicMax(&g_bmax[b], s_imax);
        if (s_dnz) atomicMax(&g_dnz[b], 1);
    }
    batch_barrier(b);
    const float Mb = __int_as_float(__ldcg(&g_bmax[b]));
    const bool hasd = __ldcg(&g_dnz[b]) != 0;

    for (int step = 0; step <= STEPS; ++step) {
        // ---- head: poll partner partials (tag >= step), combine, emit, gather ----
        if (step > 0) {
            if (w == 0) {
                float m = -1e30f, ss = 0.f; int id = 0x7FFFFFFF;
                if (l < NBPB) {
                    const float4* slot = &g_part2[(step - 1) & 1][b][l];
                    unsigned tag;
                    do {
                        asm volatile("ld.acquire.gpu.global.u32 %0, [%1];"
                                     : "=r"(tag)
                                     : "l"((const unsigned*)&slot->w) : "memory");
                    } while ((int)tag < step);
                    float4 v = __ldcg(slot);
                    m = v.x; id = __float_as_int(v.y); ss = v.z;
                }
                #pragma unroll
                for (int off = 8; off > 0; off >>= 1) {
                    float mo = __shfl_down_sync(0xffffffffu, m, off);
                    int   io = __shfl_down_sync(0xffffffffu, id, off);
                    float so = __shfl_down_sync(0xffffffffu, ss, off);
                    SMAX_COMBINE(m, id, ss, mo, io, so);
                }
                if (l == 0) {
                    if (k == 0) {
                        float logp = -__logf(ss);
                        int oi = b * STEPS + (step - 1);
                        if (oi < out_size) out[oi] = (float)id;
                        int oj = Bz * STEPS + oi;
                        if (oj < out_size) out[oj] = logp;
                    }
                    s_dec[0] = st[(b * 2 + 0) * Sz + id];
                    s_dec[1] = st[(b * 2 + 1) * Sz + id];
                }
            }
        } else if (t == 0) { s_dec[0] = 0.f; s_dec[1] = 0.f; }
        __syncthreads();
        if (step == STEPS) break;

        // ---- LSTM finish + h update (redundant per block, bitwise identical) ----
        if (t < Hz) {
            float4 pgv = make_float4(0.f, 0.f, 0.f, 0.f);
            if (step > 0)
                pgv = __ldcg(&g_pg4[(step - 1) & 1][b][t]);
            float d0 = s_dec[0], d1 = s_dec[1];
            float4 u0 = s_uvv[t],          u1 = s_uvv[Hz + t],
                   u2 = s_uvv[2 * Hz + t], u3 = s_uvv[3 * Hz + t];
            float gi = pgv.x + fmaf(u0.x, d0, fmaf(u0.y, d1, u0.z));
            float gf = pgv.y + fmaf(u1.x, d0, fmaf(u1.y, d1, u1.z));
            float gc = pgv.z + fmaf(u2.x, d0, fmaf(u2.y, d1, u2.z));
            float go = pgv.w + fmaf(u3.x, d0, fmaf(u3.y, d1, u3.z));
            float c2 = fmaf(sigmoidf(gf), s_c[t], sigmoidf(gi) * tanhf(gc));
            float h2 = sigmoidf(go) * tanhf(c2);
            s_c[t] = c2;
            s_hhold[t] = h2;
        }
        __syncthreads();

        // ---- q = W_q @ h + b_q (all from smem; redundant per block) ----
        {
            #pragma unroll
            for (int r4 = 0; r4 < 4; ++r4) {
                int row = w * 4 + r4;
                const float* wq = s_wq + row * Hz;
                float acc = fmaf(wq[l],      s_hhold[l],
                            fmaf(wq[l + 32], s_hhold[l + 32],
                            fmaf(wq[l + 64], s_hhold[l + 64],
                                 wq[l + 96] * s_hhold[l + 96])));
                #pragma unroll
                for (int off = 16; off > 0; off >>= 1)
                    acc += __shfl_down_sync(0xffffffffu, acc, off);
                if (l == 0) s_qraw[row] = acc + s_bq[row];
            }
        }
        __syncthreads();
        if (t < Hz) {
            float qc = s_qraw[t] + s_Cg[t];
            s_qc[t] = qc;
            s_tab4[t] = make_float4(s_a0[t], s_a1[t], qc, s_w[t]);
            float mq = fabsf(qc);
            #pragma unroll
            for (int off = 16; off > 0; off >>= 1)
                mq = fmaxf(mq, __shfl_down_sync(0xffffffffu, mq, off));
            if (l == 0) s_wm[w] = mq;
        }
        __syncthreads();
        const float bound = fmaxf(fmaxf(s_wm[0], s_wm[1]), fmaxf(s_wm[2], s_wm[3])) + Mb;
        const int path = (bound <= 0.23f) ? 0
                       : (bound <= 0.32f) ? 1
                       : (bound <= 0.55f) ? 2 : 3;

        // ---- attention scan: on-the-fly base, 4 positions x 16 rows/thread ----
        ull A0 = 0ull, A1 = 0ull;
        if (path <= 2) {
            if (!hasd) {
                if (path == 0)
                    scan16b<3, false>(rg * 16, XV0, XV1, YV0, YV1, DV0, DV1, s_tab4, s_dd, A0, A1);
                else if (path == 1)
                    scan16b<4, false>(rg * 16, XV0, XV1, YV0, YV1, DV0, DV1, s_tab4, s_dd, A0, A1);
                else
                    scan16b<6, false>(rg * 16, XV0, XV1, YV0, YV1, DV0, DV1, s_tab4, s_dd, A0, A1);
            } else {
                if (path == 0)
                    scan16b<3, true>(rg * 16, XV0, XV1, YV0, YV1, DV0, DV1, s_tab4, s_dd, A0, A1);
                else if (path == 1)
                    scan16b<4, true>(rg * 16, XV0, XV1, YV0, YV1, DV0, DV1, s_tab4, s_dd, A0, A1);
                else
                    scan16b<6, true>(rg * 16, XV0, XV1, YV0, YV1, DV0, DV1, s_tab4, s_dd, A0, A1);
            }
        } else {
            float f0 = 0.f, f1 = 0.f, f2 = 0.f, f3 = 0.f;
            for (int i = 0; i < 16; ++i) {
                int g = rg * 16 + i;
                float a0 = s_a0[g], a1 = s_a1[g], dd = s_dd[g];
                float qc = s_qc[g], wv = s_w[g];
                f0 = fmaf(wv, tanhf(fmaf(a0, x4.x, fmaf(a1, y4.x, fmaf(dd, d4.x, qc)))), f0);
                f1 = fmaf(wv, tanhf(fmaf(a0, x4.y, fmaf(a1, y4.y, fmaf(dd, d4.y, qc)))), f1);
                f2 = fmaf(wv, tanhf(fmaf(a0, x4.z, fmaf(a1, y4.z, fmaf(dd, d4.z, qc)))), f2);
                f3 = fmaf(wv, tanhf(fmaf(a0, x4.w, fmaf(a1, y4.w, fmaf(dd, d4.w, qc)))), f3);
            }
            A0 = pack2(f0, f1); A1 = pack2(f2, f3);
        }
        {
            ulonglong2 vv; vv.x = A0; vv.y = A1;
            s_acc[rg * 128 + pg] = vv;
        }

        // ---- gate partials for NEXT step (all warps; before the sync) ----
        {
            const float* whr = s_whh + w * Hz;
            float acc = fmaf(whr[l],      s_hhold[l],
                        fmaf(whr[l + 32], s_hhold[l + 32],
                        fmaf(whr[l + 64], s_hhold[l + 64],
                             whr[l + 96] * s_hhold[l + 96])));
            #pragma unroll
            for (int off = 16; off > 0; off >>= 1)
                acc += __shfl_down_sync(0xffffffffu, acc, off);
            if (l == 0) {
                int q4 = w >> 3, r = k * 8 + (w & 7);
                float* dst = (float*)&g_pg4[step & 1][b][r];
                asm volatile("st.global.f32 [%0], %1;"
                             :: "l"(dst + q4), "f"(acc) : "memory");
            }
        }
        __syncthreads();

        // ---- reduce 8 row-groups -> block softmax partial ----
        if (t < 128) {
            ull B0 = 0ull, B1 = 0ull;
            #pragma unroll
            for (int r = 0; r < 8; ++r) {
                ulonglong2 v = s_acc[r * 128 + t];
                B0 = f2add(B0, v.x); B1 = f2add(B1, v.y);
            }
            float a0, a1, a2, a3;
            unpack2(B0, a0, a1); unpack2(B1, a2, a3);
            // replicate reference fp32 quantization `attns + 10000.0`
            float aq0 = a0 + 10000.0f, aq1 = a1 + 10000.0f;
            float aq2 = a2 + 10000.0f, aq3 = a3 + 10000.0f;
            int sb = k * SCHUNK + 4 * t;
            float m, ss; int id;
            if (aq1 > aq0) { m = aq1; id = sb + 1; ss = __expf(aq0 - aq1) + 1.f; }
            else           { m = aq0; id = sb;     ss = 1.f + __expf(aq1 - aq0); }
            float m2, ss2; int id2;
            if (aq3 > aq2) { m2 = aq3; id2 = sb + 3; ss2 = __expf(aq2 - aq3) + 1.f; }
            else           { m2 = aq2; id2 = sb + 2; ss2 = 1.f + __expf(aq3 - aq2); }
            SMAX_COMBINE(m, id, ss, m2, id2, ss2);
            #pragma unroll
            for (int off = 16; off > 0; off >>= 1) {
                float mo = __shfl_down_sync(0xffffffffu, m, off);
                int   io = __shfl_down_sync(0xffffffffu, id, off);
                float so = __shfl_down_sync(0xffffffffu, ss, off);
                SMAX_COMBINE(m, id, ss, mo, io, so);
            }
            if (l == 0) { s_wm[w] = m; s_wi[w] = id; s_ws[w] = ss; }
        }
        __syncthreads();
        if (t < 32) {
            float m  = (t < 4) ? s_wm[t] : -1e30f;
            int   id = (t < 4) ? s_wi[t] : 0x7FFFFFFF;
            float ss = (t < 4) ? s_ws[t] : 0.f;
            #pragma unroll
            for (int off = 2; off > 0; off >>= 1) {
                float mo = __shfl_down_sync(0xffffffffu, m, off);
                int   io = __shfl_down_sync(0xffffffffu, id, off);
                float so = __shfl_down_sync(0xffffffffu, ss, off);
                SMAX_COMBINE(m, id, ss, mo, io, so);
            }
            if (t == 0) {
                // publish payload, then release the tag (covers g_pg4 stores too:
                // they happen-before via __syncthreads + this gpu-scope fence)
                float4* slot = &g_part2[step & 1][b][k];
                asm volatile("fence.acq_rel.gpu;" ::: "memory");
                asm volatile("st.global.v2.f32 [%0], {%1, %2};"
                             :: "l"(&slot->x), "f"(m), "f"(__int_as_float(id)) : "memory");
                asm volatile("st.global.f32 [%0], %1;"
                             :: "l"(&slot->z), "f"(ss) : "memory");
                asm volatile("st.release.gpu.global.u32 [%0], %1;"
                             :: "l"((unsigned*)&slot->w), "r"((unsigned)(step + 1)) : "memory");
            }
        }
        // no barrier: next head polls the tags directly
    }

    // ---- teardown: all blocks done reading; reset tags for the next replay ----
    batch_barrier(b);
    if (t == 0) {
        *(unsigned*)&g_part2[0][b][k].w = 0u;
        *(unsigned*)&g_part2[1][b][k].w = 0u;
    }
}

extern "C" void kernel_launch(void* const* d_in, const int* in_sizes, int n_in,
                              void* d_out, int out_size) {
    const float* st    = (const float*)d_in[0];
    const float* dyn   = (const float*)d_in[1];
    const float* W_s   = (const float*)d_in[2];
    const float* b_s   = (const float*)d_in[3];
    const float* W_d   = (const float*)d_in[4];
    const float* b_d   = (const float*)d_in[5];
    const float* W_dec = (const float*)d_in[6];
    const float* b_dec = (const float*)d_in[7];
    const float* W_ih  = (const float*)d_in[8];
    const float* W_hh  = (const float*)d_in[9];
    const float* b_ih  = (const float*)d_in[10];
    const float* b_hh  = (const float*)d_in[11];
    const float* W_ref = (const float*)d_in[12];
    const float* b_ref = (const float*)d_in[13];
    const float* W_pd  = (const float*)d_in[14];
    const float* b_pd  = (const float*)d_in[15];
    const float* W_q   = (const float*)d_in[16];
    const float* b_q   = (const float*)d_in[17];
    const float* W_att = (const float*)d_in[18];

    const int dyn_smem = (Hz * Hz) * (int)sizeof(float) + 8 * 128 * 16;  // 64K + 16K
    static int attr_set = 0;
    if (!attr_set) {
        cudaFuncSetAttribute(persist_kernel,
                             cudaFuncAttributeMaxDynamicSharedMemorySize, dyn_smem);
        attr_set = 1;
    }

    coef_kernel<<<640, 128>>>(W_ref, W_s, b_s, b_ref, W_pd, W_d, b_d, b_pd,
                              W_ih, W_dec, b_dec, b_ih, b_hh);
    persist_kernel<<<NB, NT, dyn_smem>>>(st, dyn, W_hh, W_q, b_q, W_att,
                                         (float*)d_out, out_size);
}